// round 1
// baseline (speedup 1.0000x reference)
#include <cuda_runtime.h>
#include <math.h>

#define BH    32
#define NSEQ  4096
#define DDIM  64
#define MDIM  256
#define LCOND 256
#define CSZ   64
#define NCH   60          // (4096-256)/64
#define DN    0.35355339059327373f   // 64^-0.25
#define RATIO 0.0625f                // 256^-0.5
#define DIAGC 0.0625f                // dn^2 * 0.5
#define KEPS  1e-4f
#define SEPS  1e-6f

// ---------------- scratch (device globals; no allocations) ----------------
__device__ float g_qp[BH*NSEQ*MDIM];        // 134MB: query features
__device__ float g_kp[BH*NSEQ*MDIM];        // 134MB: key features (pre-exp, then in-place)
__device__ float g_S [BH*NCH*MDIM*DDIM];    // chunk ctx sums -> exclusive prefix (S_prev)
__device__ float g_Z [BH*NCH*MDIM];         // chunk k sums   -> exclusive prefix (z_prev)
__device__ float g_Scond[BH*MDIM*DDIM];     // cond ctx
__device__ float g_Zcond[BH*MDIM];          // cond k_cum
__device__ unsigned g_kmax_bits;            // order-preserving float max

__device__ __forceinline__ unsigned enc_f(float f){
    unsigned u = __float_as_uint(f);
    return (u & 0x80000000u) ? ~u : (u | 0x80000000u);
}
__device__ __forceinline__ float dec_f(unsigned e){
    return (e & 0x80000000u) ? __uint_as_float(e & 0x7FFFFFFFu)
                             : __uint_as_float(~e);
}

__global__ void reset_kernel(){ g_kmax_bits = 0u; }

// ---------------- feature kernel: dd = (dn*x)@P^T, diag, stab, exp ----------------
#define PADP 257

template<bool IS_Q>
__global__ __launch_bounds__(256) void feat_kernel(const float* __restrict__ data,
                                                   const float* __restrict__ proj){
    extern __shared__ float projT[];          // [64][257], DN folded in
    __shared__ float rowbuf[8][128];
    int tid = threadIdx.x;
    for (int idx = tid; idx < MDIM*DDIM; idx += 256){
        int j = idx >> 6, i = idx & 63;
        projT[i*PADP + j] = proj[idx] * DN;
    }
    __syncthreads();
    int warp = tid >> 5, lane = tid & 31;
    int rowbase = blockIdx.x * 64 + warp * 8;
    float gmax = -3.4e38f;
    float* rb = rowbuf[warp];

    for (int rr = 0; rr < 8; rr += 2){
        int r0 = rowbase + rr;
        const float* p0 = data + (size_t)r0*DDIM;
        float a0 = p0[lane],       a1 = p0[32+lane];
        float b0 = p0[64+lane],    b1 = p0[96+lane];
        float s0 = a0*a0 + a1*a1,  s1 = b0*b0 + b1*b1;
        #pragma unroll
        for (int off=16; off; off>>=1){
            s0 += __shfl_xor_sync(0xffffffffu, s0, off);
            s1 += __shfl_xor_sync(0xffffffffu, s1, off);
        }
        float diag0 = s0*DIAGC, diag1 = s1*DIAGC;
        __syncwarp();
        rb[lane]=a0; rb[lane+32]=a1; rb[64+lane]=b0; rb[96+lane]=b1;
        __syncwarp();
        float dd0[8], dd1[8];
        #pragma unroll
        for (int jj=0;jj<8;jj++){ dd0[jj]=0.f; dd1[jj]=0.f; }
        #pragma unroll
        for (int i=0;i<64;i++){
            float q0 = rb[i], q1 = rb[64+i];
            #pragma unroll
            for (int jj=0;jj<8;jj++){
                float pv = projT[i*PADP + jj*32 + lane];
                dd0[jj] = fmaf(q0, pv, dd0[jj]);
                dd1[jj] = fmaf(q1, pv, dd1[jj]);
            }
        }
        if (IS_Q){
            float m0 = dd0[0], m1 = dd1[0];
            #pragma unroll
            for (int jj=1;jj<8;jj++){ m0=fmaxf(m0,dd0[jj]); m1=fmaxf(m1,dd1[jj]); }
            #pragma unroll
            for (int off=16; off; off>>=1){
                m0 = fmaxf(m0, __shfl_xor_sync(0xffffffffu,m0,off));
                m1 = fmaxf(m1, __shfl_xor_sync(0xffffffffu,m1,off));
            }
            float* o0 = g_qp + (size_t)r0*MDIM;
            #pragma unroll
            for (int jj=0;jj<8;jj++){
                o0[jj*32+lane]        = RATIO*(__expf(dd0[jj]-diag0-m0)+KEPS);
                o0[MDIM + jj*32+lane] = RATIO*(__expf(dd1[jj]-diag1-m1)+KEPS);
            }
        } else {
            float* o0 = g_kp + (size_t)r0*MDIM;
            #pragma unroll
            for (int jj=0;jj<8;jj++){
                gmax = fmaxf(gmax, fmaxf(dd0[jj], dd1[jj]));
                o0[jj*32+lane]        = dd0[jj]-diag0;
                o0[MDIM + jj*32+lane] = dd1[jj]-diag1;
            }
        }
    }
    if (!IS_Q){
        #pragma unroll
        for (int off=16; off; off>>=1)
            gmax = fmaxf(gmax, __shfl_xor_sync(0xffffffffu,gmax,off));
        if (lane==0) atomicMax(&g_kmax_bits, enc_f(gmax));
    }
}

// ---------------- kp finalize: exp with global stab ----------------
__global__ __launch_bounds__(256) void kfin_kernel(){
    float kmax = dec_f(g_kmax_bits);
    size_t i = (size_t)blockIdx.x*blockDim.x + threadIdx.x;
    size_t n4 = (size_t)BH*NSEQ*MDIM/4;
    if (i < n4){
        float4 x = reinterpret_cast<float4*>(g_kp)[i];
        x.x = RATIO*(__expf(x.x-kmax)+KEPS);
        x.y = RATIO*(__expf(x.y-kmax)+KEPS);
        x.z = RATIO*(__expf(x.z-kmax)+KEPS);
        x.w = RATIO*(__expf(x.w-kmax)+KEPS);
        reinterpret_cast<float4*>(g_kp)[i] = x;
    }
}

// ---------------- chunk states: S_c = K_c^T V_c, z_c = sum k ----------------
__global__ __launch_bounds__(256) void chunk_state_kernel(const float* __restrict__ v){
    int bh = blockIdx.y;
    int c  = blockIdx.x;   // 0 = cond(256 rows), 1..60 = rest chunks(64 rows)
    int rowbase, nrows;
    float *Sout, *Zout;
    if (c == 0){
        rowbase = bh*NSEQ; nrows = LCOND;
        Sout = g_Scond + (size_t)bh*MDIM*DDIM;
        Zout = g_Zcond + bh*MDIM;
    } else {
        rowbase = bh*NSEQ + LCOND + (c-1)*CSZ; nrows = CSZ;
        Sout = g_S + (size_t)(bh*NCH + c-1)*MDIM*DDIM;
        Zout = g_Z + (bh*NCH + c-1)*MDIM;
    }
    __shared__ float vs[8][64];
    int m = threadIdx.x;
    float acc[64];
    #pragma unroll
    for (int e=0;e<64;e++) acc[e]=0.f;
    float z = 0.f;
    for (int r0=0; r0<nrows; r0+=8){
        __syncthreads();
        for (int idx=m; idx<512; idx+=256){
            int rr = idx>>6, e = idx&63;
            vs[rr][e] = v[(size_t)(rowbase+r0+rr)*DDIM + e];
        }
        __syncthreads();
        #pragma unroll
        for (int rr=0; rr<8; rr++){
            float kv = g_kp[(size_t)(rowbase+r0+rr)*MDIM + m];
            z += kv;
            #pragma unroll
            for (int e=0;e<64;e+=4){
                float4 vv = *reinterpret_cast<const float4*>(&vs[rr][e]);
                acc[e+0] = fmaf(kv, vv.x, acc[e+0]);
                acc[e+1] = fmaf(kv, vv.y, acc[e+1]);
                acc[e+2] = fmaf(kv, vv.z, acc[e+2]);
                acc[e+3] = fmaf(kv, vv.w, acc[e+3]);
            }
        }
    }
    #pragma unroll
    for (int e=0;e<64;e+=4){
        float4 o = make_float4(acc[e],acc[e+1],acc[e+2],acc[e+3]);
        *reinterpret_cast<float4*>(&Sout[m*64+e]) = o;
    }
    Zout[m] = z;
}

// ---------------- exclusive prefix over chunks (seeded with cond state) ----------------
__global__ __launch_bounds__(256) void prefix_kernel(){
    int idx = blockIdx.x*256 + threadIdx.x;
    const int totS = BH*MDIM*DDIM;          // 524288
    if (idx < totS){
        int bh = idx >> 14;
        int j  = idx & 16383;
        float acc = g_Scond[idx];
        float* p = g_S + (size_t)bh*NCH*MDIM*DDIM + j;
        #pragma unroll 4
        for (int c=0;c<NCH;c++){
            float t = p[(size_t)c*MDIM*DDIM];
            p[(size_t)c*MDIM*DDIM] = acc;
            acc += t;
        }
    } else {
        int k2 = idx - totS;                // < BH*MDIM = 8192
        int bh = k2 >> 8;
        int j  = k2 & 255;
        float acc = g_Zcond[k2];
        float* p = g_Z + bh*NCH*MDIM + j;
        #pragma unroll 4
        for (int c=0;c<NCH;c++){
            float t = p[c*MDIM];
            p[c*MDIM] = acc;
            acc += t;
        }
    }
}

// ---------------- attention output: cond tiles + rest chunks ----------------
#define P 68
__global__ __launch_bounds__(256) void attn_kernel(const float* __restrict__ v,
                                                   float* __restrict__ out){
    __shared__ float Qs[32*P];
    __shared__ float Ks[32*P];    // also reused for V tiles
    __shared__ float Ss[32*P];
    __shared__ float As[64*P];
    __shared__ float zps[32];
    __shared__ float dens[64];

    int tid = threadIdx.x;
    int tx = tid & 15, ty = tid >> 4;
    int bh = blockIdx.y;
    int cc = blockIdx.x;                 // 0..63 : 0-3 cond, 4-63 rest
    bool is_cond = (cc < 4);
    int rowbase;
    const float *Sp, *zp;
    if (is_cond){
        rowbase = bh*NSEQ + cc*64;
        Sp = g_Scond + (size_t)bh*MDIM*DDIM;
        zp = g_Zcond + bh*MDIM;
    } else {
        int c = cc - 4;
        rowbase = bh*NSEQ + LCOND + c*CSZ;
        Sp = g_S + (size_t)(bh*NCH + c)*MDIM*DDIM;
        zp = g_Z + (bh*NCH + c)*MDIM;
    }
    const float* Qg = g_qp + (size_t)rowbase*MDIM;
    const float* Kg = g_kp + (size_t)rowbase*MDIM;
    const float* Vg = v + (size_t)rowbase*DDIM;
    float epsv = is_cond ? 0.f : SEPS;

    float accA[16], accO[16];
    #pragma unroll
    for (int i=0;i<16;i++){ accA[i]=0.f; accO[i]=0.f; }
    float den_loc = 0.f;

    // main k-loop over m: A += Q K^T (rest only), O += Q @ S_prev, den += Q.(zp+eps)
    for (int m0=0; m0<MDIM; m0+=32){
        __syncthreads();
        for (int idx=tid; idx<2048; idx+=256){
            int t = idx>>5, mm = idx&31;
            Qs[mm*P + t] = Qg[t*MDIM + m0 + mm];
        }
        if (!is_cond){
            for (int idx=tid; idx<2048; idx+=256){
                int t = idx>>5, mm = idx&31;
                Ks[mm*P + t] = Kg[t*MDIM + m0 + mm];
            }
        }
        for (int idx=tid; idx<2048; idx+=256){
            int mm = idx>>6, e = idx&63;
            Ss[mm*P + e] = Sp[(m0+mm)*DDIM + e];
        }
        if (tid<32) zps[tid] = zp[m0+tid];
        __syncthreads();
        #pragma unroll 4
        for (int mm=0; mm<32; mm++){
            float4 aq = *reinterpret_cast<const float4*>(&Qs[mm*P + ty*4]);
            float4 bs = *reinterpret_cast<const float4*>(&Ss[mm*P + tx*4]);
            float a[4] = {aq.x,aq.y,aq.z,aq.w};
            float b[4] = {bs.x,bs.y,bs.z,bs.w};
            #pragma unroll
            for (int i=0;i<4;i++)
                #pragma unroll
                for (int j=0;j<4;j++)
                    accO[i*4+j] = fmaf(a[i], b[j], accO[i*4+j]);
            if (!is_cond){
                float4 bk = *reinterpret_cast<const float4*>(&Ks[mm*P + tx*4]);
                float bb[4] = {bk.x,bk.y,bk.z,bk.w};
                #pragma unroll
                for (int i=0;i<4;i++)
                    #pragma unroll
                    for (int j=0;j<4;j++)
                        accA[i*4+j] = fmaf(a[i], bb[j], accA[i*4+j]);
            }
        }
        if (tid < 64){
            #pragma unroll
            for (int mm=0; mm<32; mm++)
                den_loc = fmaf(Qs[mm*P + tid], zps[mm] + epsv, den_loc);
        }
    }

    if (!is_cond){
        __syncthreads();
        // masked A -> smem
        #pragma unroll
        for (int i=0;i<4;i++){
            int t = ty*4+i;
            #pragma unroll
            for (int j=0;j<4;j++){
                int s = tx*4+j;
                As[t*P + s] = (s<=t) ? accA[i*4+j] : 0.f;
            }
        }
        __syncthreads();
        if (tid < 64){
            float s = 0.f;
            #pragma unroll 8
            for (int ss=0; ss<64; ss++) s += As[tid*P + ss];
            den_loc += s;
        }
        // O += A_mask @ V  (two 32-row V tiles staged into Ks buffer)
        for (int s0=0; s0<64; s0+=32){
            __syncthreads();
            for (int idx=tid; idx<2048; idx+=256){
                int ss = idx>>6, e = idx&63;
                Ks[ss*P + e] = Vg[(s0+ss)*DDIM + e];
            }
            __syncthreads();
            #pragma unroll 4
            for (int ss=0; ss<32; ss++){
                float4 bv = *reinterpret_cast<const float4*>(&Ks[ss*P + tx*4]);
                float b[4] = {bv.x,bv.y,bv.z,bv.w};
                float a[4];
                #pragma unroll
                for (int i=0;i<4;i++) a[i] = As[(ty*4+i)*P + s0+ss];
                #pragma unroll
                for (int i=0;i<4;i++)
                    #pragma unroll
                    for (int j=0;j<4;j++)
                        accO[i*4+j] = fmaf(a[i], b[j], accO[i*4+j]);
            }
        }
    }

    if (tid < 64) dens[tid] = den_loc;
    __syncthreads();
    #pragma unroll
    for (int i=0;i<4;i++){
        int t = ty*4+i;
        float inv = 1.f / dens[t];
        float4 o = make_float4(accO[i*4+0]*inv, accO[i*4+1]*inv,
                               accO[i*4+2]*inv, accO[i*4+3]*inv);
        *reinterpret_cast<float4*>(&out[(size_t)(rowbase+t)*DDIM + tx*4]) = o;
    }
}

// ---------------- launch ----------------
extern "C" void kernel_launch(void* const* d_in, const int* in_sizes, int n_in,
                              void* d_out, int out_size){
    const float* q    = (const float*)d_in[0];
    const float* k    = (const float*)d_in[1];
    const float* v    = (const float*)d_in[2];
    const float* proj = (const float*)d_in[3];
    float* out = (float*)d_out;

    const int FEAT_SMEM = DDIM*PADP*sizeof(float);   // 65792 B
    cudaFuncSetAttribute(feat_kernel<true>,  cudaFuncAttributeMaxDynamicSharedMemorySize, FEAT_SMEM);
    cudaFuncSetAttribute(feat_kernel<false>, cudaFuncAttributeMaxDynamicSharedMemorySize, FEAT_SMEM);

    reset_kernel<<<1,1>>>();
    feat_kernel<false><<<2048,256,FEAT_SMEM>>>(k, proj);   // k: dd-diag + global max
    feat_kernel<true ><<<2048,256,FEAT_SMEM>>>(q, proj);   // q: full features
    kfin_kernel<<<32768,256>>>();                          // k: exp with global stab
    chunk_state_kernel<<<dim3(61,32),256>>>(v);            // per-chunk S,z (+ cond)
    prefix_kernel<<<2080,256>>>();                         // exclusive prefix over chunks
    attn_kernel<<<dim3(64,32),256>>>(v, out);              // outputs (cond + rest)
}

// round 2
// speedup vs baseline: 1.1584x; 1.1584x over previous
#include <cuda_runtime.h>
#include <math.h>
#include <stdint.h>

#define BH    32
#define NSEQ  4096
#define DDIM  64
#define MDIM  256
#define LCOND 256
#define CSZ   64
#define NCH   60          // (4096-256)/64
#define DN    0.35355339059327373f   // 64^-0.25
#define RATIO 0.0625f                // 256^-0.5
#define DIAGC 0.0625f                // dn^2 * 0.5
#define KEPS  1e-4f
#define SEPS  1e-6f
#define FP    68          // padded stride for 64-wide smem tiles
#define CP    260         // padded stride for 256-wide smem tiles

// ---------------- scratch ----------------
__device__ float g_qp[BH*NSEQ*MDIM];
__device__ float g_kp[BH*NSEQ*MDIM];
__device__ float g_S [BH*NCH*MDIM*DDIM];   // per-chunk TRANSPOSED ctx: [e][m]
__device__ float g_Z [BH*NCH*MDIM];
__device__ float g_Scond[BH*MDIM*DDIM];    // [e][m]
__device__ float g_Zcond[BH*MDIM];
__device__ unsigned g_kmax_bits;

__device__ __forceinline__ unsigned enc_f(float f){
    unsigned u = __float_as_uint(f);
    return (u & 0x80000000u) ? ~u : (u | 0x80000000u);
}
__device__ __forceinline__ float dec_f(unsigned e){
    return (e & 0x80000000u) ? __uint_as_float(e & 0x7FFFFFFFu)
                             : __uint_as_float(~e);
}
__device__ __forceinline__ uint32_t f2tf(float f){
    uint32_t r; asm("cvt.rna.tf32.f32 %0, %1;" : "=r"(r) : "f"(f)); return r;
}
__device__ __forceinline__ float f2tff(float f){
    return __uint_as_float(f2tf(f));
}
__device__ __forceinline__ void mma_tf32(float c[4],
        uint32_t a0,uint32_t a1,uint32_t a2,uint32_t a3,
        uint32_t b0,uint32_t b1){
    asm volatile("mma.sync.aligned.m16n8k8.row.col.f32.tf32.tf32.f32 "
        "{%0,%1,%2,%3}, {%4,%5,%6,%7}, {%8,%9}, {%0,%1,%2,%3};"
        : "+f"(c[0]),"+f"(c[1]),"+f"(c[2]),"+f"(c[3])
        : "r"(a0),"r"(a1),"r"(a2),"r"(a3),"r"(b0),"r"(b1));
}
__device__ __forceinline__ uint32_t ldu(const float* p){ return __float_as_uint(*p); }

__global__ void reset_kernel(){ g_kmax_bits = 0u; }

// ================= feature kernel (tf32 mma) =================
// C[64 rows x 256 m] = X[64x64] @ (DN*P)^T ; diag f32 from raw X.
template<bool IS_Q>
__global__ __launch_bounds__(256) void feat_mma(const float* __restrict__ data,
                                                const float* __restrict__ proj){
    extern __shared__ float sm[];
    float* Xs = sm;               // [64][FP] raw f32
    float* Ps = sm + 64*FP;       // [256][FP] tf32-rounded
    float* Csm = Ps;              // epilogue reuse: [64][CP]
    __shared__ float rowsq[64], rowst[64];
    __shared__ unsigned bmax;

    int tid = threadIdx.x, lane = tid&31, warp = tid>>5;
    int gid = lane>>2, t4 = lane&3;
    int rowbase = blockIdx.x*64;
    if (tid==0) bmax = 0u;

    const float* xg = data + (size_t)rowbase*DDIM;
    for (int i=tid;i<4096;i+=256)
        Xs[(i>>6)*FP + (i&63)] = xg[i];
    for (int i=tid;i<16384;i+=256)
        Ps[(i>>6)*FP + (i&63)] = f2tff(proj[i]*DN);
    __syncthreads();

    // per-row sum of squares (full f32)
    {
        int row = tid>>2, q = tid&3;
        float s = 0.f;
        #pragma unroll
        for (int i=0;i<16;i++){ float x = Xs[row*FP + q*16 + i]; s = fmaf(x,x,s); }
        s += __shfl_xor_sync(~0u, s, 1);
        s += __shfl_xor_sync(~0u, s, 2);
        if (q==0) rowsq[row] = s*DIAGC;
    }

    float c[16][4];
    #pragma unroll
    for (int nt=0;nt<16;nt++){ c[nt][0]=0.f;c[nt][1]=0.f;c[nt][2]=0.f;c[nt][3]=0.f; }
    int mrow = (warp>>1)*16;
    int nbase = (warp&1)*128;

    #pragma unroll
    for (int k0=0;k0<64;k0+=8){
        uint32_t a0 = f2tf(Xs[(mrow+gid  )*FP + k0 + t4]);
        uint32_t a1 = f2tf(Xs[(mrow+gid+8)*FP + k0 + t4]);
        uint32_t a2 = f2tf(Xs[(mrow+gid  )*FP + k0 + t4 + 4]);
        uint32_t a3 = f2tf(Xs[(mrow+gid+8)*FP + k0 + t4 + 4]);
        #pragma unroll
        for (int nt=0;nt<16;nt++){
            int n0 = nbase + nt*8;
            uint32_t b0 = ldu(&Ps[(n0+gid)*FP + k0 + t4]);
            uint32_t b1 = ldu(&Ps[(n0+gid)*FP + k0 + t4 + 4]);
            mma_tf32(c[nt], a0,a1,a2,a3, b0,b1);
        }
    }
    __syncthreads();      // Ps fully consumed

    #pragma unroll
    for (int nt=0;nt<16;nt++){
        int col = nbase + nt*8 + t4*2;
        int r0 = mrow + gid;
        Csm[r0*CP + col]       = c[nt][0];
        Csm[r0*CP + col+1]     = c[nt][1];
        Csm[(r0+8)*CP + col]   = c[nt][2];
        Csm[(r0+8)*CP + col+1] = c[nt][3];
    }
    __syncthreads();

    int row = tid>>2, q = tid&3;
    if (IS_Q){
        float mx = -3.4e38f;
        #pragma unroll 8
        for (int i=0;i<64;i++) mx = fmaxf(mx, Csm[row*CP + q*64 + i]);
        mx = fmaxf(mx, __shfl_xor_sync(~0u,mx,1));
        mx = fmaxf(mx, __shfl_xor_sync(~0u,mx,2));
        if (q==0) rowst[row] = mx;
        __syncthreads();
        float* og = g_qp + (size_t)rowbase*MDIM;
        for (int i=tid;i<16384;i+=256){
            int r = i>>8, cc = i&255;
            og[i] = RATIO*(__expf(Csm[r*CP+cc] - rowsq[r] - rowst[r]) + KEPS);
        }
    } else {
        float mx = -3.4e38f;
        #pragma unroll 8
        for (int i=0;i<64;i++) mx = fmaxf(mx, Csm[row*CP + q*64 + i]);
        #pragma unroll
        for (int off=16;off;off>>=1)
            mx = fmaxf(mx, __shfl_xor_sync(~0u,mx,off));
        if (lane==0) atomicMax(&bmax, enc_f(mx));
        __syncthreads();
        float* og = g_kp + (size_t)rowbase*MDIM;
        for (int i=tid;i<16384;i+=256){
            int r = i>>8;
            og[i] = Csm[r*CP+(i&255)] - rowsq[r];
        }
        if (tid==0) atomicMax(&g_kmax_bits, bmax);
    }
}

// ================= kp finalize =================
__global__ __launch_bounds__(256) void kfin_kernel(){
    float kmax = dec_f(g_kmax_bits);
    size_t i = (size_t)blockIdx.x*blockDim.x + threadIdx.x;
    size_t n4 = (size_t)BH*NSEQ*MDIM/4;
    if (i < n4){
        float4 x = reinterpret_cast<float4*>(g_kp)[i];
        x.x = RATIO*(__expf(x.x-kmax)+KEPS);
        x.y = RATIO*(__expf(x.y-kmax)+KEPS);
        x.z = RATIO*(__expf(x.z-kmax)+KEPS);
        x.w = RATIO*(__expf(x.w-kmax)+KEPS);
        reinterpret_cast<float4*>(g_kp)[i] = x;
    }
}

// ================= chunk states (tf32 mma) =================
// S_T[e][m] = sum_r V[r][e] * kp[r][m] ; z[m] = sum_r kp[r][m] (f32)
__global__ __launch_bounds__(256) void chunk_mma(const float* __restrict__ v){
    extern __shared__ float sm[];
    float* VT = sm;              // [64 e][FP r] tf32
    float* KT = sm + 64*FP;      // [256 m][FP r] tf32
    float* Ssm = KT;             // epilogue reuse [64][CP]

    int tid = threadIdx.x, lane = tid&31, warp = tid>>5;
    int gid = lane>>2, t4 = lane&3;
    int bh = blockIdx.y, cidx = blockIdx.x;   // 0=cond, 1..60 rest
    int rowbase, npass;
    float *Sout, *Zout;
    if (cidx==0){
        rowbase = bh*NSEQ; npass = 4;
        Sout = g_Scond + (size_t)bh*MDIM*DDIM;
        Zout = g_Zcond + bh*MDIM;
    } else {
        rowbase = bh*NSEQ + LCOND + (cidx-1)*CSZ; npass = 1;
        Sout = g_S + (size_t)(bh*NCH + cidx-1)*MDIM*DDIM;
        Zout = g_Z + (bh*NCH + cidx-1)*MDIM;
    }

    float c[16][4];
    #pragma unroll
    for (int nt=0;nt<16;nt++){ c[nt][0]=0.f;c[nt][1]=0.f;c[nt][2]=0.f;c[nt][3]=0.f; }
    float z = 0.f;
    int erow = (warp>>1)*16;
    int nbase = (warp&1)*128;

    for (int p=0;p<npass;p++){
        int r0base = rowbase + p*64;
        __syncthreads();
        for (int i=tid;i<4096;i+=256){
            int r = i>>6, e = i&63;
            VT[e*FP + r] = f2tff(v[(size_t)(r0base+r)*DDIM + e]);
        }
        // KT: thread tid = m, loop rows
        {
            const float* kg = g_kp + (size_t)r0base*MDIM + tid;
            #pragma unroll 4
            for (int r=0;r<64;r++){
                float kv = kg[(size_t)r*MDIM];
                z += kv;
                KT[tid*FP + r] = f2tff(kv);
            }
        }
        __syncthreads();
        #pragma unroll
        for (int k0=0;k0<64;k0+=8){
            uint32_t a0 = ldu(&VT[(erow+gid  )*FP + k0 + t4]);
            uint32_t a1 = ldu(&VT[(erow+gid+8)*FP + k0 + t4]);
            uint32_t a2 = ldu(&VT[(erow+gid  )*FP + k0 + t4 + 4]);
            uint32_t a3 = ldu(&VT[(erow+gid+8)*FP + k0 + t4 + 4]);
            #pragma unroll
            for (int nt=0;nt<16;nt++){
                int n0 = nbase + nt*8;
                uint32_t b0 = ldu(&KT[(n0+gid)*FP + k0 + t4]);
                uint32_t b1 = ldu(&KT[(n0+gid)*FP + k0 + t4 + 4]);
                mma_tf32(c[nt], a0,a1,a2,a3, b0,b1);
            }
        }
    }
    __syncthreads();
    #pragma unroll
    for (int nt=0;nt<16;nt++){
        int col = nbase + nt*8 + t4*2;
        int r0 = erow + gid;
        Ssm[r0*CP + col]       = c[nt][0];
        Ssm[r0*CP + col+1]     = c[nt][1];
        Ssm[(r0+8)*CP + col]   = c[nt][2];
        Ssm[(r0+8)*CP + col+1] = c[nt][3];
    }
    __syncthreads();
    for (int i=tid;i<16384;i+=256)
        Sout[i] = Ssm[(i>>8)*CP + (i&255)];
    Zout[tid] = z;
}

// ================= exclusive prefix over chunks =================
__global__ __launch_bounds__(256) void prefix_kernel(){
    int idx = blockIdx.x*256 + threadIdx.x;
    const int totS = BH*MDIM*DDIM;
    if (idx < totS){
        int bh = idx >> 14;
        int j  = idx & 16383;
        float acc = g_Scond[idx];
        float* p = g_S + (size_t)bh*NCH*MDIM*DDIM + j;
        #pragma unroll 4
        for (int c=0;c<NCH;c++){
            float t = p[(size_t)c*MDIM*DDIM];
            p[(size_t)c*MDIM*DDIM] = acc;
            acc += t;
        }
    } else {
        int k2 = idx - totS;
        int bh = k2 >> 8;
        int j  = k2 & 255;
        float acc = g_Zcond[k2];
        float* p = g_Z + bh*NCH*MDIM + j;
        #pragma unroll 4
        for (int c=0;c<NCH;c++){
            float t = p[c*MDIM];
            p[c*MDIM] = acc;
            acc += t;
        }
    }
}

// ================= attention output (tf32 mma) =================
__global__ __launch_bounds__(256) void attn_mma(const float* __restrict__ v,
                                                float* __restrict__ out){
    extern __shared__ float sm[];
    float* Qs = sm;             // [64 t][FP m] tf32
    float* Ks = sm + 64*FP;     // [64 t'][FP m] tf32 ; reused as VT[e][s]
    float* Ss = sm + 2*64*FP;   // [64 e][FP m] tf32 ; reused as As[t][s]
    __shared__ float zps[64];
    __shared__ float den2p[4][64];
    __shared__ float denrow[64];
    __shared__ float invden[64];

    int tid = threadIdx.x, lane = tid&31, warp = tid>>5;
    int gid = lane>>2, t4 = lane&3;
    int bh = blockIdx.y, cc = blockIdx.x;
    bool is_cond = (cc < 4);
    int rowbase;
    const float *Sp, *zp;
    if (is_cond){
        rowbase = bh*NSEQ + cc*64;
        Sp = g_Scond + (size_t)bh*MDIM*DDIM;
        zp = g_Zcond + bh*MDIM;
    } else {
        int c = cc-4;
        rowbase = bh*NSEQ + LCOND + c*CSZ;
        Sp = g_S + (size_t)(bh*NCH + c)*MDIM*DDIM;
        zp = g_Z + (bh*NCH + c)*MDIM;
    }
    const float* Qg = g_qp + (size_t)rowbase*MDIM;
    const float* Kg = g_kp + (size_t)rowbase*MDIM;
    const float* Vg = v + (size_t)rowbase*DDIM;
    float epsv = is_cond ? 0.f : SEPS;

    if (tid<64) denrow[tid] = 0.f;

    float accO[4][4], accA[4][4];
    #pragma unroll
    for (int nt=0;nt<4;nt++){
        accO[nt][0]=0.f;accO[nt][1]=0.f;accO[nt][2]=0.f;accO[nt][3]=0.f;
        accA[nt][0]=0.f;accA[nt][1]=0.f;accA[nt][2]=0.f;accA[nt][3]=0.f;
    }
    float den2 = 0.f;
    int mrow = (warp>>1)*16;
    int nb = (warp&1)*32;

    for (int mt=0;mt<4;mt++){
        int m0 = mt*64;
        __syncthreads();
        for (int i=tid;i<4096;i+=256){
            int t = i>>6, mm = i&63;
            Qs[t*FP+mm] = f2tff(Qg[(size_t)t*MDIM + m0 + mm]);
        }
        if (!is_cond){
            for (int i=tid;i<4096;i+=256){
                int t = i>>6, mm = i&63;
                Ks[t*FP+mm] = f2tff(Kg[(size_t)t*MDIM + m0 + mm]);
            }
        }
        for (int i=tid;i<4096;i+=256){
            int e = i>>6, mm = i&63;
            Ss[e*FP+mm] = f2tff(Sp[e*MDIM + m0 + mm]);
        }
        if (tid<64) zps[tid] = zp[m0+tid];
        __syncthreads();
        // denominator: q . (zp + eps)  (f32)
        {
            int row = tid&63, grp = tid>>6;
            float d = 0.f;
            #pragma unroll
            for (int j=0;j<16;j++){
                int mm = grp*16 + j;
                d = fmaf(Qs[row*FP+mm], zps[mm]+epsv, d);
            }
            den2 += d;
        }
        #pragma unroll
        for (int k0=0;k0<64;k0+=8){
            uint32_t a0 = ldu(&Qs[(mrow+gid  )*FP + k0 + t4]);
            uint32_t a1 = ldu(&Qs[(mrow+gid+8)*FP + k0 + t4]);
            uint32_t a2 = ldu(&Qs[(mrow+gid  )*FP + k0 + t4 + 4]);
            uint32_t a3 = ldu(&Qs[(mrow+gid+8)*FP + k0 + t4 + 4]);
            #pragma unroll
            for (int nt=0;nt<4;nt++){
                int n0 = nb + nt*8;
                uint32_t s0 = ldu(&Ss[(n0+gid)*FP + k0 + t4]);
                uint32_t s1 = ldu(&Ss[(n0+gid)*FP + k0 + t4 + 4]);
                mma_tf32(accO[nt], a0,a1,a2,a3, s0,s1);
            }
            if (!is_cond){
                #pragma unroll
                for (int nt=0;nt<4;nt++){
                    int n0 = nb + nt*8;
                    uint32_t b0 = ldu(&Ks[(n0+gid)*FP + k0 + t4]);
                    uint32_t b1 = ldu(&Ks[(n0+gid)*FP + k0 + t4 + 4]);
                    mma_tf32(accA[nt], a0,a1,a2,a3, b0,b1);
                }
            }
        }
    }
    __syncthreads();
    den2p[tid>>6][tid&63] = den2;

    if (!is_cond){
        // mask + stage scores (tf32) into Ss-region (As[t][s]); rowsum in f32
        float rs0 = 0.f, rs1 = 0.f;
        #pragma unroll
        for (int nt=0;nt<4;nt++){
            int col = nb + nt*8 + t4*2;
            int r0 = mrow + gid;
            float v00 = (col   <= r0  ) ? accA[nt][0] : 0.f;
            float v01 = (col+1 <= r0  ) ? accA[nt][1] : 0.f;
            float v10 = (col   <= r0+8) ? accA[nt][2] : 0.f;
            float v11 = (col+1 <= r0+8) ? accA[nt][3] : 0.f;
            rs0 += v00 + v01; rs1 += v10 + v11;
            Ss[r0*FP + col]       = f2tff(v00);
            Ss[r0*FP + col+1]     = f2tff(v01);
            Ss[(r0+8)*FP + col]   = f2tff(v10);
            Ss[(r0+8)*FP + col+1] = f2tff(v11);
        }
        atomicAdd(&denrow[mrow+gid],   rs0);
        atomicAdd(&denrow[mrow+gid+8], rs1);
        // stage V transposed into Ks-region: VT[e][s]
        for (int i=tid;i<4096;i+=256){
            int s = i>>6, e = i&63;
            Ks[e*FP + s] = f2tff(Vg[(size_t)s*DDIM + e]);
        }
        __syncthreads();
        // O += A_mask @ V
        #pragma unroll
        for (int k0=0;k0<64;k0+=8){
            uint32_t a0 = ldu(&Ss[(mrow+gid  )*FP + k0 + t4]);
            uint32_t a1 = ldu(&Ss[(mrow+gid+8)*FP + k0 + t4]);
            uint32_t a2 = ldu(&Ss[(mrow+gid  )*FP + k0 + t4 + 4]);
            uint32_t a3 = ldu(&Ss[(mrow+gid+8)*FP + k0 + t4 + 4]);
            #pragma unroll
            for (int nt=0;nt<4;nt++){
                int n0 = nb + nt*8;
                uint32_t b0 = ldu(&Ks[(n0+gid)*FP + k0 + t4]);
                uint32_t b1 = ldu(&Ks[(n0+gid)*FP + k0 + t4 + 4]);
                mma_tf32(accO[nt], a0,a1,a2,a3, b0,b1);
            }
        }
    }
    __syncthreads();
    if (tid<64){
        float d = denrow[tid] + den2p[0][tid] + den2p[1][tid]
                + den2p[2][tid] + den2p[3][tid];
        invden[tid] = 1.f / d;
    }
    __syncthreads();
    #pragma unroll
    for (int nt=0;nt<4;nt++){
        int col = nb + nt*8 + t4*2;
        int r0 = mrow + gid;
        float i0 = invden[r0], i1 = invden[r0+8];
        float2 o0 = make_float2(accO[nt][0]*i0, accO[nt][1]*i0);
        float2 o1 = make_float2(accO[nt][2]*i1, accO[nt][3]*i1);
        *reinterpret_cast<float2*>(&out[(size_t)(rowbase+r0  )*DDIM + col]) = o0;
        *reinterpret_cast<float2*>(&out[(size_t)(rowbase+r0+8)*DDIM + col]) = o1;
    }
}

// ================= launch =================
extern "C" void kernel_launch(void* const* d_in, const int* in_sizes, int n_in,
                              void* d_out, int out_size){
    const float* q    = (const float*)d_in[0];
    const float* k    = (const float*)d_in[1];
    const float* v    = (const float*)d_in[2];
    const float* proj = (const float*)d_in[3];
    float* out = (float*)d_out;

    const int BIG_SMEM  = (64*FP + 256*FP)*sizeof(float);   // 87040
    const int ATTN_SMEM = 3*64*FP*sizeof(float);            // 52224
    static bool attr_done = false;
    if (!attr_done){
        cudaFuncSetAttribute(feat_mma<true>,  cudaFuncAttributeMaxDynamicSharedMemorySize, BIG_SMEM);
        cudaFuncSetAttribute(feat_mma<false>, cudaFuncAttributeMaxDynamicSharedMemorySize, BIG_SMEM);
        cudaFuncSetAttribute(chunk_mma,       cudaFuncAttributeMaxDynamicSharedMemorySize, BIG_SMEM);
        cudaFuncSetAttribute(attn_mma,        cudaFuncAttributeMaxDynamicSharedMemorySize, ATTN_SMEM);
        attr_done = true;
    }

    reset_kernel<<<1,1>>>();
    feat_mma<false><<<2048,256,BIG_SMEM>>>(k, proj);
    feat_mma<true ><<<2048,256,BIG_SMEM>>>(q, proj);
    kfin_kernel<<<32768,256>>>();
    chunk_mma<<<dim3(61,32),256,BIG_SMEM>>>(v);
    prefix_kernel<<<2080,256>>>();
    attn_mma<<<dim3(64,32),256,ATTN_SMEM>>>(v, out);
}

// round 6
// speedup vs baseline: 2.2406x; 1.9342x over previous
#include <cuda_runtime.h>
#include <math.h>
#include <stdint.h>

#define BH    32
#define NSEQ  4096
#define DDIM  64
#define MDIM  256
#define LCOND 256
#define CSZ   64
#define NCH   60          // (4096-256)/64
#define DN    0.35355339059327373f   // 64^-0.25
#define RATIO 0.0625f                // 256^-0.5
#define DIAGC 0.0625f                // dn^2 * 0.5
#define KEPS  1e-4f
#define SEPS  1e-6f
#define FP    68          // padded stride for 64-wide smem tiles
#define CP    260         // padded stride for 256-wide smem tiles

// ---------------- scratch ----------------
__device__ float g_qp[BH*NSEQ*MDIM];       // tf32-rounded query features
__device__ float g_kp[BH*NSEQ*MDIM];       // key features (pre-exp f32, then tf32 after kfin)
__device__ float g_S [BH*NCH*MDIM*DDIM];   // per-chunk ctx [e][m] -> tf32-rounded prefix
__device__ float g_Z [BH*NCH*MDIM];
__device__ float g_Scond[BH*MDIM*DDIM];    // [e][m] tf32-rounded
__device__ float g_Zcond[BH*MDIM];
__device__ float g_vt[BH*NSEQ*DDIM];       // tf32-rounded V
__device__ float g_P [MDIM*DDIM];          // tf32-rounded DN*proj
__device__ unsigned g_kmax_bits;

__device__ __forceinline__ unsigned enc_f(float f){
    unsigned u = __float_as_uint(f);
    return (u & 0x80000000u) ? ~u : (u | 0x80000000u);
}
__device__ __forceinline__ float dec_f(unsigned e){
    return (e & 0x80000000u) ? __uint_as_float(e & 0x7FFFFFFFu)
                             : __uint_as_float(~e);
}
__device__ __forceinline__ float f2tff(float f){
    uint32_t r; asm("cvt.rna.tf32.f32 %0, %1;" : "=r"(r) : "f"(f));
    return __uint_as_float(r);
}
__device__ __forceinline__ void mma_tf32(float c[4],
        uint32_t a0,uint32_t a1,uint32_t a2,uint32_t a3,
        uint32_t b0,uint32_t b1){
    asm volatile("mma.sync.aligned.m16n8k8.row.col.f32.tf32.tf32.f32 "
        "{%0,%1,%2,%3}, {%4,%5,%6,%7}, {%8,%9}, {%0,%1,%2,%3};"
        : "+f"(c[0]),"+f"(c[1]),"+f"(c[2]),"+f"(c[3])
        : "r"(a0),"r"(a1),"r"(a2),"r"(a3),"r"(b0),"r"(b1));
}
__device__ __forceinline__ uint32_t ldu(const float* p){ return __float_as_uint(*p); }
__device__ __forceinline__ uint32_t smem_u32(const void* p){
    uint32_t a;
    asm("{ .reg .u64 t; cvta.to.shared.u64 t, %1; cvt.u32.u64 %0, t; }"
        : "=r"(a) : "l"(p));
    return a;
}
__device__ __forceinline__ void cpa16(uint32_t dst, const void* src){
    asm volatile("cp.async.cg.shared.global [%0], [%1], 16;" :: "r"(dst), "l"(src));
}
#define CPA_COMMIT() asm volatile("cp.async.commit_group;" ::: "memory")
#define CPA_WAIT0()  asm volatile("cp.async.wait_group 0;" ::: "memory")

__global__ void reset_kernel(){ g_kmax_bits = 0u; }

// ---------------- prep: rounded P and V ----------------
__global__ __launch_bounds__(256) void prep_kernel(const float* __restrict__ proj,
                                                   const float* __restrict__ v){
    int i = blockIdx.x*256 + threadIdx.x;
    float4 x = reinterpret_cast<const float4*>(v)[i];
    x.x = f2tff(x.x); x.y = f2tff(x.y); x.z = f2tff(x.z); x.w = f2tff(x.w);
    reinterpret_cast<float4*>(g_vt)[i] = x;
    if (i < 4096){
        float4 p = reinterpret_cast<const float4*>(proj)[i];
        p.x = f2tff(p.x*DN); p.y = f2tff(p.y*DN);
        p.z = f2tff(p.z*DN); p.w = f2tff(p.w*DN);
        reinterpret_cast<float4*>(g_P)[i] = p;
    }
}

// ================= feature kernel =================
// Block: 64 rows. D[64 x 256] = X @ (DN*P)^T.
// smem: sA frag-order [4 mt][8 s][32 lane][4] (16KB), sB pair-order (64KB);
// epilogue overlays Csm[64][CP].
template<bool IS_Q>
__global__ __launch_bounds__(256) void feat_mma(const float* __restrict__ data){
    extern __shared__ float sm[];
    float* sA  = sm;             // 4096 floats
    float* sB  = sm + 4096;      // 16384 floats
    float* Csm = sm;             // overlay 64*CP
    __shared__ float rowsq[64], rowst[64];
    __shared__ unsigned bmax;

    int tid = threadIdx.x, lane = tid & 31, warp = tid >> 5;
    int gid = lane >> 2, t4 = lane & 3;
    int rowbase = blockIdx.x * 64;
    if (tid == 0) bmax = 0u;
    if (tid < 64) rowsq[tid] = 0.f;
    __syncthreads();

    // stage X: frag order + rowsq
    const float* xg = data + (size_t)rowbase * DDIM;
    {
        // thread handles i = tid + 256k: kk = tid&63 const, r = (tid>>6)+4k
        int kk = tid & 63;
        int s = kk >> 3, t4s = kk & 3, jk = ((kk >> 2) & 1) << 1;
        #pragma unroll
        for (int kloop = 0; kloop < 16; kloop++){
            int r = (tid >> 6) + kloop*4;
            float x = xg[r*64 + kk];
            float sq = x * x;
            #pragma unroll
            for (int o = 16; o; o >>= 1) sq += __shfl_xor_sync(~0u, sq, o);
            if (lane == 0) atomicAdd(&rowsq[r], sq);
            int mt = r >> 4, rr = r & 15;
            int ln = ((rr & 7) << 2) | t4s;
            int j  = (rr >> 3) | jk;
            sA[(mt*8 + s)*128 + ln*4 + j] = f2tff(x);
        }
    }
    // stage P: pair order (pre-rounded)
    {
        int kk = tid & 63;
        int s = kk >> 3, t4s = kk & 3, h = (kk >> 2) & 1;
        #pragma unroll
        for (int kloop = 0; kloop < 64; kloop++){
            int n = (tid >> 6) + kloop*4;
            int ntg = n >> 3, g = n & 7;
            sB[(ntg*8 + s)*64 + g*8 + ((t4s ^ (ntg & 3)) << 1) + h] = g_P[n*64 + kk];
        }
    }
    __syncthreads();

    float c[16][4];
    #pragma unroll
    for (int nt = 0; nt < 16; nt++){ c[nt][0]=0.f;c[nt][1]=0.f;c[nt][2]=0.f;c[nt][3]=0.f; }
    int mt = warp >> 1, nbh = warp & 1;
    #pragma unroll
    for (int s = 0; s < 8; s++){
        float4 av = *reinterpret_cast<float4*>(&sA[(mt*8 + s)*128 + lane*4]);
        uint32_t a0 = __float_as_uint(av.x), a1 = __float_as_uint(av.y);
        uint32_t a2 = __float_as_uint(av.z), a3 = __float_as_uint(av.w);
        #pragma unroll
        for (int nt = 0; nt < 16; nt++){
            int ntg = nbh*16 + nt;
            float2 bv = *reinterpret_cast<float2*>(
                &sB[(ntg*8 + s)*64 + gid*8 + ((t4 ^ (ntg & 3)) << 1)]);
            mma_tf32(c[nt], a0,a1,a2,a3,
                     __float_as_uint(bv.x), __float_as_uint(bv.y));
        }
    }
    __syncthreads();     // operands consumed; overlay Csm

    int mrow = mt*16, nbase = nbh*128;
    #pragma unroll
    for (int nt = 0; nt < 16; nt++){
        int col = nbase + nt*8 + t4*2;
        int r0 = mrow + gid;
        Csm[r0*CP + col]       = c[nt][0];
        Csm[r0*CP + col+1]     = c[nt][1];
        Csm[(r0+8)*CP + col]   = c[nt][2];
        Csm[(r0+8)*CP + col+1] = c[nt][3];
    }
    __syncthreads();

    int row = tid >> 2, q = tid & 3;
    if (IS_Q){
        float mx = -3.4e38f;
        #pragma unroll 8
        for (int i = 0; i < 64; i++) mx = fmaxf(mx, Csm[row*CP + q*64 + i]);
        mx = fmaxf(mx, __shfl_xor_sync(~0u, mx, 1));
        mx = fmaxf(mx, __shfl_xor_sync(~0u, mx, 2));
        if (q == 0) rowst[row] = mx;
        __syncthreads();
        float* og = g_qp + (size_t)rowbase*MDIM;
        for (int i = tid; i < 16384; i += 256){
            int r = i >> 8, cc = i & 255;
            og[i] = f2tff(RATIO*(__expf(Csm[r*CP+cc] - rowsq[r]*DIAGC - rowst[r]) + KEPS));
        }
    } else {
        float mx = -3.4e38f;
        #pragma unroll 8
        for (int i = 0; i < 64; i++) mx = fmaxf(mx, Csm[row*CP + q*64 + i]);
        #pragma unroll
        for (int o = 16; o; o >>= 1) mx = fmaxf(mx, __shfl_xor_sync(~0u, mx, o));
        if (lane == 0) atomicMax(&bmax, enc_f(mx));
        __syncthreads();
        float* og = g_kp + (size_t)rowbase*MDIM;
        for (int i = tid; i < 16384; i += 256){
            int r = i >> 8;
            og[i] = Csm[r*CP + (i & 255)] - rowsq[r]*DIAGC;
        }
        if (tid == 0) atomicMax(&g_kmax_bits, bmax);
    }
}

// ================= kp finalize: exp + tf32 round =================
__global__ __launch_bounds__(256) void kfin_kernel(){
    float kmax = dec_f(g_kmax_bits);
    size_t i = (size_t)blockIdx.x*blockDim.x + threadIdx.x;
    float4 x = reinterpret_cast<float4*>(g_kp)[i];
    x.x = f2tff(RATIO*(__expf(x.x-kmax)+KEPS));
    x.y = f2tff(RATIO*(__expf(x.y-kmax)+KEPS));
    x.z = f2tff(RATIO*(__expf(x.z-kmax)+KEPS));
    x.w = f2tff(RATIO*(__expf(x.w-kmax)+KEPS));
    reinterpret_cast<float4*>(g_kp)[i] = x;
}

// ================= chunk states =================
// S[e][m] = sum_r v[r][e]*kp[r][m] ; z[m] = sum_r kp[r][m] (f32)
__global__ __launch_bounds__(256) void chunk_mma(){
    extern __shared__ float sm[];
    float* VT  = sm;             // [64 e][FP r]   17408B
    float* KT  = sm + 64*FP;     // pair-order 64KB
    float* Ssm = sm;             // overlay [64][CP]

    int tid = threadIdx.x, lane = tid & 31, warp = tid >> 5;
    int gid = lane >> 2, t4 = lane & 3;
    int bh = blockIdx.y, cidx = blockIdx.x;   // 0=cond, 1..60 rest
    int rowbase, npass;
    float *Sout, *Zout;
    if (cidx == 0){
        rowbase = bh*NSEQ; npass = 4;
        Sout = g_Scond + (size_t)bh*MDIM*DDIM;
        Zout = g_Zcond + bh*MDIM;
    } else {
        rowbase = bh*NSEQ + LCOND + (cidx-1)*CSZ; npass = 1;
        Sout = g_S + (size_t)(bh*NCH + cidx-1)*MDIM*DDIM;
        Zout = g_Z + (bh*NCH + cidx-1)*MDIM;
    }

    float c[16][4];
    #pragma unroll
    for (int nt = 0; nt < 16; nt++){ c[nt][0]=0.f;c[nt][1]=0.f;c[nt][2]=0.f;c[nt][3]=0.f; }
    float z = 0.f;
    int erow = (warp >> 1)*16, nbh = warp & 1;

    // per-thread constant B indexing: m = tid
    int m_ntg = tid >> 3, m_g = tid & 7, m_x = m_ntg & 3;
    for (int p = 0; p < npass; p++){
        int r0 = rowbase + p*64;
        __syncthreads();
        const float* vg = g_vt + (size_t)r0*DDIM;
        for (int i = tid; i < 4096; i += 256){
            int r = i >> 6, e = i & 63;
            VT[e*FP + r] = vg[i];
        }
        const float* kg = g_kp + (size_t)r0*MDIM + tid;
        #pragma unroll 4
        for (int r = 0; r < 64; r++){
            float kv = kg[(size_t)r*MDIM];
            z += kv;
            int s = r >> 3, t4s = r & 3, h = (r >> 2) & 1;
            KT[(m_ntg*8 + s)*64 + m_g*8 + ((t4s ^ m_x) << 1) + h] = kv;
        }
        __syncthreads();
        #pragma unroll
        for (int s = 0; s < 8; s++){
            int k0 = s*8;
            uint32_t a0 = ldu(&VT[(erow+gid  )*FP + k0 + t4]);
            uint32_t a1 = ldu(&VT[(erow+gid+8)*FP + k0 + t4]);
            uint32_t a2 = ldu(&VT[(erow+gid  )*FP + k0 + t4 + 4]);
            uint32_t a3 = ldu(&VT[(erow+gid+8)*FP + k0 + t4 + 4]);
            #pragma unroll
            for (int nt = 0; nt < 16; nt++){
                int ntg = nbh*16 + nt;
                float2 bv = *reinterpret_cast<float2*>(
                    &KT[(ntg*8 + s)*64 + gid*8 + ((t4 ^ (ntg & 3)) << 1)]);
                mma_tf32(c[nt], a0,a1,a2,a3,
                         __float_as_uint(bv.x), __float_as_uint(bv.y));
            }
        }
    }
    Zout[tid] = z;
    __syncthreads();
    int nbase = nbh*128;
    #pragma unroll
    for (int nt = 0; nt < 16; nt++){
        int col = nbase + nt*8 + t4*2;
        int r0 = erow + gid;
        Ssm[r0*CP + col]       = c[nt][0];
        Ssm[r0*CP + col+1]     = c[nt][1];
        Ssm[(r0+8)*CP + col]   = c[nt][2];
        Ssm[(r0+8)*CP + col+1] = c[nt][3];
    }
    __syncthreads();
    for (int i = tid; i < 16384; i += 256)
        Sout[i] = f2tff(Ssm[(i >> 8)*CP + (i & 255)]);
}

// ================= exclusive prefix over chunks =================
__global__ __launch_bounds__(256) void prefix_kernel(){
    int idx = blockIdx.x*256 + threadIdx.x;
    const int totS = BH*MDIM*DDIM;
    if (idx < totS){
        int bh = idx >> 14;
        int j  = idx & 16383;
        float acc = g_Scond[idx];
        float* p = g_S + (size_t)bh*NCH*MDIM*DDIM + j;
        #pragma unroll 4
        for (int c = 0; c < NCH; c++){
            float t = p[(size_t)c*MDIM*DDIM];
            p[(size_t)c*MDIM*DDIM] = f2tff(acc);
            acc += t;
        }
    } else {
        int k2 = idx - totS;
        if (k2 < BH*MDIM){
            int bh = k2 >> 8;
            int j  = k2 & 255;
            float acc = g_Zcond[k2];
            float* p = g_Z + bh*NCH*MDIM + j;
            #pragma unroll 4
            for (int c = 0; c < NCH; c++){
                float t = p[c*MDIM];
                p[c*MDIM] = acc;
                acc += t;
            }
        }
    }
}

// ================= attention output =================
__global__ __launch_bounds__(256) void attn_mma(float* __restrict__ out){
    extern __shared__ float sm[];
    float* Qs = sm;             // [64 t][FP m]
    float* Ks = sm + 64*FP;     // [64 t'][FP m] ; phase2: VT[e][s]
    float* Ss = sm + 2*64*FP;   // [64 e][FP m]  ; phase2: As[t][s]
    __shared__ float zps[64];
    __shared__ float den2p[4][64];
    __shared__ float denrow[64];
    __shared__ float invden[64];

    int tid = threadIdx.x, lane = tid & 31, warp = tid >> 5;
    int gid = lane >> 2, t4 = lane & 3;
    int bh = blockIdx.y, cc = blockIdx.x;
    bool is_cond = (cc < 4);
    int rowbase;
    const float *Sp, *zp;
    if (is_cond){
        rowbase = bh*NSEQ + cc*64;
        Sp = g_Scond + (size_t)bh*MDIM*DDIM;
        zp = g_Zcond + bh*MDIM;
    } else {
        int c = cc - 4;
        rowbase = bh*NSEQ + LCOND + c*CSZ;
        Sp = g_S + (size_t)(bh*NCH + c)*MDIM*DDIM;
        zp = g_Z + (bh*NCH + c)*MDIM;
    }
    const float* Qg = g_qp + (size_t)rowbase*MDIM;
    const float* Kg = g_kp + (size_t)rowbase*MDIM;
    const float* Vg = g_vt + (size_t)rowbase*DDIM;
    float epsv = is_cond ? 0.f : SEPS;
    uint32_t QsA = smem_u32(Qs), KsA = smem_u32(Ks), SsA = smem_u32(Ss);

    if (tid < 64) denrow[tid] = 0.f;

    float accO[4][4], accA[4][4];
    #pragma unroll
    for (int nt = 0; nt < 4; nt++){
        accO[nt][0]=0.f;accO[nt][1]=0.f;accO[nt][2]=0.f;accO[nt][3]=0.f;
        accA[nt][0]=0.f;accA[nt][1]=0.f;accA[nt][2]=0.f;accA[nt][3]=0.f;
    }
    float den2 = 0.f;
    int mrow = (warp >> 1)*16;
    int nb = (warp & 1)*32;

    for (int mtl = 0; mtl < 4; mtl++){
        int m0 = mtl*64;
        __syncthreads();
        for (int i = tid; i < 1024; i += 256){
            int t = i >> 4, qd = (i & 15)*4;
            cpa16(QsA + (t*FP + qd)*4, Qg + (size_t)t*MDIM + m0 + qd);
            cpa16(SsA + (t*FP + qd)*4, Sp + t*MDIM + m0 + qd);
        }
        if (!is_cond)
            for (int i = tid; i < 1024; i += 256){
                int t = i >> 4, qd = (i & 15)*4;
                cpa16(KsA + (t*FP + qd)*4, Kg + (size_t)t*MDIM + m0 + qd);
            }
        if (tid < 64) zps[tid] = zp[m0 + tid];
        CPA_COMMIT(); CPA_WAIT0();
        __syncthreads();
        // denominator: q . (zp + eps)  (f32)
        {
            int row = tid & 63, grp = tid >> 6;
            float d = 0.f;
            #pragma unroll
            for (int j = 0; j < 16; j++){
                int mm = grp*16 + j;
                d = fmaf(Qs[row*FP + mm], zps[mm] + epsv, d);
            }
            den2 += d;
        }
        #pragma unroll
        for (int s = 0; s < 8; s++){
            int k0 = s*8;
            uint32_t a0 = ldu(&Qs[(mrow+gid  )*FP + k0 + t4]);
            uint32_t a1 = ldu(&Qs[(mrow+gid+8)*FP + k0 + t4]);
            uint32_t a2 = ldu(&Qs[(mrow+gid  )*FP + k0 + t4 + 4]);
            uint32_t a3 = ldu(&Qs[(mrow+gid+8)*FP + k0 + t4 + 4]);
            #pragma unroll
            for (int nt = 0; nt < 4; nt++){
                int n0 = nb + nt*8;
                uint32_t s0 = ldu(&Ss[(n0+gid)*FP + k0 + t4]);
                uint32_t s1 = ldu(&Ss[(n0+gid)*FP + k0 + t4 + 4]);
                mma_tf32(accO[nt], a0,a1,a2,a3, s0,s1);
            }
            if (!is_cond){
                #pragma unroll
                for (int nt = 0; nt < 4; nt++){
                    int n0 = nb + nt*8;
                    uint32_t b0 = ldu(&Ks[(n0+gid)*FP + k0 + t4]);
                    uint32_t b1 = ldu(&Ks[(n0+gid)*FP + k0 + t4 + 4]);
                    mma_tf32(accA[nt], a0,a1,a2,a3, b0,b1);
                }
            }
        }
    }
    __syncthreads();
    den2p[tid >> 6][tid & 63] = den2;

    if (!is_cond){
        // mask + stage scores (tf32) into Ss (As[t][s]); rowsum f32
        float rs0 = 0.f, rs1 = 0.f;
        #pragma unroll
        for (int nt = 0; nt < 4; nt++){
            int col = nb + nt*8 + t4*2;
            int r0 = mrow + gid;
            float v00 = (col   <= r0  ) ? accA[nt][0] : 0.f;
            float v01 = (col+1 <= r0  ) ? accA[nt][1] : 0.f;
            float v10 = (col   <= r0+8) ? accA[nt][2] : 0.f;
            float v11 = (col+1 <= r0+8) ? accA[nt][3] : 0.f;
            rs0 += v00 + v01; rs1 += v10 + v11;
            Ss[r0*FP + col]       = f2tff(v00);
            Ss[r0*FP + col+1]     = f2tff(v01);
            Ss[(r0+8)*FP + col]   = f2tff(v10);
            Ss[(r0+8)*FP + col+1] = f2tff(v11);
        }
        atomicAdd(&denrow[mrow+gid],   rs0);
        atomicAdd(&denrow[mrow+gid+8], rs1);
        // stage V transposed (pre-rounded): VT[e][s]
        for (int i = tid; i < 4096; i += 256){
            int s = i >> 6, e = i & 63;
            Ks[e*FP + s] = Vg[i];
        }
        __syncthreads();
        // O += A_mask @ V
        #pragma unroll
        for (int s = 0; s < 8; s++){
            int k0 = s*8;
            uint32_t a0 = ldu(&Ss[(mrow+gid  )*FP + k0 + t4]);
            uint32_t a1 = ldu(&Ss[(mrow+gid+8)*FP + k0 + t4]);
            uint32_t a2 = ldu(&Ss[(mrow+gid  )*FP + k0 + t4 + 4]);
            uint32_t a3 = ldu(&Ss[(mrow+gid+8)*FP + k0 + t4 + 4]);
            #pragma unroll
            for (int nt = 0; nt < 4; nt++){
                int n0 = nb + nt*8;
                uint32_t b0 = ldu(&Ks[(n0+gid)*FP + k0 + t4]);
                uint32_t b1 = ldu(&Ks[(n0+gid)*FP + k0 + t4 + 4]);
                mma_tf32(accO[nt], a0,a1,a2,a3, b0,b1);
            }
        }
    }
    __syncthreads();
    if (tid < 64){
        float d = denrow[tid] + den2p[0][tid] + den2p[1][tid]
                + den2p[2][tid] + den2p[3][tid];
        invden[tid] = 1.f / d;
    }
    __syncthreads();
    #pragma unroll
    for (int nt = 0; nt < 4; nt++){
        int col = nb + nt*8 + t4*2;
        int r0 = mrow + gid;
        float i0 = invden[r0], i1 = invden[r0+8];
        float2 o0 = make_float2(accO[nt][0]*i0, accO[nt][1]*i0);
        float2 o1 = make_float2(accO[nt][2]*i1, accO[nt][3]*i1);
        *reinterpret_cast<float2*>(&out[(size_t)(rowbase+r0  )*DDIM + col]) = o0;
        *reinterpret_cast<float2*>(&out[(size_t)(rowbase+r0+8)*DDIM + col]) = o1;
    }
}

// ================= launch =================
extern "C" void kernel_launch(void* const* d_in, const int* in_sizes, int n_in,
                              void* d_out, int out_size){
    const float* q    = (const float*)d_in[0];
    const float* k    = (const float*)d_in[1];
    const float* v    = (const float*)d_in[2];
    const float* proj = (const float*)d_in[3];
    float* out = (float*)d_out;

    const int FEAT_SMEM  = (4096 + 16384) * 4;        // 81920
    const int CHUNK_SMEM = (64*FP + 16384) * 4;       // 82944
    const int ATTN_SMEM  = 3*64*FP*4;                 // 52224
    cudaFuncSetAttribute(feat_mma<true>,  cudaFuncAttributeMaxDynamicSharedMemorySize, FEAT_SMEM);
    cudaFuncSetAttribute(feat_mma<false>, cudaFuncAttributeMaxDynamicSharedMemorySize, FEAT_SMEM);
    cudaFuncSetAttribute(chunk_mma,       cudaFuncAttributeMaxDynamicSharedMemorySize, CHUNK_SMEM);
    cudaFuncSetAttribute(attn_mma,        cudaFuncAttributeMaxDynamicSharedMemorySize, ATTN_SMEM);

    reset_kernel<<<1,1>>>();
    prep_kernel<<<8192,256>>>(proj, v);
    feat_mma<false><<<2048,256,FEAT_SMEM>>>(k);
    feat_mma<true ><<<2048,256,FEAT_SMEM>>>(q);
    kfin_kernel<<<32768,256>>>();
    chunk_mma<<<dim3(61,32),256,CHUNK_SMEM>>>();
    prefix_kernel<<<2112,256>>>();
    attn_mma<<<dim3(64,32),256,ATTN_SMEM>>>(out);
}

// round 7
// speedup vs baseline: 2.4635x; 1.0995x over previous
#include <cuda_runtime.h>
#include <math.h>
#include <stdint.h>

#define BH    32
#define NSEQ  4096
#define DDIM  64
#define MDIM  256
#define LCOND 256
#define CSZ   64
#define NCH   60          // (4096-256)/64
#define DN    0.35355339059327373f   // 64^-0.25
#define RATIO 0.0625f                // 256^-0.5
#define DIAGC 0.0625f                // dn^2 * 0.5
#define KEPS  1e-4f
#define SEPS  1e-6f
#define FP    68          // padded stride for 64-wide smem tiles
#define CP    260         // padded stride for 256-wide smem tiles

// ---------------- scratch ----------------
__device__ float g_qp[BH*NSEQ*MDIM];       // tf32-rounded query features
__device__ float g_kp[BH*NSEQ*MDIM];       // key features (pre-exp f32, then tf32)
__device__ float g_S [BH*NCH*MDIM*DDIM];   // per-chunk ctx [e][m] -> tf32 prefix
__device__ float g_Z [BH*NCH*MDIM];
__device__ float g_Scond[BH*MDIM*DDIM];    // [e][m]
__device__ float g_Zcond[BH*MDIM];
__device__ float g_vt[BH*NSEQ*DDIM];       // tf32-rounded V
__device__ float4 g_P4[4096];              // DN*proj, tf32, PAIR-ORDER swizzled
__device__ unsigned g_kmax_bits;

__device__ __forceinline__ unsigned enc_f(float f){
    unsigned u = __float_as_uint(f);
    return (u & 0x80000000u) ? ~u : (u | 0x80000000u);
}
__device__ __forceinline__ float dec_f(unsigned e){
    return (e & 0x80000000u) ? __uint_as_float(e & 0x7FFFFFFFu)
                             : __uint_as_float(~e);
}
__device__ __forceinline__ float f2tff(float f){
    uint32_t r; asm("cvt.rna.tf32.f32 %0, %1;" : "=r"(r) : "f"(f));
    return __uint_as_float(r);
}
__device__ __forceinline__ void mma_tf32(float c[4],
        uint32_t a0,uint32_t a1,uint32_t a2,uint32_t a3,
        uint32_t b0,uint32_t b1){
    asm volatile("mma.sync.aligned.m16n8k8.row.col.f32.tf32.tf32.f32 "
        "{%0,%1,%2,%3}, {%4,%5,%6,%7}, {%8,%9}, {%0,%1,%2,%3};"
        : "+f"(c[0]),"+f"(c[1]),"+f"(c[2]),"+f"(c[3])
        : "r"(a0),"r"(a1),"r"(a2),"r"(a3),"r"(b0),"r"(b1));
}
__device__ __forceinline__ void mma4(float c[4], float4 av, float2 bv){
    mma_tf32(c, __float_as_uint(av.x), __float_as_uint(av.y),
                __float_as_uint(av.z), __float_as_uint(av.w),
                __float_as_uint(bv.x), __float_as_uint(bv.y));
}
__device__ __forceinline__ uint32_t ldu(const float* p){ return __float_as_uint(*p); }
__device__ __forceinline__ uint32_t smem_u32(const void* p){
    uint32_t a;
    asm("{ .reg .u64 t; cvta.to.shared.u64 t, %1; cvt.u32.u64 %0, t; }"
        : "=r"(a) : "l"(p));
    return a;
}
__device__ __forceinline__ void cpa16(uint32_t dst, const void* src){
    asm volatile("cp.async.cg.shared.global [%0], [%1], 16;" :: "r"(dst), "l"(src));
}
#define CPA_COMMIT() asm volatile("cp.async.commit_group;" ::: "memory")
#define CPA_WAIT0()  asm volatile("cp.async.wait_group 0;" ::: "memory")

// pair-order B index: element (n,k) -> word offset inside [32|? ntg][8 s][64]
// pos = (ntg*8+s)*64 + ((g^s)<<3) + ((t4k^(ntg&3))<<1) + h
__device__ __forceinline__ int bpos(int n, int k){
    int ntg = n >> 3, g = n & 7, s = k >> 3, t4k = k & 3, h = (k >> 2) & 1;
    return (ntg*8 + s)*64 + ((g ^ s) << 3) + (((t4k ^ (ntg & 3))) << 1) + h;
}

__global__ void reset_kernel(){ g_kmax_bits = 0u; }

// ---------------- prep: rounded V; pair-order swizzled rounded P ----------------
__global__ __launch_bounds__(256) void prep_kernel(const float* __restrict__ proj,
                                                   const float* __restrict__ v){
    int i = blockIdx.x*256 + threadIdx.x;
    float4 x = reinterpret_cast<const float4*>(v)[i];
    x.x = f2tff(x.x); x.y = f2tff(x.y); x.z = f2tff(x.z); x.w = f2tff(x.w);
    reinterpret_cast<float4*>(g_vt)[i] = x;
    if (i < 16384){
        // invert pair-order: pos=i -> (n,k)
        int pos = i;
        int ntg = pos >> 9, s = (pos >> 6) & 7, gg = (pos >> 3) & 7, slot = pos & 7;
        int g = gg ^ s;
        int t4k = ((slot >> 1) ^ ntg) & 3;
        int h = slot & 1;
        int n = ntg*8 + g, k = s*8 + h*4 + t4k;
        reinterpret_cast<float*>(g_P4)[pos] = f2tff(proj[n*64 + k] * DN);
    }
}

// ================= feature kernel =================
// Block: 64 rows, 8 warps. D[64 x 256] = X @ (DN*P)^T.
// warp tile: m32 (mh=warp>>2) x n64 (nq=warp&3).
template<bool IS_Q>
__global__ __launch_bounds__(256) void feat_mma(const float* __restrict__ data){
    extern __shared__ float sm[];
    float* sA  = sm;             // 4096 floats frag-order
    float* sB  = sm + 4096;      // 16384 floats pair-order (cp.async'd)
    float* Csm = sm;             // overlay 64*CP
    __shared__ float rowsq[64], rowst[64];
    __shared__ unsigned bmax;

    int tid = threadIdx.x, lane = tid & 31, warp = tid >> 5;
    int gid = lane >> 2, t4 = lane & 3;
    int rowbase = blockIdx.x * 64;
    if (tid == 0) bmax = 0u;
    if (tid < 64) rowsq[tid] = 0.f;
    __syncthreads();

    // B: straight cp.async from pre-swizzled g_P
    {
        uint32_t sBA = smem_u32(sB);
        const float4* gp = g_P4;
        for (int i = tid; i < 4096; i += 256)
            cpa16(sBA + i*16, gp + i);
        CPA_COMMIT();
    }
    // stage X: frag order + rowsq
    const float* xg = data + (size_t)rowbase * DDIM;
    {
        int kk = tid & 63;
        int s = kk >> 3, t4s = kk & 3, jk = ((kk >> 2) & 1) << 1;
        #pragma unroll
        for (int kloop = 0; kloop < 16; kloop++){
            int r = (tid >> 6) + kloop*4;
            float x = xg[r*64 + kk];
            float sq = x * x;
            #pragma unroll
            for (int o = 16; o; o >>= 1) sq += __shfl_xor_sync(~0u, sq, o);
            if (lane == 0) atomicAdd(&rowsq[r], sq);
            int mt = r >> 4, rr = r & 15;
            int ln = ((rr & 7) << 2) | t4s;
            int j  = (rr >> 3) | jk;
            sA[(mt*8 + s)*128 + ln*4 + j] = f2tff(x);
        }
    }
    CPA_WAIT0();
    __syncthreads();

    int mh = warp >> 2, nq = warp & 3;
    float c[2][8][4];
    #pragma unroll
    for (int mi = 0; mi < 2; mi++)
        #pragma unroll
        for (int nt = 0; nt < 8; nt++){ c[mi][nt][0]=0.f;c[mi][nt][1]=0.f;c[mi][nt][2]=0.f;c[mi][nt][3]=0.f; }

    #pragma unroll
    for (int s = 0; s < 8; s++){
        float4 av0 = *reinterpret_cast<float4*>(&sA[((mh*2  )*8 + s)*128 + lane*4]);
        float4 av1 = *reinterpret_cast<float4*>(&sA[((mh*2+1)*8 + s)*128 + lane*4]);
        #pragma unroll
        for (int nt = 0; nt < 8; nt++){
            int ntg = nq*8 + nt;
            float2 bv = *reinterpret_cast<float2*>(
                &sB[(ntg*8 + s)*64 + ((gid ^ s) << 3) + ((t4 ^ (nt & 3)) << 1)]);
            mma4(c[0][nt], av0, bv);
            mma4(c[1][nt], av1, bv);
        }
    }
    __syncthreads();     // operands consumed; overlay Csm

    #pragma unroll
    for (int mi = 0; mi < 2; mi++){
        int r0 = (mh*2 + mi)*16 + gid;
        #pragma unroll
        for (int nt = 0; nt < 8; nt++){
            int col = nq*64 + nt*8 + t4*2;
            Csm[r0*CP + col]       = c[mi][nt][0];
            Csm[r0*CP + col+1]     = c[mi][nt][1];
            Csm[(r0+8)*CP + col]   = c[mi][nt][2];
            Csm[(r0+8)*CP + col+1] = c[mi][nt][3];
        }
    }
    __syncthreads();

    int row = tid >> 2, q = tid & 3;
    if (IS_Q){
        float mx = -3.4e38f;
        #pragma unroll 8
        for (int i = 0; i < 64; i++) mx = fmaxf(mx, Csm[row*CP + q*64 + i]);
        mx = fmaxf(mx, __shfl_xor_sync(~0u, mx, 1));
        mx = fmaxf(mx, __shfl_xor_sync(~0u, mx, 2));
        if (q == 0) rowst[row] = mx;
        __syncthreads();
        float* og = g_qp + (size_t)rowbase*MDIM;
        for (int i = tid; i < 16384; i += 256){
            int r = i >> 8, cc = i & 255;
            og[i] = f2tff(RATIO*(__expf(Csm[r*CP+cc] - rowsq[r]*DIAGC - rowst[r]) + KEPS));
        }
    } else {
        float mx = -3.4e38f;
        #pragma unroll 8
        for (int i = 0; i < 64; i++) mx = fmaxf(mx, Csm[row*CP + q*64 + i]);
        #pragma unroll
        for (int o = 16; o; o >>= 1) mx = fmaxf(mx, __shfl_xor_sync(~0u, mx, o));
        if (lane == 0) atomicMax(&bmax, enc_f(mx));
        __syncthreads();
        float* og = g_kp + (size_t)rowbase*MDIM;
        for (int i = tid; i < 16384; i += 256){
            int r = i >> 8;
            og[i] = Csm[r*CP + (i & 255)] - rowsq[r]*DIAGC;
        }
        if (tid == 0) atomicMax(&g_kmax_bits, bmax);
    }
}

// ================= kp finalize: exp + tf32 round =================
__global__ __launch_bounds__(256) void kfin_kernel(){
    float kmax = dec_f(g_kmax_bits);
    size_t i = (size_t)blockIdx.x*blockDim.x + threadIdx.x;
    float4 x = reinterpret_cast<float4*>(g_kp)[i];
    x.x = f2tff(RATIO*(__expf(x.x-kmax)+KEPS));
    x.y = f2tff(RATIO*(__expf(x.y-kmax)+KEPS));
    x.z = f2tff(RATIO*(__expf(x.z-kmax)+KEPS));
    x.w = f2tff(RATIO*(__expf(x.w-kmax)+KEPS));
    reinterpret_cast<float4*>(g_kp)[i] = x;
}

// ================= chunk states =================
// S[e][m] = sum_r v[r][e]*kp[r][m] ; z[m] = sum_r kp[r][m] (f32)
// warp tile: e32 (eh=warp>>2) x m64 (nq=warp&3)
__global__ __launch_bounds__(256) void chunk_mma(){
    extern __shared__ float sm[];
    float* VT  = sm;             // [64 e][FP r]
    float* KT  = sm + 64*FP;     // pair-order 16384 floats
    float* Ssm = sm;             // overlay [64][CP]

    int tid = threadIdx.x, lane = tid & 31, warp = tid >> 5;
    int gid = lane >> 2, t4 = lane & 3;
    int bh = blockIdx.y, cidx = blockIdx.x;   // 0=cond, 1..60 rest
    int rowbase, npass;
    float *Sout, *Zout;
    if (cidx == 0){
        rowbase = bh*NSEQ; npass = 4;
        Sout = g_Scond + (size_t)bh*MDIM*DDIM;
        Zout = g_Zcond + bh*MDIM;
    } else {
        rowbase = bh*NSEQ + LCOND + (cidx-1)*CSZ; npass = 1;
        Sout = g_S + (size_t)(bh*NCH + cidx-1)*MDIM*DDIM;
        Zout = g_Z + (bh*NCH + cidx-1)*MDIM;
    }

    int eh = warp >> 2, nq = warp & 3;
    float c[2][8][4];
    #pragma unroll
    for (int mi = 0; mi < 2; mi++)
        #pragma unroll
        for (int nt = 0; nt < 8; nt++){ c[mi][nt][0]=0.f;c[mi][nt][1]=0.f;c[mi][nt][2]=0.f;c[mi][nt][3]=0.f; }
    float z = 0.f;

    // per-thread constant B staging indexing: m = tid
    int m_ntg = tid >> 3, m_g = tid & 7, m_x = m_ntg & 3;
    for (int p = 0; p < npass; p++){
        int r0 = rowbase + p*64;
        __syncthreads();
        const float* vg = g_vt + (size_t)r0*DDIM;
        for (int i = tid; i < 4096; i += 256){
            int r = i >> 6, e = i & 63;
            VT[e*FP + r] = vg[i];
        }
        const float* kg = g_kp + (size_t)r0*MDIM + tid;
        #pragma unroll 4
        for (int r = 0; r < 64; r++){
            float kv = kg[(size_t)r*MDIM];
            z += kv;
            int s = r >> 3, t4s = r & 3, h = (r >> 2) & 1;
            KT[(m_ntg*8 + s)*64 + ((m_g ^ s) << 3) + ((t4s ^ m_x) << 1) + h] = kv;
        }
        __syncthreads();
        #pragma unroll
        for (int s = 0; s < 8; s++){
            int k0 = s*8;
            int er0 = eh*32;
            uint32_t a00 = ldu(&VT[(er0+gid   )*FP + k0 + t4]);
            uint32_t a01 = ldu(&VT[(er0+gid+8 )*FP + k0 + t4]);
            uint32_t a02 = ldu(&VT[(er0+gid   )*FP + k0 + t4 + 4]);
            uint32_t a03 = ldu(&VT[(er0+gid+8 )*FP + k0 + t4 + 4]);
            uint32_t a10 = ldu(&VT[(er0+gid+16)*FP + k0 + t4]);
            uint32_t a11 = ldu(&VT[(er0+gid+24)*FP + k0 + t4]);
            uint32_t a12 = ldu(&VT[(er0+gid+16)*FP + k0 + t4 + 4]);
            uint32_t a13 = ldu(&VT[(er0+gid+24)*FP + k0 + t4 + 4]);
            #pragma unroll
            for (int nt = 0; nt < 8; nt++){
                int ntg = nq*8 + nt;
                float2 bv = *reinterpret_cast<float2*>(
                    &KT[(ntg*8 + s)*64 + ((gid ^ s) << 3) + ((t4 ^ (nt & 3)) << 1)]);
                uint32_t b0 = __float_as_uint(bv.x), b1 = __float_as_uint(bv.y);
                mma_tf32(c[0][nt], a00,a01,a02,a03, b0,b1);
                mma_tf32(c[1][nt], a10,a11,a12,a13, b0,b1);
            }
        }
    }
    Zout[tid] = z;
    __syncthreads();
    #pragma unroll
    for (int mi = 0; mi < 2; mi++){
        int r0 = (eh*2 + mi)*16 + gid;
        #pragma unroll
        for (int nt = 0; nt < 8; nt++){
            int col = nq*64 + nt*8 + t4*2;
            Ssm[r0*CP + col]       = c[mi][nt][0];
            Ssm[r0*CP + col+1]     = c[mi][nt][1];
            Ssm[(r0+8)*CP + col]   = c[mi][nt][2];
            Ssm[(r0+8)*CP + col+1] = c[mi][nt][3];
        }
    }
    __syncthreads();
    for (int i = tid; i < 16384; i += 256)
        Sout[i] = f2tff(Ssm[(i >> 8)*CP + (i & 255)]);
}

// ================= exclusive prefix over chunks =================
__global__ __launch_bounds__(256) void prefix_kernel(){
    int idx = blockIdx.x*256 + threadIdx.x;
    const int totS = BH*MDIM*DDIM;
    if (idx < totS){
        int bh = idx >> 14;
        int j  = idx & 16383;
        float acc = g_Scond[idx];
        float* p = g_S + (size_t)bh*NCH*MDIM*DDIM + j;
        #pragma unroll 4
        for (int c = 0; c < NCH; c++){
            float t = p[(size_t)c*MDIM*DDIM];
            p[(size_t)c*MDIM*DDIM] = f2tff(acc);
            acc += t;
        }
    } else {
        int k2 = idx - totS;
        if (k2 < BH*MDIM){
            int bh = k2 >> 8;
            int j  = k2 & 255;
            float acc = g_Zcond[k2];
            float* p = g_Z + bh*NCH*MDIM + j;
            #pragma unroll 4
            for (int c = 0; c < NCH; c++){
                float t = p[c*MDIM];
                p[c*MDIM] = acc;
                acc += t;
            }
        }
    }
}

// ================= attention output =================
// 128 threads, 4 warps; warp tile m32 (mh=warp>>1) x n32 (nh=warp&1).
__global__ __launch_bounds__(128) void attn_mma(float* __restrict__ out){
    extern __shared__ float sm[];
    float* Qs = sm;             // [64 t][FP m]
    float* Ks = sm + 64*FP;     // [64 t'][FP m] ; phase2: VT[e][s]
    float* Ss = sm + 2*64*FP;   // [64 e][FP m]  ; phase2: As[t][s]
    __shared__ float zps[64];
    __shared__ float den2p[2][64];
    __shared__ float denrow[64];
    __shared__ float invden[64];

    int tid = threadIdx.x, lane = tid & 31, warp = tid >> 5;
    int gid = lane >> 2, t4 = lane & 3;
    int bh = blockIdx.y, cc = blockIdx.x;
    bool is_cond = (cc < 4);
    int rowbase;
    const float *Sp, *zp;
    if (is_cond){
        rowbase = bh*NSEQ + cc*64;
        Sp = g_Scond + (size_t)bh*MDIM*DDIM;
        zp = g_Zcond + bh*MDIM;
    } else {
        int c = cc - 4;
        rowbase = bh*NSEQ + LCOND + c*CSZ;
        Sp = g_S + (size_t)(bh*NCH + c)*MDIM*DDIM;
        zp = g_Z + (bh*NCH + c)*MDIM;
    }
    const float* Qg = g_qp + (size_t)rowbase*MDIM;
    const float* Kg = g_kp + (size_t)rowbase*MDIM;
    const float* Vg = g_vt + (size_t)rowbase*DDIM;
    float epsv = is_cond ? 0.f : SEPS;
    uint32_t QsA = smem_u32(Qs), KsA = smem_u32(Ks), SsA = smem_u32(Ss);

    if (tid < 64) denrow[tid] = 0.f;

    int mh = warp >> 1, nh = warp & 1;
    float accO[2][4][4], accA[2][4][4];
    #pragma unroll
    for (int mi = 0; mi < 2; mi++)
        #pragma unroll
        for (int nt = 0; nt < 4; nt++){
            accO[mi][nt][0]=0.f;accO[mi][nt][1]=0.f;accO[mi][nt][2]=0.f;accO[mi][nt][3]=0.f;
            accA[mi][nt][0]=0.f;accA[mi][nt][1]=0.f;accA[mi][nt][2]=0.f;accA[mi][nt][3]=0.f;
        }
    float den2 = 0.f;

    for (int mtl = 0; mtl < 4; mtl++){
        int m0 = mtl*64;
        __syncthreads();
        for (int i = tid; i < 1024; i += 128){
            int t = i >> 4, qd = (i & 15)*4;
            cpa16(QsA + (t*FP + qd)*4, Qg + (size_t)t*MDIM + m0 + qd);
            cpa16(SsA + (t*FP + qd)*4, Sp + t*MDIM + m0 + qd);
        }
        if (!is_cond)
            for (int i = tid; i < 1024; i += 128){
                int t = i >> 4, qd = (i & 15)*4;
                cpa16(KsA + (t*FP + qd)*4, Kg + (size_t)t*MDIM + m0 + qd);
            }
        if (tid < 64) zps[tid] = zp[m0 + tid];
        CPA_COMMIT(); CPA_WAIT0();
        __syncthreads();
        // denominator: q . (zp + eps)  (f32), 2 groups of 32 m each
        {
            int row = tid & 63, grp = tid >> 6;
            float d = 0.f;
            #pragma unroll
            for (int j = 0; j < 32; j++){
                int mm = grp*32 + j;
                d = fmaf(Qs[row*FP + mm], zps[mm] + epsv, d);
            }
            den2 += d;
        }
        #pragma unroll
        for (int s = 0; s < 8; s++){
            int k0 = s*8;
            int mr = mh*32;
            uint32_t a00 = ldu(&Qs[(mr+gid   )*FP + k0 + t4]);
            uint32_t a01 = ldu(&Qs[(mr+gid+8 )*FP + k0 + t4]);
            uint32_t a02 = ldu(&Qs[(mr+gid   )*FP + k0 + t4 + 4]);
            uint32_t a03 = ldu(&Qs[(mr+gid+8 )*FP + k0 + t4 + 4]);
            uint32_t a10 = ldu(&Qs[(mr+gid+16)*FP + k0 + t4]);
            uint32_t a11 = ldu(&Qs[(mr+gid+24)*FP + k0 + t4]);
            uint32_t a12 = ldu(&Qs[(mr+gid+16)*FP + k0 + t4 + 4]);
            uint32_t a13 = ldu(&Qs[(mr+gid+24)*FP + k0 + t4 + 4]);
            #pragma unroll
            for (int nt = 0; nt < 4; nt++){
                int n0 = nh*32 + nt*8;
                uint32_t s0 = ldu(&Ss[(n0+gid)*FP + k0 + t4]);
                uint32_t s1 = ldu(&Ss[(n0+gid)*FP + k0 + t4 + 4]);
                mma_tf32(accO[0][nt], a00,a01,a02,a03, s0,s1);
                mma_tf32(accO[1][nt], a10,a11,a12,a13, s0,s1);
                if (!is_cond){
                    uint32_t b0 = ldu(&Ks[(n0+gid)*FP + k0 + t4]);
                    uint32_t b1 = ldu(&Ks[(n0+gid)*FP + k0 + t4 + 4]);
                    mma_tf32(accA[0][nt], a00,a01,a02,a03, b0,b1);
                    mma_tf32(accA[1][nt], a10,a11,a12,a13, b0,b1);
                }
            }
        }
    }
    __syncthreads();
    den2p[tid >> 6][tid & 63] = den2;

    if (!is_cond){
        // mask + stage scores into Ss (As[t][s]); rowsum f32
        #pragma unroll
        for (int mi = 0; mi < 2; mi++){
            int r0 = mh*32 + mi*16 + gid;
            float rs0 = 0.f, rs1 = 0.f;
            #pragma unroll
            for (int nt = 0; nt < 4; nt++){
                int col = nh*32 + nt*8 + t4*2;
                float v00 = (col   <= r0  ) ? accA[mi][nt][0] : 0.f;
                float v01 = (col+1 <= r0  ) ? accA[mi][nt][1] : 0.f;
                float v10 = (col   <= r0+8) ? accA[mi][nt][2] : 0.f;
                float v11 = (col+1 <= r0+8) ? accA[mi][nt][3] : 0.f;
                rs0 += v00 + v01; rs1 += v10 + v11;
                Ss[r0*FP + col]       = f2tff(v00);
                Ss[r0*FP + col+1]     = f2tff(v01);
                Ss[(r0+8)*FP + col]   = f2tff(v10);
                Ss[(r0+8)*FP + col+1] = f2tff(v11);
            }
            atomicAdd(&denrow[r0],   rs0);
            atomicAdd(&denrow[r0+8], rs1);
        }
        // stage V transposed (pre-rounded): VT[e][s]
        for (int i = tid; i < 4096; i += 128){
            int s = i >> 6, e = i & 63;
            Ks[e*FP + s] = Vg[i];
        }
        __syncthreads();
        // O += A_mask @ V
        #pragma unroll
        for (int s = 0; s < 8; s++){
            int k0 = s*8;
            int mr = mh*32;
            uint32_t a00 = ldu(&Ss[(mr+gid   )*FP + k0 + t4]);
            uint32_t a01 = ldu(&Ss[(mr+gid+8 )*FP + k0 + t4]);
            uint32_t a02 = ldu(&Ss[(mr+gid   )*FP + k0 + t4 + 4]);
            uint32_t a03 = ldu(&Ss[(mr+gid+8 )*FP + k0 + t4 + 4]);
            uint32_t a10 = ldu(&Ss[(mr+gid+16)*FP + k0 + t4]);
            uint32_t a11 = ldu(&Ss[(mr+gid+24)*FP + k0 + t4]);
            uint32_t a12 = ldu(&Ss[(mr+gid+16)*FP + k0 + t4 + 4]);
            uint32_t a13 = ldu(&Ss[(mr+gid+24)*FP + k0 + t4 + 4]);
            #pragma unroll
            for (int nt = 0; nt < 4; nt++){
                int n0 = nh*32 + nt*8;
                uint32_t b0 = ldu(&Ks[(n0+gid)*FP + k0 + t4]);
                uint32_t b1 = ldu(&Ks[(n0+gid)*FP + k0 + t4 + 4]);
                mma_tf32(accO[0][nt], a00,a01,a02,a03, b0,b1);
                mma_tf32(accO[1][nt], a10,a11,a12,a13, b0,b1);
            }
        }
    }
    __syncthreads();
    if (tid < 64){
        float d = denrow[tid] + den2p[0][tid] + den2p[1][tid];
        invden[tid] = 1.f / d;
    }
    __syncthreads();
    #pragma unroll
    for (int mi = 0; mi < 2; mi++){
        int r0 = mh*32 + mi*16 + gid;
        float i0 = invden[r0], i1 = invden[r0+8];
        #pragma unroll
        for (int nt = 0; nt < 4; nt++){
            int col = nh*32 + nt*8 + t4*2;
            float2 o0 = make_float2(accO[mi][nt][0]*i0, accO[mi][nt][1]*i0);
            float2 o1 = make_float2(accO[mi][nt][2]*i1, accO[mi][nt][3]*i1);
            *reinterpret_cast<float2*>(&out[(size_t)(rowbase+r0  )*DDIM + col]) = o0;
            *reinterpret_cast<float2*>(&out[(size_t)(rowbase+r0+8)*DDIM + col]) = o1;
        }
    }
}

// ================= launch =================
extern "C" void kernel_launch(void* const* d_in, const int* in_sizes, int n_in,
                              void* d_out, int out_size){
    const float* q    = (const float*)d_in[0];
    const float* k    = (const float*)d_in[1];
    const float* v    = (const float*)d_in[2];
    const float* proj = (const float*)d_in[3];
    float* out = (float*)d_out;

    const int FEAT_SMEM  = (4096 + 16384) * 4;        // 81920
    const int CHUNK_SMEM = (64*FP + 16384) * 4;       // 82944
    const int ATTN_SMEM  = 3*64*FP*4;                 // 52224
    cudaFuncSetAttribute(feat_mma<true>,  cudaFuncAttributeMaxDynamicSharedMemorySize, FEAT_SMEM);
    cudaFuncSetAttribute(feat_mma<false>, cudaFuncAttributeMaxDynamicSharedMemorySize, FEAT_SMEM);
    cudaFuncSetAttribute(chunk_mma,       cudaFuncAttributeMaxDynamicSharedMemorySize, CHUNK_SMEM);
    cudaFuncSetAttribute(attn_mma,        cudaFuncAttributeMaxDynamicSharedMemorySize, ATTN_SMEM);

    reset_kernel<<<1,1>>>();
    prep_kernel<<<8192,256>>>(proj, v);
    feat_mma<false><<<2048,256,FEAT_SMEM>>>(k);
    feat_mma<true ><<<2048,256,FEAT_SMEM>>>(q);
    kfin_kernel<<<32768,256>>>();
    chunk_mma<<<dim3(61,32),256,CHUNK_SMEM>>>();
    prefix_kernel<<<2112,256>>>();
    attn_mma<<<dim3(64,32),128,ATTN_SMEM>>>(out);
}

// round 9
// speedup vs baseline: 2.5956x; 1.0536x over previous
#include <cuda_runtime.h>
#include <math.h>
#include <stdint.h>

#define BH    32
#define NSEQ  4096
#define DDIM  64
#define MDIM  256
#define LCOND 256
#define CSZ   64
#define NCH   60          // (4096-256)/64
#define DN    0.35355339059327373f   // 64^-0.25
#define RATIO 0.0625f                // 256^-0.5
#define DIAGC 0.0625f                // dn^2 * 0.5
#define KEPS  1e-4f
#define SEPS  1e-6f
#define FP    68          // padded stride for 64-wide smem tiles (16B-aligned rows)
#define VTP   67          // conflict-free pad for scalar-only [e][r] tiles
#define CP    260         // padded stride for 256-wide smem tiles

// ---------------- scratch ----------------
__device__ float g_qp[BH*NSEQ*MDIM];       // tf32-rounded query features
__device__ float g_kp[BH*NSEQ*MDIM];       // key features (pre-exp f32, then tf32)
__device__ float g_S [BH*NCH*MDIM*DDIM];   // per-chunk ctx [e][m] -> tf32 prefix
__device__ float g_Z [BH*NCH*MDIM];
__device__ float g_Scond[BH*MDIM*DDIM];    // [e][m]
__device__ float g_Zcond[BH*MDIM];
__device__ float g_vt[BH*NSEQ*DDIM];       // tf32-rounded V
__device__ float4 g_P4[4096];              // DN*proj, tf32, PAIR-ORDER swizzled
__device__ unsigned g_kmax_bits;

__device__ __forceinline__ unsigned enc_f(float f){
    unsigned u = __float_as_uint(f);
    return (u & 0x80000000u) ? ~u : (u | 0x80000000u);
}
__device__ __forceinline__ float dec_f(unsigned e){
    return (e & 0x80000000u) ? __uint_as_float(e & 0x7FFFFFFFu)
                             : __uint_as_float(~e);
}
__device__ __forceinline__ float f2tff(float f){
    uint32_t r; asm("cvt.rna.tf32.f32 %0, %1;" : "=r"(r) : "f"(f));
    return __uint_as_float(r);
}
__device__ __forceinline__ void mma_tf32(float c[4],
        uint32_t a0,uint32_t a1,uint32_t a2,uint32_t a3,
        uint32_t b0,uint32_t b1){
    asm volatile("mma.sync.aligned.m16n8k8.row.col.f32.tf32.tf32.f32 "
        "{%0,%1,%2,%3}, {%4,%5,%6,%7}, {%8,%9}, {%0,%1,%2,%3};"
        : "+f"(c[0]),"+f"(c[1]),"+f"(c[2]),"+f"(c[3])
        : "r"(a0),"r"(a1),"r"(a2),"r"(a3),"r"(b0),"r"(b1));
}
__device__ __forceinline__ void mma4(float c[4], float4 av, float2 bv){
    mma_tf32(c, __float_as_uint(av.x), __float_as_uint(av.y),
                __float_as_uint(av.z), __float_as_uint(av.w),
                __float_as_uint(bv.x), __float_as_uint(bv.y));
}
__device__ __forceinline__ uint32_t ldu(const float* p){ return __float_as_uint(*p); }
__device__ __forceinline__ uint32_t smem_u32(const void* p){
    uint32_t a;
    asm("{ .reg .u64 t; cvta.to.shared.u64 t, %1; cvt.u32.u64 %0, t; }"
        : "=r"(a) : "l"(p));
    return a;
}
__device__ __forceinline__ void cpa16(uint32_t dst, const void* src){
    asm volatile("cp.async.cg.shared.global [%0], [%1], 16;" :: "r"(dst), "l"(src));
}
#define CPA_COMMIT() asm volatile("cp.async.commit_group;" ::: "memory")
#define CPA_WAIT0()  asm volatile("cp.async.wait_group 0;" ::: "memory")

__global__ void reset_kernel(){ g_kmax_bits = 0u; }

// ---------------- prep: rounded V; pair-order swizzled rounded P ----------------
__global__ __launch_bounds__(256) void prep_kernel(const float* __restrict__ proj,
                                                   const float* __restrict__ v){
    int i = blockIdx.x*256 + threadIdx.x;
    float4 x = reinterpret_cast<const float4*>(v)[i];
    x.x = f2tff(x.x); x.y = f2tff(x.y); x.z = f2tff(x.z); x.w = f2tff(x.w);
    reinterpret_cast<float4*>(g_vt)[i] = x;
    if (i < 16384){
        int pos = i;
        int ntg = pos >> 9, s = (pos >> 6) & 7, gg = (pos >> 3) & 7, slot = pos & 7;
        int g = gg ^ s;
        int t4k = ((slot >> 1) ^ ntg) & 3;
        int h = slot & 1;
        int n = ntg*8 + g, k = s*8 + h*4 + t4k;
        reinterpret_cast<float*>(g_P4)[pos] = f2tff(proj[n*64 + k] * DN);
    }
}

// ================= feature kernel =================
// Block: 128 rows, 16 warps (512 thr). D[128 x 256] = X @ (DN*P)^T.
// warp tile: m32 (mh=warp>>2) x n64 (nq=warp&3). Register epilogue.
template<bool IS_Q>
__global__ __launch_bounds__(512) void feat_mma(const float* __restrict__ data){
    extern __shared__ float sm[];
    float* sA  = sm;             // 8192 floats frag-order
    float* sB  = sm + 8192;      // 16384 floats pair-order (cp.async'd)
    __shared__ float rowsq[128];
    __shared__ unsigned rowmx[128];
    __shared__ unsigned bmax;

    int tid = threadIdx.x, lane = tid & 31, warp = tid >> 5;
    int gid = lane >> 2, t4 = lane & 3;
    int rowbase = blockIdx.x * 128;
    if (tid == 0) bmax = 0u;
    if (tid < 128){ rowsq[tid] = 0.f; rowmx[tid] = 0u; }
    __syncthreads();

    // B: straight cp.async from pre-swizzled g_P
    {
        uint32_t sBA = smem_u32(sB);
        for (int i = tid; i < 4096; i += 512)
            cpa16(sBA + i*16, g_P4 + i);
        CPA_COMMIT();
    }
    // stage X: frag order + rowsq
    const float* xg = data + (size_t)rowbase * DDIM;
    {
        int kk = tid & 63;
        int s = kk >> 3, t4s = kk & 3, jk = ((kk >> 2) & 1) << 1;
        #pragma unroll
        for (int kloop = 0; kloop < 16; kloop++){
            int r = (tid >> 6) + kloop*8;
            float x = xg[r*64 + kk];
            float sq = x * x;
            #pragma unroll
            for (int o = 16; o; o >>= 1) sq += __shfl_xor_sync(~0u, sq, o);
            if (lane == 0) atomicAdd(&rowsq[r], sq);
            int mt = r >> 4, rr = r & 15;
            int ln = ((rr & 7) << 2) | t4s;
            int j  = (rr >> 3) | jk;
            sA[(mt*8 + s)*128 + ln*4 + j] = f2tff(x);
        }
    }
    CPA_WAIT0();
    __syncthreads();

    int mh = warp >> 2, nq = warp & 3;
    float c[2][8][4];
    #pragma unroll
    for (int mi = 0; mi < 2; mi++)
        #pragma unroll
        for (int nt = 0; nt < 8; nt++){ c[mi][nt][0]=0.f;c[mi][nt][1]=0.f;c[mi][nt][2]=0.f;c[mi][nt][3]=0.f; }

    #pragma unroll
    for (int s = 0; s < 8; s++){
        float4 av0 = *reinterpret_cast<float4*>(&sA[((mh*2  )*8 + s)*128 + lane*4]);
        float4 av1 = *reinterpret_cast<float4*>(&sA[((mh*2+1)*8 + s)*128 + lane*4]);
        #pragma unroll
        for (int nt = 0; nt < 8; nt++){
            int ntg = nq*8 + nt;
            float2 bv = *reinterpret_cast<float2*>(
                &sB[(ntg*8 + s)*64 + ((gid ^ s) << 3) + ((t4 ^ (nt & 3)) << 1)]);
            mma4(c[0][nt], av0, bv);
            mma4(c[1][nt], av1, bv);
        }
    }

    // ---------- register epilogue ----------
    if (IS_Q){
        // per-row max: rows r0=mh*32+mi*16+gid (h=0), r0+8 (h=1)
        float mx[2][2];
        #pragma unroll
        for (int mi = 0; mi < 2; mi++){
            mx[mi][0] = -3.4e38f; mx[mi][1] = -3.4e38f;
            #pragma unroll
            for (int nt = 0; nt < 8; nt++){
                mx[mi][0] = fmaxf(mx[mi][0], fmaxf(c[mi][nt][0], c[mi][nt][1]));
                mx[mi][1] = fmaxf(mx[mi][1], fmaxf(c[mi][nt][2], c[mi][nt][3]));
            }
            #pragma unroll
            for (int o = 1; o < 4; o <<= 1){
                mx[mi][0] = fmaxf(mx[mi][0], __shfl_xor_sync(~0u, mx[mi][0], o));
                mx[mi][1] = fmaxf(mx[mi][1], __shfl_xor_sync(~0u, mx[mi][1], o));
            }
        }
        if (t4 == 0){
            #pragma unroll
            for (int mi = 0; mi < 2; mi++){
                atomicMax(&rowmx[mh*32 + mi*16 + gid],     enc_f(mx[mi][0]));
                atomicMax(&rowmx[mh*32 + mi*16 + gid + 8], enc_f(mx[mi][1]));
            }
        }
        __syncthreads();
        float* og = g_qp + (size_t)rowbase*MDIM;
        #pragma unroll
        for (int mi = 0; mi < 2; mi++){
            int r0 = mh*32 + mi*16 + gid;
            float sub0 = rowsq[r0]*DIAGC   + dec_f(rowmx[r0]);
            float sub1 = rowsq[r0+8]*DIAGC + dec_f(rowmx[r0+8]);
            #pragma unroll
            for (int nt = 0; nt < 8; nt++){
                int col = nq*64 + nt*8 + t4*2;
                float2 o0 = make_float2(
                    f2tff(RATIO*(__expf(c[mi][nt][0]-sub0)+KEPS)),
                    f2tff(RATIO*(__expf(c[mi][nt][1]-sub0)+KEPS)));
                float2 o1 = make_float2(
                    f2tff(RATIO*(__expf(c[mi][nt][2]-sub1)+KEPS)),
                    f2tff(RATIO*(__expf(c[mi][nt][3]-sub1)+KEPS)));
                *reinterpret_cast<float2*>(&og[(size_t)r0*MDIM + col])     = o0;
                *reinterpret_cast<float2*>(&og[(size_t)(r0+8)*MDIM + col]) = o1;
            }
        }
    } else {
        float mx = -3.4e38f;
        #pragma unroll
        for (int mi = 0; mi < 2; mi++)
            #pragma unroll
            for (int nt = 0; nt < 8; nt++){
                mx = fmaxf(mx, fmaxf(fmaxf(c[mi][nt][0], c[mi][nt][1]),
                                     fmaxf(c[mi][nt][2], c[mi][nt][3])));
            }
        #pragma unroll
        for (int o = 16; o; o >>= 1) mx = fmaxf(mx, __shfl_xor_sync(~0u, mx, o));
        if (lane == 0) atomicMax(&bmax, enc_f(mx));
        float* og = g_kp + (size_t)rowbase*MDIM;
        #pragma unroll
        for (int mi = 0; mi < 2; mi++){
            int r0 = mh*32 + mi*16 + gid;
            float d0 = rowsq[r0]*DIAGC, d1 = rowsq[r0+8]*DIAGC;
            #pragma unroll
            for (int nt = 0; nt < 8; nt++){
                int col = nq*64 + nt*8 + t4*2;
                float2 o0 = make_float2(c[mi][nt][0]-d0, c[mi][nt][1]-d0);
                float2 o1 = make_float2(c[mi][nt][2]-d1, c[mi][nt][3]-d1);
                *reinterpret_cast<float2*>(&og[(size_t)r0*MDIM + col])     = o0;
                *reinterpret_cast<float2*>(&og[(size_t)(r0+8)*MDIM + col]) = o1;
            }
        }
        __syncthreads();
        if (tid == 0) atomicMax(&g_kmax_bits, bmax);
    }
}

// ================= kp finalize: exp + tf32 round =================
__global__ __launch_bounds__(256) void kfin_kernel(){
    float kmax = dec_f(g_kmax_bits);
    size_t i = (size_t)blockIdx.x*blockDim.x + threadIdx.x;
    float4 x = reinterpret_cast<float4*>(g_kp)[i];
    x.x = f2tff(RATIO*(__expf(x.x-kmax)+KEPS));
    x.y = f2tff(RATIO*(__expf(x.y-kmax)+KEPS));
    x.z = f2tff(RATIO*(__expf(x.z-kmax)+KEPS));
    x.w = f2tff(RATIO*(__expf(x.w-kmax)+KEPS));
    reinterpret_cast<float4*>(g_kp)[i] = x;
}

// ================= chunk states =================
// S[e][m] = sum_r v[r][e]*kp[r][m] ; z[m] = sum_r kp[r][m] (f32)
__global__ __launch_bounds__(256) void chunk_mma(){
    extern __shared__ float sm[];
    float* VT  = sm;             // [64 e][VTP r] conflict-free
    float* KT  = sm + 64*VTP;    // pair-order 16384 floats
    float* Ssm = sm;             // overlay [64][CP]

    int tid = threadIdx.x, lane = tid & 31, warp = tid >> 5;
    int gid = lane >> 2, t4 = lane & 3;
    int bh = blockIdx.y, cidx = blockIdx.x;   // 0=cond, 1..60 rest
    int rowbase, npass;
    float *Sout, *Zout;
    if (cidx == 0){
        rowbase = bh*NSEQ; npass = 4;
        Sout = g_Scond + (size_t)bh*MDIM*DDIM;
        Zout = g_Zcond + bh*MDIM;
    } else {
        rowbase = bh*NSEQ + LCOND + (cidx-1)*CSZ; npass = 1;
        Sout = g_S + (size_t)(bh*NCH + cidx-1)*MDIM*DDIM;
        Zout = g_Z + (bh*NCH + cidx-1)*MDIM;
    }

    int eh = warp >> 2, nq = warp & 3;
    float c[2][8][4];
    #pragma unroll
    for (int mi = 0; mi < 2; mi++)
        #pragma unroll
        for (int nt = 0; nt < 8; nt++){ c[mi][nt][0]=0.f;c[mi][nt][1]=0.f;c[mi][nt][2]=0.f;c[mi][nt][3]=0.f; }
    float z = 0.f;

    int m_ntg = tid >> 3, m_g = tid & 7, m_x = m_ntg & 3;
    for (int p = 0; p < npass; p++){
        int r0 = rowbase + p*64;
        __syncthreads();
        const float* vg = g_vt + (size_t)r0*DDIM;
        for (int i = tid; i < 4096; i += 256){
            int r = i >> 6, e = i & 63;
            VT[e*VTP + r] = vg[i];
        }
        const float* kg = g_kp + (size_t)r0*MDIM + tid;
        #pragma unroll 4
        for (int r = 0; r < 64; r++){
            float kv = kg[(size_t)r*MDIM];
            z += kv;
            int s = r >> 3, t4s = r & 3, h = (r >> 2) & 1;
            KT[(m_ntg*8 + s)*64 + ((m_g ^ s) << 3) + ((t4s ^ m_x) << 1) + h] = kv;
        }
        __syncthreads();
        #pragma unroll
        for (int s = 0; s < 8; s++){
            int k0 = s*8;
            int er0 = eh*32;
            uint32_t a00 = ldu(&VT[(er0+gid   )*VTP + k0 + t4]);
            uint32_t a01 = ldu(&VT[(er0+gid+8 )*VTP + k0 + t4]);
            uint32_t a02 = ldu(&VT[(er0+gid   )*VTP + k0 + t4 + 4]);
            uint32_t a03 = ldu(&VT[(er0+gid+8 )*VTP + k0 + t4 + 4]);
            uint32_t a10 = ldu(&VT[(er0+gid+16)*VTP + k0 + t4]);
            uint32_t a11 = ldu(&VT[(er0+gid+24)*VTP + k0 + t4]);
            uint32_t a12 = ldu(&VT[(er0+gid+16)*VTP + k0 + t4 + 4]);
            uint32_t a13 = ldu(&VT[(er0+gid+24)*VTP + k0 + t4 + 4]);
            #pragma unroll
            for (int nt = 0; nt < 8; nt++){
                int ntg = nq*8 + nt;
                float2 bv = *reinterpret_cast<float2*>(
                    &KT[(ntg*8 + s)*64 + ((gid ^ s) << 3) + ((t4 ^ (nt & 3)) << 1)]);
                uint32_t b0 = __float_as_uint(bv.x), b1 = __float_as_uint(bv.y);
                mma_tf32(c[0][nt], a00,a01,a02,a03, b0,b1);
                mma_tf32(c[1][nt], a10,a11,a12,a13, b0,b1);
            }
        }
    }
    Zout[tid] = z;
    __syncthreads();
    #pragma unroll
    for (int mi = 0; mi < 2; mi++){
        int r0 = (eh*2 + mi)*16 + gid;
        #pragma unroll
        for (int nt = 0; nt < 8; nt++){
            int col = nq*64 + nt*8 + t4*2;
            Ssm[r0*CP + col]       = c[mi][nt][0];
            Ssm[r0*CP + col+1]     = c[mi][nt][1];
            Ssm[(r0+8)*CP + col]   = c[mi][nt][2];
            Ssm[(r0+8)*CP + col+1] = c[mi][nt][3];
        }
    }
    __syncthreads();
    for (int i = tid; i < 16384; i += 256)
        Sout[i] = f2tff(Ssm[(i >> 8)*CP + (i & 255)]);
}

// ================= exclusive prefix over chunks =================
__global__ __launch_bounds__(256) void prefix_kernel(){
    int idx = blockIdx.x*256 + threadIdx.x;
    const int totS = BH*MDIM*DDIM;
    if (idx < totS){
        int bh = idx >> 14;
        int j  = idx & 16383;
        float acc = g_Scond[idx];
        float* p = g_S + (size_t)bh*NCH*MDIM*DDIM + j;
        #pragma unroll 4
        for (int c = 0; c < NCH; c++){
            float t = p[(size_t)c*MDIM*DDIM];
            p[(size_t)c*MDIM*DDIM] = f2tff(acc);
            acc += t;
        }
    } else {
        int k2 = idx - totS;
        if (k2 < BH*MDIM){
            int bh = k2 >> 8;
            int j  = k2 & 255;
            float acc = g_Zcond[k2];
            float* p = g_Z + bh*NCH*MDIM + j;
            #pragma unroll 4
            for (int c = 0; c < NCH; c++){
                float t = p[c*MDIM];
                p[c*MDIM] = acc;
                acc += t;
            }
        }
    }
}

// ================= attention output =================
// 128 threads, 4 warps; warp tile m32 (mh=warp>>1) x n32 (nh=warp&1).
__global__ __launch_bounds__(128) void attn_mma(float* __restrict__ out){
    extern __shared__ float sm[];
    float* Qs = sm;             // [64 t][FP m]
    float* Ks = sm + 64*FP;     // [64 t'][FP m] ; phase2: VT[e][s] stride VTP
    float* Ss = sm + 2*64*FP;   // [64 e][FP m]  ; phase2: As[t][s]
    __shared__ float zps[64];
    __shared__ float den2p[2][64];
    __shared__ float denrow[64];
    __shared__ float invden[64];

    int tid = threadIdx.x, lane = tid & 31, warp = tid >> 5;
    int gid = lane >> 2, t4 = lane & 3;
    int bh = blockIdx.y, cc = blockIdx.x;
    bool is_cond = (cc < 4);
    int rowbase;
    const float *Sp, *zp;
    if (is_cond){
        rowbase = bh*NSEQ + cc*64;
        Sp = g_Scond + (size_t)bh*MDIM*DDIM;
        zp = g_Zcond + bh*MDIM;
    } else {
        int c = cc - 4;
        rowbase = bh*NSEQ + LCOND + c*CSZ;
        Sp = g_S + (size_t)(bh*NCH + c)*MDIM*DDIM;
        zp = g_Z + (bh*NCH + c)*MDIM;
    }
    const float* Qg = g_qp + (size_t)rowbase*MDIM;
    const float* Kg = g_kp + (size_t)rowbase*MDIM;
    const float* Vg = g_vt + (size_t)rowbase*DDIM;
    float epsv = is_cond ? 0.f : SEPS;
    uint32_t QsA = smem_u32(Qs), KsA = smem_u32(Ks), SsA = smem_u32(Ss);

    if (tid < 64) denrow[tid] = 0.f;

    int mh = warp >> 1, nh = warp & 1;
    float accO[2][4][4], accA[2][4][4];
    #pragma unroll
    for (int mi = 0; mi < 2; mi++)
        #pragma unroll
        for (int nt = 0; nt < 4; nt++){
            accO[mi][nt][0]=0.f;accO[mi][nt][1]=0.f;accO[mi][nt][2]=0.f;accO[mi][nt][3]=0.f;
            accA[mi][nt][0]=0.f;accA[mi][nt][1]=0.f;accA[mi][nt][2]=0.f;accA[mi][nt][3]=0.f;
        }
    float den2 = 0.f;

    for (int mtl = 0; mtl < 4; mtl++){
        int m0 = mtl*64;
        __syncthreads();
        for (int i = tid; i < 1024; i += 128){
            int t = i >> 4, qd = (i & 15)*4;
            cpa16(QsA + (t*FP + qd)*4, Qg + (size_t)t*MDIM + m0 + qd);
            cpa16(SsA + (t*FP + qd)*4, Sp + t*MDIM + m0 + qd);
        }
        if (!is_cond)
            for (int i = tid; i < 1024; i += 128){
                int t = i >> 4, qd = (i & 15)*4;
                cpa16(KsA + (t*FP + qd)*4, Kg + (size_t)t*MDIM + m0 + qd);
            }
        if (tid < 64) zps[tid] = zp[m0 + tid];
        CPA_COMMIT(); CPA_WAIT0();
        __syncthreads();
        {
            int row = tid & 63, grp = tid >> 6;
            float d = 0.f;
            #pragma unroll
            for (int j = 0; j < 32; j++){
                int mm = grp*32 + j;
                d = fmaf(Qs[row*FP + mm], zps[mm] + epsv, d);
            }
            den2 += d;
        }
        #pragma unroll
        for (int s = 0; s < 8; s++){
            int k0 = s*8;
            int mr = mh*32;
            uint32_t a00 = ldu(&Qs[(mr+gid   )*FP + k0 + t4]);
            uint32_t a01 = ldu(&Qs[(mr+gid+8 )*FP + k0 + t4]);
            uint32_t a02 = ldu(&Qs[(mr+gid   )*FP + k0 + t4 + 4]);
            uint32_t a03 = ldu(&Qs[(mr+gid+8 )*FP + k0 + t4 + 4]);
            uint32_t a10 = ldu(&Qs[(mr+gid+16)*FP + k0 + t4]);
            uint32_t a11 = ldu(&Qs[(mr+gid+24)*FP + k0 + t4]);
            uint32_t a12 = ldu(&Qs[(mr+gid+16)*FP + k0 + t4 + 4]);
            uint32_t a13 = ldu(&Qs[(mr+gid+24)*FP + k0 + t4 + 4]);
            #pragma unroll
            for (int nt = 0; nt < 4; nt++){
                int n0 = nh*32 + nt*8;
                uint32_t s0 = ldu(&Ss[(n0+gid)*FP + k0 + t4]);
                uint32_t s1 = ldu(&Ss[(n0+gid)*FP + k0 + t4 + 4]);
                mma_tf32(accO[0][nt], a00,a01,a02,a03, s0,s1);
                mma_tf32(accO[1][nt], a10,a11,a12,a13, s0,s1);
                if (!is_cond){
                    uint32_t b0 = ldu(&Ks[(n0+gid)*FP + k0 + t4]);
                    uint32_t b1 = ldu(&Ks[(n0+gid)*FP + k0 + t4 + 4]);
                    mma_tf32(accA[0][nt], a00,a01,a02,a03, b0,b1);
                    mma_tf32(accA[1][nt], a10,a11,a12,a13, b0,b1);
                }
            }
        }
    }
    __syncthreads();
    den2p[tid >> 6][tid & 63] = den2;

    if (!is_cond){
        #pragma unroll
        for (int mi = 0; mi < 2; mi++){
            int r0 = mh*32 + mi*16 + gid;
            float rs0 = 0.f, rs1 = 0.f;
            #pragma unroll
            for (int nt = 0; nt < 4; nt++){
                int col = nh*32 + nt*8 + t4*2;
                float v00 = (col   <= r0  ) ? accA[mi][nt][0] : 0.f;
                float v01 = (col+1 <= r0  ) ? accA[mi][nt][1] : 0.f;
                float v10 = (col   <= r0+8) ? accA[mi][nt][2] : 0.f;
                float v11 = (col+1 <= r0+8) ? accA[mi][nt][3] : 0.f;
                rs0 += v00 + v01; rs1 += v10 + v11;
                Ss[r0*FP + col]       = f2tff(v00);
                Ss[r0*FP + col+1]     = f2tff(v01);
                Ss[(r0+8)*FP + col]   = f2tff(v10);
                Ss[(r0+8)*FP + col+1] = f2tff(v11);
            }
            atomicAdd(&denrow[r0],   rs0);
            atomicAdd(&denrow[r0+8], rs1);
        }
        for (int i = tid; i < 4096; i += 128){
            int s = i >> 6, e = i & 63;
            Ks[e*VTP + s] = Vg[i];
        }
        __syncthreads();
        #pragma unroll
        for (int s = 0; s < 8; s++){
            int k0 = s*8;
            int mr = mh*32;
            uint32_t a00 = ldu(&Ss[(mr+gid   )*FP + k0 + t4]);
            uint32_t a01 = ldu(&Ss[(mr+gid+8 )*FP + k0 + t4]);
            uint32_t a02 = ldu(&Ss[(mr+gid   )*FP + k0 + t4 + 4]);
            uint32_t a03 = ldu(&Ss[(mr+gid+8 )*FP + k0 + t4 + 4]);
            uint32_t a10 = ldu(&Ss[(mr+gid+16)*FP + k0 + t4]);
            uint32_t a11 = ldu(&Ss[(mr+gid+24)*FP + k0 + t4]);
            uint32_t a12 = ldu(&Ss[(mr+gid+16)*FP + k0 + t4 + 4]);
            uint32_t a13 = ldu(&Ss[(mr+gid+24)*FP + k0 + t4 + 4]);
            #pragma unroll
            for (int nt = 0; nt < 4; nt++){
                int n0 = nh*32 + nt*8;
                uint32_t b0 = ldu(&Ks[(n0+gid)*VTP + k0 + t4]);
                uint32_t b1 = ldu(&Ks[(n0+gid)*VTP + k0 + t4 + 4]);
                mma_tf32(accO[0][nt], a00,a01,a02,a03, b0,b1);
                mma_tf32(accO[1][nt], a10,a11,a12,a13, b0,b1);
            }
        }
    }
    __syncthreads();
    if (tid < 64){
        float d = denrow[tid] + den2p[0][tid] + den2p[1][tid];
        invden[tid] = 1.f / d;
    }
    __syncthreads();
    #pragma unroll
    for (int mi = 0; mi < 2; mi++){
        int r0 = mh*32 + mi*16 + gid;
        float i0 = invden[r0], i1 = invden[r0+8];
        #pragma unroll
        for (int nt = 0; nt < 4; nt++){
            int col = nh*32 + nt*8 + t4*2;
            float2 o0 = make_float2(accO[mi][nt][0]*i0, accO[mi][nt][1]*i0);
            float2 o1 = make_float2(accO[mi][nt][2]*i1, accO[mi][nt][3]*i1);
            *reinterpret_cast<float2*>(&out[(size_t)(rowbase+r0  )*DDIM + col]) = o0;
            *reinterpret_cast<float2*>(&out[(size_t)(rowbase+r0+8)*DDIM + col]) = o1;
        }
    }
}

// ================= launch =================
extern "C" void kernel_launch(void* const* d_in, const int* in_sizes, int n_in,
                              void* d_out, int out_size){
    const float* q    = (const float*)d_in[0];
    const float* k    = (const float*)d_in[1];
    const float* v    = (const float*)d_in[2];
    const float* proj = (const float*)d_in[3];
    float* out = (float*)d_out;

    const int FEAT_SMEM  = (8192 + 16384) * 4;        // 98304
    const int CHUNK_SMEM = (64*VTP + 16384) * 4;      // 82688
    const int ATTN_SMEM  = 3*64*FP*4;                 // 52224
    cudaFuncSetAttribute(feat_mma<true>,  cudaFuncAttributeMaxDynamicSharedMemorySize, FEAT_SMEM);
    cudaFuncSetAttribute(feat_mma<false>, cudaFuncAttributeMaxDynamicSharedMemorySize, FEAT_SMEM);
    cudaFuncSetAttribute(chunk_mma,       cudaFuncAttributeMaxDynamicSharedMemorySize, CHUNK_SMEM);
    cudaFuncSetAttribute(attn_mma,        cudaFuncAttributeMaxDynamicSharedMemorySize, ATTN_SMEM);

    reset_kernel<<<1,1>>>();
    prep_kernel<<<8192,256>>>(proj, v);
    feat_mma<false><<<1024,512,FEAT_SMEM>>>(k);
    feat_mma<true ><<<1024,512,FEAT_SMEM>>>(q);
    kfin_kernel<<<32768,256>>>();
    chunk_mma<<<dim3(61,32),256,CHUNK_SMEM>>>();
    prefix_kernel<<<2112,256>>>();
    attn_mma<<<dim3(64,32),128,ATTN_SMEM>>>(out);
}

// round 10
// speedup vs baseline: 2.6252x; 1.0114x over previous
#include <cuda_runtime.h>
#include <math.h>
#include <stdint.h>

#define BH    32
#define NSEQ  4096
#define DDIM  64
#define MDIM  256
#define LCOND 256
#define CSZ   64
#define NCH   60          // (4096-256)/64
#define DN    0.35355339059327373f   // 64^-0.25
#define RATIO 0.0625f                // 256^-0.5
#define DIAGC 0.0625f                // dn^2 * 0.5
#define KEPS  1e-4f
#define SEPS  1e-6f
#define FP    68          // padded stride for 64-wide smem tiles (16B-aligned rows)
#define VTP   67          // conflict-free pad for scalar-only [e][r] tiles

// ---------------- scratch ----------------
__device__ float g_qp[BH*NSEQ*MDIM];       // tf32-rounded query features
__device__ float g_kp[BH*NSEQ*MDIM];       // key features (pre-exp f32, then tf32)
__device__ float g_S [BH*NCH*MDIM*DDIM];   // per-chunk ctx [e][m] -> tf32 prefix
__device__ float g_Z [BH*NCH*MDIM];
__device__ float g_Scond[BH*MDIM*DDIM];    // [e][m]
__device__ float g_Zcond[BH*MDIM];
__device__ float4 g_P4[4096];              // DN*proj, tf32, PAIR-ORDER swizzled
__device__ unsigned g_kmax_bits;

__device__ __forceinline__ unsigned enc_f(float f){
    unsigned u = __float_as_uint(f);
    return (u & 0x80000000u) ? ~u : (u | 0x80000000u);
}
__device__ __forceinline__ float dec_f(unsigned e){
    return (e & 0x80000000u) ? __uint_as_float(e & 0x7FFFFFFFu)
                             : __uint_as_float(~e);
}
__device__ __forceinline__ float f2tff(float f){
    uint32_t r; asm("cvt.rna.tf32.f32 %0, %1;" : "=r"(r) : "f"(f));
    return __uint_as_float(r);
}
__device__ __forceinline__ void mma_tf32(float c[4],
        uint32_t a0,uint32_t a1,uint32_t a2,uint32_t a3,
        uint32_t b0,uint32_t b1){
    asm volatile("mma.sync.aligned.m16n8k8.row.col.f32.tf32.tf32.f32 "
        "{%0,%1,%2,%3}, {%4,%5,%6,%7}, {%8,%9}, {%0,%1,%2,%3};"
        : "+f"(c[0]),"+f"(c[1]),"+f"(c[2]),"+f"(c[3])
        : "r"(a0),"r"(a1),"r"(a2),"r"(a3),"r"(b0),"r"(b1));
}
__device__ __forceinline__ void mma4(float c[4], float4 av, float2 bv){
    mma_tf32(c, __float_as_uint(av.x), __float_as_uint(av.y),
                __float_as_uint(av.z), __float_as_uint(av.w),
                __float_as_uint(bv.x), __float_as_uint(bv.y));
}
__device__ __forceinline__ uint32_t ldu(const float* p){ return __float_as_uint(*p); }
__device__ __forceinline__ uint32_t smem_u32(const void* p){
    uint32_t a;
    asm("{ .reg .u64 t; cvta.to.shared.u64 t, %1; cvt.u32.u64 %0, t; }"
        : "=r"(a) : "l"(p));
    return a;
}
__device__ __forceinline__ void cpa16(uint32_t dst, const void* src){
    asm volatile("cp.async.cg.shared.global [%0], [%1], 16;" :: "r"(dst), "l"(src));
}
#define CPA_COMMIT() asm volatile("cp.async.commit_group;" ::: "memory")
#define CPA_WAIT0()  asm volatile("cp.async.wait_group 0;" ::: "memory")

// ---------------- prep: pair-order swizzled rounded P + reset ----------------
__global__ __launch_bounds__(256) void prep_kernel(const float* __restrict__ proj){
    int i = blockIdx.x*256 + threadIdx.x;
    if (i == 0) g_kmax_bits = 0u;
    int pos = i;
    int ntg = pos >> 9, s = (pos >> 6) & 7, gg = (pos >> 3) & 7, slot = pos & 7;
    int g = gg ^ s;
    int t4k = ((slot >> 1) ^ ntg) & 3;
    int h = slot & 1;
    int n = ntg*8 + g, k = s*8 + h*4 + t4k;
    reinterpret_cast<float*>(g_P4)[pos] = f2tff(proj[n*64 + k] * DN);
}

// ================= feature kernel =================
// Block: 128 rows, 16 warps (512 thr). D[128 x 256] = X @ (DN*P)^T.
template<bool IS_Q>
__global__ __launch_bounds__(512) void feat_mma(const float* __restrict__ data){
    extern __shared__ float sm[];
    float* sA  = sm;             // 8192 floats frag-order
    float* sB  = sm + 8192;      // 16384 floats pair-order (cp.async'd)
    __shared__ float rowsq[128];
    __shared__ unsigned rowmx[128];
    __shared__ unsigned bmax;

    int tid = threadIdx.x, lane = tid & 31, warp = tid >> 5;
    int gid = lane >> 2, t4 = lane & 3;
    int rowbase = blockIdx.x * 128;
    if (tid == 0) bmax = 0u;
    if (tid < 128){ rowsq[tid] = 0.f; rowmx[tid] = 0u; }
    __syncthreads();

    {
        uint32_t sBA = smem_u32(sB);
        for (int i = tid; i < 4096; i += 512)
            cpa16(sBA + i*16, g_P4 + i);
        CPA_COMMIT();
    }
    const float* xg = data + (size_t)rowbase * DDIM;
    {
        int kk = tid & 63;
        int s = kk >> 3, t4s = kk & 3, jk = ((kk >> 2) & 1) << 1;
        #pragma unroll
        for (int kloop = 0; kloop < 16; kloop++){
            int r = (tid >> 6) + kloop*8;
            float x = xg[r*64 + kk];
            float sq = x * x;
            #pragma unroll
            for (int o = 16; o; o >>= 1) sq += __shfl_xor_sync(~0u, sq, o);
            if (lane == 0) atomicAdd(&rowsq[r], sq);
            int mt = r >> 4, rr = r & 15;
            int ln = ((rr & 7) << 2) | t4s;
            int j  = (rr >> 3) | jk;
            sA[(mt*8 + s)*128 + ln*4 + j] = f2tff(x);
        }
    }
    CPA_WAIT0();
    __syncthreads();

    int mh = warp >> 2, nq = warp & 3;
    float c[2][8][4];
    #pragma unroll
    for (int mi = 0; mi < 2; mi++)
        #pragma unroll
        for (int nt = 0; nt < 8; nt++){ c[mi][nt][0]=0.f;c[mi][nt][1]=0.f;c[mi][nt][2]=0.f;c[mi][nt][3]=0.f; }

    #pragma unroll
    for (int s = 0; s < 8; s++){
        float4 av0 = *reinterpret_cast<float4*>(&sA[((mh*2  )*8 + s)*128 + lane*4]);
        float4 av1 = *reinterpret_cast<float4*>(&sA[((mh*2+1)*8 + s)*128 + lane*4]);
        #pragma unroll
        for (int nt = 0; nt < 8; nt++){
            int ntg = nq*8 + nt;
            float2 bv = *reinterpret_cast<float2*>(
                &sB[(ntg*8 + s)*64 + ((gid ^ s) << 3) + ((t4 ^ (nt & 3)) << 1)]);
            mma4(c[0][nt], av0, bv);
            mma4(c[1][nt], av1, bv);
        }
    }

    if (IS_Q){
        float mx[2][2];
        #pragma unroll
        for (int mi = 0; mi < 2; mi++){
            mx[mi][0] = -3.4e38f; mx[mi][1] = -3.4e38f;
            #pragma unroll
            for (int nt = 0; nt < 8; nt++){
                mx[mi][0] = fmaxf(mx[mi][0], fmaxf(c[mi][nt][0], c[mi][nt][1]));
                mx[mi][1] = fmaxf(mx[mi][1], fmaxf(c[mi][nt][2], c[mi][nt][3]));
            }
            #pragma unroll
            for (int o = 1; o < 4; o <<= 1){
                mx[mi][0] = fmaxf(mx[mi][0], __shfl_xor_sync(~0u, mx[mi][0], o));
                mx[mi][1] = fmaxf(mx[mi][1], __shfl_xor_sync(~0u, mx[mi][1], o));
            }
        }
        if (t4 == 0){
            #pragma unroll
            for (int mi = 0; mi < 2; mi++){
                atomicMax(&rowmx[mh*32 + mi*16 + gid],     enc_f(mx[mi][0]));
                atomicMax(&rowmx[mh*32 + mi*16 + gid + 8], enc_f(mx[mi][1]));
            }
        }
        __syncthreads();
        float* og = g_qp + (size_t)rowbase*MDIM;
        #pragma unroll
        for (int mi = 0; mi < 2; mi++){
            int r0 = mh*32 + mi*16 + gid;
            float sub0 = rowsq[r0]*DIAGC   + dec_f(rowmx[r0]);
            float sub1 = rowsq[r0+8]*DIAGC + dec_f(rowmx[r0+8]);
            #pragma unroll
            for (int nt = 0; nt < 8; nt++){
                int col = nq*64 + nt*8 + t4*2;
                float2 o0 = make_float2(
                    f2tff(RATIO*(__expf(c[mi][nt][0]-sub0)+KEPS)),
                    f2tff(RATIO*(__expf(c[mi][nt][1]-sub0)+KEPS)));
                float2 o1 = make_float2(
                    f2tff(RATIO*(__expf(c[mi][nt][2]-sub1)+KEPS)),
                    f2tff(RATIO*(__expf(c[mi][nt][3]-sub1)+KEPS)));
                *reinterpret_cast<float2*>(&og[(size_t)r0*MDIM + col])     = o0;
                *reinterpret_cast<float2*>(&og[(size_t)(r0+8)*MDIM + col]) = o1;
            }
        }
    } else {
        float mx = -3.4e38f;
        #pragma unroll
        for (int mi = 0; mi < 2; mi++)
            #pragma unroll
            for (int nt = 0; nt < 8; nt++){
                mx = fmaxf(mx, fmaxf(fmaxf(c[mi][nt][0], c[mi][nt][1]),
                                     fmaxf(c[mi][nt][2], c[mi][nt][3])));
            }
        #pragma unroll
        for (int o = 16; o; o >>= 1) mx = fmaxf(mx, __shfl_xor_sync(~0u, mx, o));
        if (lane == 0) atomicMax(&bmax, enc_f(mx));
        float* og = g_kp + (size_t)rowbase*MDIM;
        #pragma unroll
        for (int mi = 0; mi < 2; mi++){
            int r0 = mh*32 + mi*16 + gid;
            float d0 = rowsq[r0]*DIAGC, d1 = rowsq[r0+8]*DIAGC;
            #pragma unroll
            for (int nt = 0; nt < 8; nt++){
                int col = nq*64 + nt*8 + t4*2;
                float2 o0 = make_float2(c[mi][nt][0]-d0, c[mi][nt][1]-d0);
                float2 o1 = make_float2(c[mi][nt][2]-d1, c[mi][nt][3]-d1);
                *reinterpret_cast<float2*>(&og[(size_t)r0*MDIM + col])     = o0;
                *reinterpret_cast<float2*>(&og[(size_t)(r0+8)*MDIM + col]) = o1;
            }
        }
        __syncthreads();
        if (tid == 0) atomicMax(&g_kmax_bits, bmax);
    }
}

// ================= kp finalize: exp + tf32 round =================
__global__ __launch_bounds__(256) void kfin_kernel(){
    float kmax = dec_f(g_kmax_bits);
    size_t i = (size_t)blockIdx.x*blockDim.x + threadIdx.x;
    float4 x = reinterpret_cast<float4*>(g_kp)[i];
    x.x = f2tff(RATIO*(__expf(x.x-kmax)+KEPS));
    x.y = f2tff(RATIO*(__expf(x.y-kmax)+KEPS));
    x.z = f2tff(RATIO*(__expf(x.z-kmax)+KEPS));
    x.w = f2tff(RATIO*(__expf(x.w-kmax)+KEPS));
    reinterpret_cast<float4*>(g_kp)[i] = x;
}

// ================= chunk states (m-split) =================
// Block handles m-half (128 cols): S[e][mbase+..] , z[mbase+..]
// 8 warps: e32 (eh=warp>>2) x m32 (nq=warp&3). Register epilogue.
__global__ __launch_bounds__(256,3) void chunk_mma(const float* __restrict__ v){
    extern __shared__ float sm[];
    float* VT  = sm;             // [64 e][VTP r]
    float* KT  = sm + 64*VTP;    // pair-order 8192 floats (128 m)
    __shared__ float zbuf[256];

    int tid = threadIdx.x, lane = tid & 31, warp = tid >> 5;
    int gid = lane >> 2, t4 = lane & 3;
    int bh = blockIdx.y, cidx = blockIdx.x;   // 0=cond, 1..60 rest
    int mbase = blockIdx.z * 128;
    int rowbase, npass;
    float *Sout, *Zout;
    if (cidx == 0){
        rowbase = bh*NSEQ; npass = 4;
        Sout = g_Scond + (size_t)bh*MDIM*DDIM;
        Zout = g_Zcond + bh*MDIM;
    } else {
        rowbase = bh*NSEQ + LCOND + (cidx-1)*CSZ; npass = 1;
        Sout = g_S + (size_t)(bh*NCH + cidx-1)*MDIM*DDIM;
        Zout = g_Z + (bh*NCH + cidx-1)*MDIM;
    }

    int eh = warp >> 2, nq = warp & 3;
    float c[2][4][4];
    #pragma unroll
    for (int mi = 0; mi < 2; mi++)
        #pragma unroll
        for (int nt = 0; nt < 4; nt++){ c[mi][nt][0]=0.f;c[mi][nt][1]=0.f;c[mi][nt][2]=0.f;c[mi][nt][3]=0.f; }
    float z = 0.f;

    int m_local = tid & 127, rbase = (tid >> 7) * 32;
    int m_ntg = m_local >> 3, m_g = m_local & 7, m_x = m_ntg & 3;
    for (int p = 0; p < npass; p++){
        int r0 = rowbase + p*64;
        __syncthreads();
        const float* vg = v + (size_t)r0*DDIM;
        for (int i = tid; i < 4096; i += 256){
            int r = i >> 6, e = i & 63;
            VT[e*VTP + r] = f2tff(vg[i]);
        }
        const float* kg = g_kp + (size_t)(r0 + rbase)*MDIM + mbase + m_local;
        #pragma unroll 4
        for (int rr = 0; rr < 32; rr++){
            float kv = kg[(size_t)rr*MDIM];
            z += kv;
            int r = rbase + rr;
            int s = r >> 3, t4s = r & 3, h = (r >> 2) & 1;
            KT[(m_ntg*8 + s)*64 + ((m_g ^ s) << 3) + ((t4s ^ m_x) << 1) + h] = kv;
        }
        __syncthreads();
        #pragma unroll
        for (int s = 0; s < 8; s++){
            int k0 = s*8;
            int er0 = eh*32;
            uint32_t a00 = ldu(&VT[(er0+gid   )*VTP + k0 + t4]);
            uint32_t a01 = ldu(&VT[(er0+gid+8 )*VTP + k0 + t4]);
            uint32_t a02 = ldu(&VT[(er0+gid   )*VTP + k0 + t4 + 4]);
            uint32_t a03 = ldu(&VT[(er0+gid+8 )*VTP + k0 + t4 + 4]);
            uint32_t a10 = ldu(&VT[(er0+gid+16)*VTP + k0 + t4]);
            uint32_t a11 = ldu(&VT[(er0+gid+24)*VTP + k0 + t4]);
            uint32_t a12 = ldu(&VT[(er0+gid+16)*VTP + k0 + t4 + 4]);
            uint32_t a13 = ldu(&VT[(er0+gid+24)*VTP + k0 + t4 + 4]);
            #pragma unroll
            for (int nt = 0; nt < 4; nt++){
                int ntg = nq*4 + nt;
                float2 bv = *reinterpret_cast<float2*>(
                    &KT[(ntg*8 + s)*64 + ((gid ^ s) << 3) + ((t4 ^ (ntg & 3)) << 1)]);
                uint32_t b0 = __float_as_uint(bv.x), b1 = __float_as_uint(bv.y);
                mma_tf32(c[0][nt], a00,a01,a02,a03, b0,b1);
                mma_tf32(c[1][nt], a10,a11,a12,a13, b0,b1);
            }
        }
    }
    zbuf[tid] = z;
    // register epilogue: S rows e, cols mbase+col
    #pragma unroll
    for (int mi = 0; mi < 2; mi++){
        int r0 = eh*32 + mi*16 + gid;
        #pragma unroll
        for (int nt = 0; nt < 4; nt++){
            int col = mbase + nq*32 + nt*8 + t4*2;
            float2 o0 = make_float2(f2tff(c[mi][nt][0]), f2tff(c[mi][nt][1]));
            float2 o1 = make_float2(f2tff(c[mi][nt][2]), f2tff(c[mi][nt][3]));
            *reinterpret_cast<float2*>(&Sout[(size_t)r0*MDIM + col])     = o0;
            *reinterpret_cast<float2*>(&Sout[(size_t)(r0+8)*MDIM + col]) = o1;
        }
    }
    __syncthreads();
    if (tid < 128) Zout[mbase + tid] = zbuf[tid] + zbuf[tid + 128];
}

// ================= exclusive prefix over chunks =================
__global__ __launch_bounds__(256) void prefix_kernel(){
    int idx = blockIdx.x*256 + threadIdx.x;
    const int totS = BH*MDIM*DDIM;
    if (idx < totS){
        int bh = idx >> 14;
        int j  = idx & 16383;
        float acc = g_Scond[idx];
        float* p = g_S + (size_t)bh*NCH*MDIM*DDIM + j;
        #pragma unroll 4
        for (int c = 0; c < NCH; c++){
            float t = p[(size_t)c*MDIM*DDIM];
            p[(size_t)c*MDIM*DDIM] = f2tff(acc);
            acc += t;
        }
    } else {
        int k2 = idx - totS;
        if (k2 < BH*MDIM){
            int bh = k2 >> 8;
            int j  = k2 & 255;
            float acc = g_Zcond[k2];
            float* p = g_Z + bh*NCH*MDIM + j;
            #pragma unroll 4
            for (int c = 0; c < NCH; c++){
                float t = p[c*MDIM];
                p[c*MDIM] = acc;
                acc += t;
            }
        }
    }
}

// ================= attention output =================
// 256 threads, 8 warps; warp tile m32 (mh=warp>>2) x n16 (nq=warp&3).
__global__ __launch_bounds__(256,3) void attn_mma(const float* __restrict__ v,
                                                  float* __restrict__ out){
    extern __shared__ float sm[];
    float* Qs = sm;             // [64 t][FP m]
    float* Ks = sm + 64*FP;     // [64 t'][FP m] ; phase2: VT[e][s] stride VTP
    float* Ss = sm + 2*64*FP;   // [64 e][FP m]  ; phase2: As[t][s]
    __shared__ float zps[64];
    __shared__ float den2p[4][64];
    __shared__ float denrow[64];
    __shared__ float invden[64];

    int tid = threadIdx.x, lane = tid & 31, warp = tid >> 5;
    int gid = lane >> 2, t4 = lane & 3;
    int bh = blockIdx.y, cc = blockIdx.x;
    bool is_cond = (cc < 4);
    int rowbase;
    const float *Sp, *zp;
    if (is_cond){
        rowbase = bh*NSEQ + cc*64;
        Sp = g_Scond + (size_t)bh*MDIM*DDIM;
        zp = g_Zcond + bh*MDIM;
    } else {
        int c = cc - 4;
        rowbase = bh*NSEQ + LCOND + c*CSZ;
        Sp = g_S + (size_t)(bh*NCH + c)*MDIM*DDIM;
        zp = g_Z + (bh*NCH + c)*MDIM;
    }
    const float* Qg = g_qp + (size_t)rowbase*MDIM;
    const float* Kg = g_kp + (size_t)rowbase*MDIM;
    const float* Vg = v + (size_t)rowbase*DDIM;
    float epsv = is_cond ? 0.f : SEPS;
    uint32_t QsA = smem_u32(Qs), KsA = smem_u32(Ks), SsA = smem_u32(Ss);

    if (tid < 64) denrow[tid] = 0.f;

    int mh = warp >> 2, nq = warp & 3;
    float accO[2][2][4], accA[2][2][4];
    #pragma unroll
    for (int mi = 0; mi < 2; mi++)
        #pragma unroll
        for (int nt = 0; nt < 2; nt++){
            accO[mi][nt][0]=0.f;accO[mi][nt][1]=0.f;accO[mi][nt][2]=0.f;accO[mi][nt][3]=0.f;
            accA[mi][nt][0]=0.f;accA[mi][nt][1]=0.f;accA[mi][nt][2]=0.f;accA[mi][nt][3]=0.f;
        }
    float den2 = 0.f;

    for (int mtl = 0; mtl < 4; mtl++){
        int m0 = mtl*64;
        __syncthreads();
        for (int i = tid; i < 1024; i += 256){
            int t = i >> 4, qd = (i & 15)*4;
            cpa16(QsA + (t*FP + qd)*4, Qg + (size_t)t*MDIM + m0 + qd);
            cpa16(SsA + (t*FP + qd)*4, Sp + t*MDIM + m0 + qd);
        }
        if (!is_cond)
            for (int i = tid; i < 1024; i += 256){
                int t = i >> 4, qd = (i & 15)*4;
                cpa16(KsA + (t*FP + qd)*4, Kg + (size_t)t*MDIM + m0 + qd);
            }
        if (tid < 64) zps[tid] = zp[m0 + tid];
        CPA_COMMIT(); CPA_WAIT0();
        __syncthreads();
        {
            int row = tid & 63, grp = tid >> 6;
            float d = 0.f;
            #pragma unroll
            for (int j = 0; j < 16; j++){
                int mm = grp*16 + j;
                d = fmaf(Qs[row*FP + mm], zps[mm] + epsv, d);
            }
            den2 += d;
        }
        #pragma unroll
        for (int s = 0; s < 8; s++){
            int k0 = s*8;
            int mr = mh*32;
            uint32_t a00 = ldu(&Qs[(mr+gid   )*FP + k0 + t4]);
            uint32_t a01 = ldu(&Qs[(mr+gid+8 )*FP + k0 + t4]);
            uint32_t a02 = ldu(&Qs[(mr+gid   )*FP + k0 + t4 + 4]);
            uint32_t a03 = ldu(&Qs[(mr+gid+8 )*FP + k0 + t4 + 4]);
            uint32_t a10 = ldu(&Qs[(mr+gid+16)*FP + k0 + t4]);
            uint32_t a11 = ldu(&Qs[(mr+gid+24)*FP + k0 + t4]);
            uint32_t a12 = ldu(&Qs[(mr+gid+16)*FP + k0 + t4 + 4]);
            uint32_t a13 = ldu(&Qs[(mr+gid+24)*FP + k0 + t4 + 4]);
            #pragma unroll
            for (int nt = 0; nt < 2; nt++){
                int n0 = nq*16 + nt*8;
                uint32_t s0 = ldu(&Ss[(n0+gid)*FP + k0 + t4]);
                uint32_t s1 = ldu(&Ss[(n0+gid)*FP + k0 + t4 + 4]);
                mma_tf32(accO[0][nt], a00,a01,a02,a03, s0,s1);
                mma_tf32(accO[1][nt], a10,a11,a12,a13, s0,s1);
                if (!is_cond){
                    uint32_t b0 = ldu(&Ks[(n0+gid)*FP + k0 + t4]);
                    uint32_t b1 = ldu(&Ks[(n0+gid)*FP + k0 + t4 + 4]);
                    mma_tf32(accA[0][nt], a00,a01,a02,a03, b0,b1);
                    mma_tf32(accA[1][nt], a10,a11,a12,a13, b0,b1);
                }
            }
        }
    }
    __syncthreads();
    den2p[tid >> 6][tid & 63] = den2;

    if (!is_cond){
        #pragma unroll
        for (int mi = 0; mi < 2; mi++){
            int r0 = mh*32 + mi*16 + gid;
            float rs0 = 0.f, rs1 = 0.f;
            #pragma unroll
            for (int nt = 0; nt < 2; nt++){
                int col = nq*16 + nt*8 + t4*2;
                float v00 = (col   <= r0  ) ? accA[mi][nt][0] : 0.f;
                float v01 = (col+1 <= r0  ) ? accA[mi][nt][1] : 0.f;
                float v10 = (col   <= r0+8) ? accA[mi][nt][2] : 0.f;
                float v11 = (col+1 <= r0+8) ? accA[mi][nt][3] : 0.f;
                rs0 += v00 + v01; rs1 += v10 + v11;
                Ss[r0*FP + col]       = f2tff(v00);
                Ss[r0*FP + col+1]     = f2tff(v01);
                Ss[(r0+8)*FP + col]   = f2tff(v10);
                Ss[(r0+8)*FP + col+1] = f2tff(v11);
            }
            atomicAdd(&denrow[r0],   rs0);
            atomicAdd(&denrow[r0+8], rs1);
        }
        for (int i = tid; i < 4096; i += 256){
            int s = i >> 6, e = i & 63;
            Ks[e*VTP + s] = f2tff(Vg[i]);
        }
        __syncthreads();
        #pragma unroll
        for (int s = 0; s < 8; s++){
            int k0 = s*8;
            int mr = mh*32;
            uint32_t a00 = ldu(&Ss[(mr+gid   )*FP + k0 + t4]);
            uint32_t a01 = ldu(&Ss[(mr+gid+8 )*FP + k0 + t4]);
            uint32_t a02 = ldu(&Ss[(mr+gid   )*FP + k0 + t4 + 4]);
            uint32_t a03 = ldu(&Ss[(mr+gid+8 )*FP + k0 + t4 + 4]);
            uint32_t a10 = ldu(&Ss[(mr+gid+16)*FP + k0 + t4]);
            uint32_t a11 = ldu(&Ss[(mr+gid+24)*FP + k0 + t4]);
            uint32_t a12 = ldu(&Ss[(mr+gid+16)*FP + k0 + t4 + 4]);
            uint32_t a13 = ldu(&Ss[(mr+gid+24)*FP + k0 + t4 + 4]);
            #pragma unroll
            for (int nt = 0; nt < 2; nt++){
                int n0 = nq*16 + nt*8;
                uint32_t b0 = ldu(&Ks[(n0+gid)*VTP + k0 + t4]);
                uint32_t b1 = ldu(&Ks[(n0+gid)*VTP + k0 + t4 + 4]);
                mma_tf32(accO[0][nt], a00,a01,a02,a03, b0,b1);
                mma_tf32(accO[1][nt], a10,a11,a12,a13, b0,b1);
            }
        }
    }
    __syncthreads();
    if (tid < 64){
        float d = denrow[tid] + den2p[0][tid] + den2p[1][tid]
                + den2p[2][tid] + den2p[3][tid];
        invden[tid] = 1.f / d;
    }
    __syncthreads();
    #pragma unroll
    for (int mi = 0; mi < 2; mi++){
        int r0 = mh*32 + mi*16 + gid;
        float i0 = invden[r0], i1 = invden[r0+8];
        #pragma unroll
        for (int nt = 0; nt < 2; nt++){
            int col = nq*16 + nt*8 + t4*2;
            float2 o0 = make_float2(accO[mi][nt][0]*i0, accO[mi][nt][1]*i0);
            float2 o1 = make_float2(accO[mi][nt][2]*i1, accO[mi][nt][3]*i1);
            *reinterpret_cast<float2*>(&out[(size_t)(rowbase+r0  )*DDIM + col]) = o0;
            *reinterpret_cast<float2*>(&out[(size_t)(rowbase+r0+8)*DDIM + col]) = o1;
        }
    }
}

// ================= launch =================
extern "C" void kernel_launch(void* const* d_in, const int* in_sizes, int n_in,
                              void* d_out, int out_size){
    const float* q    = (const float*)d_in[0];
    const float* k    = (const float*)d_in[1];
    const float* v    = (const float*)d_in[2];
    const float* proj = (const float*)d_in[3];
    float* out = (float*)d_out;

    const int FEAT_SMEM  = (8192 + 16384) * 4;        // 98304
    const int CHUNK_SMEM = (64*VTP + 8192) * 4;       // 49920
    const int ATTN_SMEM  = 3*64*FP*4;                 // 52224
    cudaFuncSetAttribute(feat_mma<true>,  cudaFuncAttributeMaxDynamicSharedMemorySize, FEAT_SMEM);
    cudaFuncSetAttribute(feat_mma<false>, cudaFuncAttributeMaxDynamicSharedMemorySize, FEAT_SMEM);
    cudaFuncSetAttribute(chunk_mma,       cudaFuncAttributeMaxDynamicSharedMemorySize, CHUNK_SMEM);
    cudaFuncSetAttribute(attn_mma,        cudaFuncAttributeMaxDynamicSharedMemorySize, ATTN_SMEM);

    prep_kernel<<<64,256>>>(proj);
    feat_mma<false><<<1024,512,FEAT_SMEM>>>(k);
    feat_mma<true ><<<1024,512,FEAT_SMEM>>>(q);
    kfin_kernel<<<32768,256>>>();
    chunk_mma<<<dim3(61,32,2),256,CHUNK_SMEM>>>(v);
    prefix_kernel<<<2112,256>>>();
    attn_mma<<<dim3(64,32),256,ATTN_SMEM>>>(v, out);
}

// round 11
// speedup vs baseline: 4.0220x; 1.5321x over previous
#include <cuda_runtime.h>
#include <cuda_fp16.h>
#include <math.h>
#include <stdint.h>

#define BH    32
#define NSEQ  4096
#define DDIM  64
#define MDIM  256
#define LCOND 256
#define CSZ   64
#define NCH   60          // (4096-256)/64
#define DN    0.35355339059327373f   // 64^-0.25
#define DIAGC 0.0625f                // dn^2 * 0.5
#define KEPS  1e-4f
#define SEPS2 1.6e-5f     // SCAN_EPS / RATIO  (RATIO scale removed; cancels)
#define FP2   36          // u32 (half2) row stride, conflict-free frag reads

// ---------------- scratch (halves stored ratio-free) ----------------
__device__ __align__(16) __half g_qp[BH*NSEQ*MDIM];      // exp(...)+KEPS
__device__ __align__(16) __half g_kp[BH*NSEQ*MDIM];      // E_b then kp'
__device__ __align__(16) __half g_S [BH*NCH*MDIM*DDIM];  // [e][m] prefix ctx
__device__ float g_Z [BH*NCH*MDIM];
__device__ __align__(16) __half g_Scond[BH*MDIM*DDIM];
__device__ float g_Zcond[BH*MDIM];
__device__ uint32_t g_P2[8192];        // DN*proj, half2 pairs, PAIR-ORDER swizzled
__device__ float g_bmax[1024];
__device__ unsigned g_kmax_bits;

__device__ __forceinline__ unsigned enc_f(float f){
    unsigned u = __float_as_uint(f);
    return (u & 0x80000000u) ? ~u : (u | 0x80000000u);
}
__device__ __forceinline__ float dec_f(unsigned e){
    return (e & 0x80000000u) ? __uint_as_float(e & 0x7FFFFFFFu)
                             : __uint_as_float(~e);
}
__device__ __forceinline__ uint32_t packh2(float a, float b){
    __half2 h = __floats2half2_rn(a, b);
    return *reinterpret_cast<uint32_t*>(&h);
}
__device__ __forceinline__ float2 unph2(uint32_t u){
    __half2 h = *reinterpret_cast<__half2*>(&u);
    return __half22float2(h);
}
__device__ __forceinline__ uint32_t pack2h(__half a, __half b){
    __half2 h = __halves2half2(a, b);
    return *reinterpret_cast<uint32_t*>(&h);
}
__device__ __forceinline__ void mma_f16(float c[4],
        uint32_t a0,uint32_t a1,uint32_t a2,uint32_t a3,
        uint32_t b0,uint32_t b1){
    asm volatile("mma.sync.aligned.m16n8k16.row.col.f32.f16.f16.f32 "
        "{%0,%1,%2,%3}, {%4,%5,%6,%7}, {%8,%9}, {%0,%1,%2,%3};"
        : "+f"(c[0]),"+f"(c[1]),"+f"(c[2]),"+f"(c[3])
        : "r"(a0),"r"(a1),"r"(a2),"r"(a3),"r"(b0),"r"(b1));
}
__device__ __forceinline__ uint32_t smem_u32(const void* p){
    uint32_t a;
    asm("{ .reg .u64 t; cvta.to.shared.u64 t, %1; cvt.u32.u64 %0, t; }"
        : "=r"(a) : "l"(p));
    return a;
}
__device__ __forceinline__ void cpa16(uint32_t dst, const void* src){
    asm volatile("cp.async.cg.shared.global [%0], [%1], 16;" :: "r"(dst), "l"(src));
}
#define CPA_COMMIT() asm volatile("cp.async.commit_group;" ::: "memory")
#define CPA_WAIT0()  asm volatile("cp.async.wait_group 0;" ::: "memory")

// ---------------- prep: pair-order half2 P + reset ----------------
__global__ __launch_bounds__(256) void prep_kernel(const float* __restrict__ proj){
    int i = blockIdx.x*256 + threadIdx.x;      // 0..8191
    if (i == 0) g_kmax_bits = 0u;
    int ntg = i >> 8, s = (i >> 6) & 3, gg = (i >> 3) & 7, slot = i & 7;
    int g = gg ^ s;
    int t4p = ((slot >> 1) ^ ntg) & 3;
    int h = slot & 1;
    int n = ntg*8 + g, kp = s*8 + h*4 + t4p;
    g_P2[i] = packh2(proj[n*64 + kp*2] * DN, proj[n*64 + kp*2 + 1] * DN);
}

// ================= feature kernel (fp16 mma) =================
// Block: 128 rows, 16 warps. D[128 x 256] = X @ (DN*P)^T. Register epilogue.
template<bool IS_Q>
__global__ __launch_bounds__(512) void feat_mma(const float* __restrict__ data){
    extern __shared__ uint32_t smu[];
    uint32_t* sA = smu;            // 4096 u32 frag-order (half2 pairs)
    uint32_t* sB = smu + 4096;     // 8192 u32 pair-order (cp.async'd)
    __shared__ float rowsq[128];
    __shared__ unsigned rowmx[128];
    __shared__ unsigned bmax;

    int tid = threadIdx.x, lane = tid & 31, warp = tid >> 5;
    int gid = lane >> 2, t4 = lane & 3;
    int rowbase = blockIdx.x * 128;
    if (tid == 0) bmax = 0u;
    if (IS_Q && tid < 128) rowmx[tid] = 0u;

    {
        uint32_t sBA = smem_u32(sB);
        for (int i = tid; i < 2048; i += 512)
            cpa16(sBA + i*16, g_P2 + i*4);
        CPA_COMMIT();
    }
    // stage X: one row per warp per iter; full-warp rowsq reduce
    const float* xg = data + (size_t)rowbase * DDIM;
    {
        int kp2 = lane;
        int s = kp2 >> 3, t4s = kp2 & 3, jk = ((kp2 >> 2) & 1) << 1;
        #pragma unroll
        for (int kl = 0; kl < 8; kl++){
            int r = warp + kl*16;
            float2 x2 = *reinterpret_cast<const float2*>(&xg[r*64 + kp2*2]);
            float sq = x2.x*x2.x + x2.y*x2.y;
            #pragma unroll
            for (int o = 16; o; o >>= 1) sq += __shfl_xor_sync(~0u, sq, o);
            if (lane == 0) rowsq[r] = sq;
            int mt = r >> 4, rr = r & 15;
            int ln = ((rr & 7) << 2) | t4s;
            int j  = (rr >> 3) | jk;
            sA[(mt*4 + s)*128 + ln*4 + j] = packh2(x2.x, x2.y);
        }
    }
    CPA_WAIT0();
    __syncthreads();

    int mh = warp >> 2, nq = warp & 3;
    float c[2][8][4];
    #pragma unroll
    for (int mi = 0; mi < 2; mi++)
        #pragma unroll
        for (int nt = 0; nt < 8; nt++){ c[mi][nt][0]=0.f;c[mi][nt][1]=0.f;c[mi][nt][2]=0.f;c[mi][nt][3]=0.f; }

    #pragma unroll
    for (int s = 0; s < 4; s++){
        uint4 av0 = *reinterpret_cast<uint4*>(&sA[((mh*2  )*4 + s)*128 + lane*4]);
        uint4 av1 = *reinterpret_cast<uint4*>(&sA[((mh*2+1)*4 + s)*128 + lane*4]);
        #pragma unroll
        for (int nt = 0; nt < 8; nt++){
            int ntg = nq*8 + nt;
            uint2 bv = *reinterpret_cast<uint2*>(
                &sB[(ntg*4 + s)*64 + ((gid ^ s) << 3) + ((t4 ^ (nt & 3)) << 1)]);
            mma_f16(c[0][nt], av0.x,av0.y,av0.z,av0.w, bv.x,bv.y);
            mma_f16(c[1][nt], av1.x,av1.y,av1.z,av1.w, bv.x,bv.y);
        }
    }

    if (IS_Q){
        float mx[2][2];
        #pragma unroll
        for (int mi = 0; mi < 2; mi++){
            mx[mi][0] = -3.4e38f; mx[mi][1] = -3.4e38f;
            #pragma unroll
            for (int nt = 0; nt < 8; nt++){
                mx[mi][0] = fmaxf(mx[mi][0], fmaxf(c[mi][nt][0], c[mi][nt][1]));
                mx[mi][1] = fmaxf(mx[mi][1], fmaxf(c[mi][nt][2], c[mi][nt][3]));
            }
            #pragma unroll
            for (int o = 1; o < 4; o <<= 1){
                mx[mi][0] = fmaxf(mx[mi][0], __shfl_xor_sync(~0u, mx[mi][0], o));
                mx[mi][1] = fmaxf(mx[mi][1], __shfl_xor_sync(~0u, mx[mi][1], o));
            }
        }
        if (t4 == 0){
            #pragma unroll
            for (int mi = 0; mi < 2; mi++){
                atomicMax(&rowmx[mh*32 + mi*16 + gid],     enc_f(mx[mi][0]));
                atomicMax(&rowmx[mh*32 + mi*16 + gid + 8], enc_f(mx[mi][1]));
            }
        }
        __syncthreads();
        uint32_t* ogu = reinterpret_cast<uint32_t*>(g_qp + (size_t)rowbase*MDIM);
        #pragma unroll
        for (int mi = 0; mi < 2; mi++){
            int r0 = mh*32 + mi*16 + gid;
            float sub0 = rowsq[r0]*DIAGC   + dec_f(rowmx[r0]);
            float sub1 = rowsq[r0+8]*DIAGC + dec_f(rowmx[r0+8]);
            #pragma unroll
            for (int nt = 0; nt < 8; nt++){
                int colh = nq*32 + nt*4 + t4;
                ogu[(size_t)r0*128 + colh] = packh2(
                    __expf(c[mi][nt][0]-sub0)+KEPS,
                    __expf(c[mi][nt][1]-sub0)+KEPS);
                ogu[(size_t)(r0+8)*128 + colh] = packh2(
                    __expf(c[mi][nt][2]-sub1)+KEPS,
                    __expf(c[mi][nt][3]-sub1)+KEPS);
            }
        }
    } else {
        float mx = -3.4e38f;
        #pragma unroll
        for (int mi = 0; mi < 2; mi++)
            #pragma unroll
            for (int nt = 0; nt < 8; nt++)
                mx = fmaxf(mx, fmaxf(fmaxf(c[mi][nt][0], c[mi][nt][1]),
                                     fmaxf(c[mi][nt][2], c[mi][nt][3])));
        #pragma unroll
        for (int o = 16; o; o >>= 1) mx = fmaxf(mx, __shfl_xor_sync(~0u, mx, o));
        if (lane == 0) atomicMax(&bmax, enc_f(mx));
        __syncthreads();
        float bmaxf = dec_f(bmax);
        if (tid == 0){
            atomicMax(&g_kmax_bits, bmax);
            g_bmax[blockIdx.x] = bmaxf;
        }
        uint32_t* ogu = reinterpret_cast<uint32_t*>(g_kp + (size_t)rowbase*MDIM);
        #pragma unroll
        for (int mi = 0; mi < 2; mi++){
            int r0 = mh*32 + mi*16 + gid;
            float s0 = rowsq[r0]*DIAGC + bmaxf, s1 = rowsq[r0+8]*DIAGC + bmaxf;
            #pragma unroll
            for (int nt = 0; nt < 8; nt++){
                int colh = nq*32 + nt*4 + t4;
                ogu[(size_t)r0*128 + colh] = packh2(
                    __expf(c[mi][nt][0]-s0), __expf(c[mi][nt][1]-s0));
                ogu[(size_t)(r0+8)*128 + colh] = packh2(
                    __expf(c[mi][nt][2]-s1), __expf(c[mi][nt][3]-s1));
            }
        }
    }
}

// ================= kp finalize: kp = E*exp(bmax-kmax) + KEPS =================
__global__ __launch_bounds__(256) void kfin_kernel(){
    float kmax = dec_f(g_kmax_bits);
    size_t i = (size_t)blockIdx.x*256 + threadIdx.x;    // uint4 index (8 halves)
    int b = (int)(i >> 12);
    float s = __expf(g_bmax[b] - kmax);
    uint4 w = reinterpret_cast<uint4*>(g_kp)[i];
    float2 f0 = unph2(w.x), f1 = unph2(w.y), f2 = unph2(w.z), f3 = unph2(w.w);
    w.x = packh2(f0.x*s + KEPS, f0.y*s + KEPS);
    w.y = packh2(f1.x*s + KEPS, f1.y*s + KEPS);
    w.z = packh2(f2.x*s + KEPS, f2.y*s + KEPS);
    w.w = packh2(f3.x*s + KEPS, f3.y*s + KEPS);
    reinterpret_cast<uint4*>(g_kp)[i] = w;
}

// ================= chunk states (m-split, fp16) =================
__global__ __launch_bounds__(256,3) void chunk_mma(const float* __restrict__ v){
    extern __shared__ uint32_t smu[];
    uint32_t* VT = smu;            // [64 e][FP2] pairs over r
    uint32_t* KT = smu + 64*FP2;   // pair-order 4096 u32 (128 m)
    __shared__ float zbuf[256];

    int tid = threadIdx.x, lane = tid & 31, warp = tid >> 5;
    int gid = lane >> 2, t4 = lane & 3;
    int bh = blockIdx.y, cidx = blockIdx.x;
    int mbase = blockIdx.z * 128;
    int rowbase, npass;
    __half *Sout; float *Zout;
    if (cidx == 0){
        rowbase = bh*NSEQ; npass = 4;
        Sout = g_Scond + (size_t)bh*MDIM*DDIM;
        Zout = g_Zcond + bh*MDIM;
    } else {
        rowbase = bh*NSEQ + LCOND + (cidx-1)*CSZ; npass = 1;
        Sout = g_S + (size_t)(bh*NCH + cidx-1)*MDIM*DDIM;
        Zout = g_Z + (bh*NCH + cidx-1)*MDIM;
    }

    int eh = warp >> 2, nq = warp & 3;
    float c[2][4][4];
    #pragma unroll
    for (int mi = 0; mi < 2; mi++)
        #pragma unroll
        for (int nt = 0; nt < 4; nt++){ c[mi][nt][0]=0.f;c[mi][nt][1]=0.f;c[mi][nt][2]=0.f;c[mi][nt][3]=0.f; }
    float z = 0.f;

    int m_local = tid & 127, rbase = (tid >> 7) * 32;
    int m_ntg = m_local >> 3, m_g = m_local & 7, m_x = m_ntg & 3;
    for (int p = 0; p < npass; p++){
        int r0 = rowbase + p*64;
        __syncthreads();
        const float* vg = v + (size_t)r0*DDIM;
        for (int i = tid; i < 2048; i += 256){
            int rp = i >> 6, e = i & 63;
            VT[e*FP2 + rp] = packh2(vg[rp*128 + e], vg[rp*128 + 64 + e]);
        }
        const __half* kg = g_kp + (size_t)(r0 + rbase)*MDIM + mbase + m_local;
        #pragma unroll 4
        for (int j = 0; j < 16; j++){
            __half kv0 = kg[(size_t)(2*j)*MDIM];
            __half kv1 = kg[(size_t)(2*j+1)*MDIM];
            z += __half2float(kv0) + __half2float(kv1);
            int rp = (rbase >> 1) + j;
            int s4 = rp >> 3, t4p = rp & 3, h = (rp >> 2) & 1;
            KT[(m_ntg*4 + s4)*64 + ((m_g ^ s4) << 3) + ((t4p ^ m_x) << 1) + h] = pack2h(kv0, kv1);
        }
        __syncthreads();
        #pragma unroll
        for (int s = 0; s < 4; s++){
            int kp0 = s*8, er0 = eh*32;
            uint32_t a00 = VT[(er0+gid   )*FP2 + kp0 + t4];
            uint32_t a01 = VT[(er0+gid+8 )*FP2 + kp0 + t4];
            uint32_t a02 = VT[(er0+gid   )*FP2 + kp0 + t4 + 4];
            uint32_t a03 = VT[(er0+gid+8 )*FP2 + kp0 + t4 + 4];
            uint32_t a10 = VT[(er0+gid+16)*FP2 + kp0 + t4];
            uint32_t a11 = VT[(er0+gid+24)*FP2 + kp0 + t4];
            uint32_t a12 = VT[(er0+gid+16)*FP2 + kp0 + t4 + 4];
            uint32_t a13 = VT[(er0+gid+24)*FP2 + kp0 + t4 + 4];
            #pragma unroll
            for (int nt = 0; nt < 4; nt++){
                int ntg = nq*4 + nt;
                uint2 bv = *reinterpret_cast<uint2*>(
                    &KT[(ntg*4 + s)*64 + ((gid ^ s) << 3) + ((t4 ^ (ntg & 3)) << 1)]);
                mma_f16(c[0][nt], a00,a01,a02,a03, bv.x,bv.y);
                mma_f16(c[1][nt], a10,a11,a12,a13, bv.x,bv.y);
            }
        }
    }
    zbuf[tid] = z;
    uint32_t* SoU = reinterpret_cast<uint32_t*>(Sout);
    #pragma unroll
    for (int mi = 0; mi < 2; mi++){
        int r0 = eh*32 + mi*16 + gid;
        #pragma unroll
        for (int nt = 0; nt < 4; nt++){
            int colh = (mbase >> 1) + nq*16 + nt*4 + t4;
            SoU[(size_t)r0*128 + colh]     = packh2(c[mi][nt][0], c[mi][nt][1]);
            SoU[(size_t)(r0+8)*128 + colh] = packh2(c[mi][nt][2], c[mi][nt][3]);
        }
    }
    __syncthreads();
    if (tid < 128) Zout[mbase + tid] = zbuf[tid] + zbuf[tid + 128];
}

// ================= exclusive prefix over chunks =================
__global__ __launch_bounds__(256) void prefix_kernel(){
    int idx = blockIdx.x*256 + threadIdx.x;
    const int totS2 = BH*8192;                 // half2 columns
    if (idx < totS2){
        int bh = idx >> 13;
        int j  = idx & 8191;
        float2 acc = unph2(reinterpret_cast<uint32_t*>(g_Scond)[idx]);
        uint32_t* p = reinterpret_cast<uint32_t*>(g_S) + (size_t)bh*NCH*8192 + j;
        #pragma unroll 4
        for (int c = 0; c < NCH; c++){
            uint32_t t = p[(size_t)c*8192];
            p[(size_t)c*8192] = packh2(acc.x, acc.y);
            float2 f = unph2(t);
            acc.x += f.x; acc.y += f.y;
        }
    } else {
        int k2 = idx - totS2;
        int bh = k2 >> 8;
        int j  = k2 & 255;
        float acc = g_Zcond[k2];
        float* p = g_Z + bh*NCH*MDIM + j;
        #pragma unroll 4
        for (int c = 0; c < NCH; c++){
            float t = p[c*MDIM];
            p[c*MDIM] = acc;
            acc += t;
        }
    }
}

// ================= attention output (fp16) =================
// 256 threads, 8 warps; warp tile m32 (mh=warp>>2) x n16 (nq=warp&3).
__global__ __launch_bounds__(256,3) void attn_mma(const float* __restrict__ v,
                                                  float* __restrict__ out){
    extern __shared__ uint32_t smu[];
    uint32_t* Qs = smu;               // [64][FP2]
    uint32_t* Ks = smu + 64*FP2;      // K tile ; phase2: V^T pairs
    uint32_t* Ss = smu + 2*64*FP2;    // S tile ; phase2: As pairs
    __shared__ float zps[64];
    __shared__ float den2p[4][64];
    __shared__ float denrow[64];
    __shared__ float invden[64];

    int tid = threadIdx.x, lane = tid & 31, warp = tid >> 5;
    int gid = lane >> 2, t4 = lane & 3;
    int bh = blockIdx.y, cc = blockIdx.x;
    bool is_cond = (cc < 4);
    int rowbase;
    const __half *Sp; const float *zp;
    if (is_cond){
        rowbase = bh*NSEQ + cc*64;
        Sp = g_Scond + (size_t)bh*MDIM*DDIM;
        zp = g_Zcond + bh*MDIM;
    } else {
        int c = cc - 4;
        rowbase = bh*NSEQ + LCOND + c*CSZ;
        Sp = g_S + (size_t)(bh*NCH + c)*MDIM*DDIM;
        zp = g_Z + (bh*NCH + c)*MDIM;
    }
    const __half* Qg = g_qp + (size_t)rowbase*MDIM;
    const __half* Kg = g_kp + (size_t)rowbase*MDIM;
    const float* Vg = v + (size_t)rowbase*DDIM;
    float epsv = is_cond ? 0.f : SEPS2;
    uint32_t QsA = smem_u32(Qs), KsA = smem_u32(Ks), SsA = smem_u32(Ss);

    if (tid < 64) denrow[tid] = 0.f;

    int mh = warp >> 2, nq = warp & 3;
    float accO[2][2][4], accA[2][2][4];
    #pragma unroll
    for (int mi = 0; mi < 2; mi++)
        #pragma unroll
        for (int nt = 0; nt < 2; nt++){
            accO[mi][nt][0]=0.f;accO[mi][nt][1]=0.f;accO[mi][nt][2]=0.f;accO[mi][nt][3]=0.f;
            accA[mi][nt][0]=0.f;accA[mi][nt][1]=0.f;accA[mi][nt][2]=0.f;accA[mi][nt][3]=0.f;
        }
    float den2 = 0.f;

    for (int mtl = 0; mtl < 4; mtl++){
        int m0 = mtl*64;
        __syncthreads();
        for (int i = tid; i < 512; i += 256){
            int t = i >> 3, qd = (i & 7)*4;
            cpa16(QsA + (t*FP2 + qd)*4, Qg + (size_t)t*MDIM + m0 + qd*2);
            cpa16(SsA + (t*FP2 + qd)*4, Sp + (size_t)t*MDIM + m0 + qd*2);
        }
        if (!is_cond)
            for (int i = tid; i < 512; i += 256){
                int t = i >> 3, qd = (i & 7)*4;
                cpa16(KsA + (t*FP2 + qd)*4, Kg + (size_t)t*MDIM + m0 + qd*2);
            }
        if (tid < 64) zps[tid] = zp[m0 + tid];
        CPA_COMMIT(); CPA_WAIT0();
        __syncthreads();
        {
            int row = tid & 63, grp = tid >> 6;
            float d = 0.f;
            #pragma unroll
            for (int j = 0; j < 8; j++){
                int mp = grp*8 + j;
                float2 f = unph2(Qs[row*FP2 + mp]);
                d = fmaf(f.x, zps[2*mp] + epsv, d);
                d = fmaf(f.y, zps[2*mp+1] + epsv, d);
            }
            den2 += d;
        }
        #pragma unroll
        for (int s = 0; s < 4; s++){
            int kp0 = s*8, mr = mh*32;
            uint32_t a00 = Qs[(mr+gid   )*FP2 + kp0 + t4];
            uint32_t a01 = Qs[(mr+gid+8 )*FP2 + kp0 + t4];
            uint32_t a02 = Qs[(mr+gid   )*FP2 + kp0 + t4 + 4];
            uint32_t a03 = Qs[(mr+gid+8 )*FP2 + kp0 + t4 + 4];
            uint32_t a10 = Qs[(mr+gid+16)*FP2 + kp0 + t4];
            uint32_t a11 = Qs[(mr+gid+24)*FP2 + kp0 + t4];
            uint32_t a12 = Qs[(mr+gid+16)*FP2 + kp0 + t4 + 4];
            uint32_t a13 = Qs[(mr+gid+24)*FP2 + kp0 + t4 + 4];
            #pragma unroll
            for (int nt = 0; nt < 2; nt++){
                int n0 = nq*16 + nt*8;
                uint32_t s0 = Ss[(n0+gid)*FP2 + kp0 + t4];
                uint32_t s1 = Ss[(n0+gid)*FP2 + kp0 + t4 + 4];
                mma_f16(accO[0][nt], a00,a01,a02,a03, s0,s1);
                mma_f16(accO[1][nt], a10,a11,a12,a13, s0,s1);
                if (!is_cond){
                    uint32_t b0 = Ks[(n0+gid)*FP2 + kp0 + t4];
                    uint32_t b1 = Ks[(n0+gid)*FP2 + kp0 + t4 + 4];
                    mma_f16(accA[0][nt], a00,a01,a02,a03, b0,b1);
                    mma_f16(accA[1][nt], a10,a11,a12,a13, b0,b1);
                }
            }
        }
    }
    __syncthreads();
    den2p[tid >> 6][tid & 63] = den2;

    if (!is_cond){
        #pragma unroll
        for (int mi = 0; mi < 2; mi++){
            int r0 = mh*32 + mi*16 + gid;
            float rs0 = 0.f, rs1 = 0.f;
            #pragma unroll
            for (int nt = 0; nt < 2; nt++){
                int col = nq*16 + nt*8 + t4*2;
                int colh = nq*8 + nt*4 + t4;
                float v00 = (col   <= r0  ) ? accA[mi][nt][0] : 0.f;
                float v01 = (col+1 <= r0  ) ? accA[mi][nt][1] : 0.f;
                float v10 = (col   <= r0+8) ? accA[mi][nt][2] : 0.f;
                float v11 = (col+1 <= r0+8) ? accA[mi][nt][3] : 0.f;
                rs0 += v00 + v01; rs1 += v10 + v11;
                Ss[r0*FP2 + colh]     = packh2(v00, v01);
                Ss[(r0+8)*FP2 + colh] = packh2(v10, v11);
            }
            atomicAdd(&denrow[r0],   rs0);
            atomicAdd(&denrow[r0+8], rs1);
        }
        for (int i = tid; i < 2048; i += 256){
            int sp = i >> 6, e = i & 63;
            Ks[e*FP2 + sp] = packh2(Vg[sp*128 + e], Vg[sp*128 + 64 + e]);
        }
        __syncthreads();
        #pragma unroll
        for (int s = 0; s < 4; s++){
            int kp0 = s*8, mr = mh*32;
            uint32_t a00 = Ss[(mr+gid   )*FP2 + kp0 + t4];
            uint32_t a01 = Ss[(mr+gid+8 )*FP2 + kp0 + t4];
            uint32_t a02 = Ss[(mr+gid   )*FP2 + kp0 + t4 + 4];
            uint32_t a03 = Ss[(mr+gid+8 )*FP2 + kp0 + t4 + 4];
            uint32_t a10 = Ss[(mr+gid+16)*FP2 + kp0 + t4];
            uint32_t a11 = Ss[(mr+gid+24)*FP2 + kp0 + t4];
            uint32_t a12 = Ss[(mr+gid+16)*FP2 + kp0 + t4 + 4];
            uint32_t a13 = Ss[(mr+gid+24)*FP2 + kp0 + t4 + 4];
            #pragma unroll
            for (int nt = 0; nt < 2; nt++){
                int n0 = nq*16 + nt*8;
                uint32_t b0 = Ks[(n0+gid)*FP2 + kp0 + t4];
                uint32_t b1 = Ks[(n0+gid)*FP2 + kp0 + t4 + 4];
                mma_f16(accO[0][nt], a00,a01,a02,a03, b0,b1);
                mma_f16(accO[1][nt], a10,a11,a12,a13, b0,b1);
            }
        }
    }
    __syncthreads();
    if (tid < 64){
        float d = denrow[tid] + den2p[0][tid] + den2p[1][tid]
                + den2p[2][tid] + den2p[3][tid];
        invden[tid] = 1.f / d;
    }
    __syncthreads();
    #pragma unroll
    for (int mi = 0; mi < 2; mi++){
        int r0 = mh*32 + mi*16 + gid;
        float i0 = invden[r0], i1 = invden[r0+8];
        #pragma unroll
        for (int nt = 0; nt < 2; nt++){
            int col = nq*16 + nt*8 + t4*2;
            float2 o0 = make_float2(accO[mi][nt][0]*i0, accO[mi][nt][1]*i0);
            float2 o1 = make_float2(accO[mi][nt][2]*i1, accO[mi][nt][3]*i1);
            *reinterpret_cast<float2*>(&out[(size_t)(rowbase+r0  )*DDIM + col]) = o0;
            *reinterpret_cast<float2*>(&out[(size_t)(rowbase+r0+8)*DDIM + col]) = o1;
        }
    }
}

// ================= launch =================
extern "C" void kernel_launch(void* const* d_in, const int* in_sizes, int n_in,
                              void* d_out, int out_size){
    const float* q    = (const float*)d_in[0];
    const float* k    = (const float*)d_in[1];
    const float* v    = (const float*)d_in[2];
    const float* proj = (const float*)d_in[3];
    float* out = (float*)d_out;

    const int FEAT_SMEM  = (4096 + 8192) * 4;       // 49152
    const int CHUNK_SMEM = (64*FP2 + 4096) * 4;     // 25600
    const int ATTN_SMEM  = 3*64*FP2*4;              // 27648
    cudaFuncSetAttribute(feat_mma<true>,  cudaFuncAttributeMaxDynamicSharedMemorySize, FEAT_SMEM);
    cudaFuncSetAttribute(feat_mma<false>, cudaFuncAttributeMaxDynamicSharedMemorySize, FEAT_SMEM);
    cudaFuncSetAttribute(chunk_mma,       cudaFuncAttributeMaxDynamicSharedMemorySize, CHUNK_SMEM);
    cudaFuncSetAttribute(attn_mma,        cudaFuncAttributeMaxDynamicSharedMemorySize, ATTN_SMEM);

    prep_kernel<<<32,256>>>(proj);
    feat_mma<false><<<1024,512,FEAT_SMEM>>>(k);
    feat_mma<true ><<<1024,512,FEAT_SMEM>>>(q);
    kfin_kernel<<<16384,256>>>();
    chunk_mma<<<dim3(61,32,2),256,CHUNK_SMEM>>>(v);
    prefix_kernel<<<1056,256>>>();
    attn_mma<<<dim3(64,32),256,ATTN_SMEM>>>(v, out);
}

// round 12
// speedup vs baseline: 4.2912x; 1.0669x over previous
#include <cuda_runtime.h>
#include <cuda_fp16.h>
#include <math.h>
#include <stdint.h>

#define BH    32
#define NSEQ  4096
#define DDIM  64
#define MDIM  256
#define LCOND 256
#define CSZ   64
#define NCH   60          // (4096-256)/64
#define DN    0.35355339059327373f   // 64^-0.25
#define DIAGC 0.0625f                // dn^2 * 0.5
#define KEPS  1e-4f
#define SEPS2 1.6e-5f     // SCAN_EPS / RATIO  (RATIO scale removed; cancels)
#define FP2   36          // u32 (half2) row stride, conflict-free frag reads

// ---------------- scratch (halves stored ratio-free) ----------------
__device__ __align__(16) __half g_qp[BH*NSEQ*MDIM];      // exp(...)+KEPS
__device__ __align__(16) __half g_kp[BH*NSEQ*MDIM];      // E = exp(dd-diag-bmax)
__device__ __align__(16) __half g_S [BH*NCH*MDIM*DDIM];  // [e][m] prefix ctx
__device__ float g_Z [BH*NCH*MDIM];
__device__ __align__(16) __half g_Scond[BH*MDIM*DDIM];
__device__ float g_Zcond[BH*MDIM];
__device__ uint32_t g_P2[8192];        // DN*proj, half2 pairs, PAIR-ORDER swizzled
__device__ float g_bmax[1024];
__device__ unsigned g_kmax_bits;

__device__ __forceinline__ unsigned enc_f(float f){
    unsigned u = __float_as_uint(f);
    return (u & 0x80000000u) ? ~u : (u | 0x80000000u);
}
__device__ __forceinline__ float dec_f(unsigned e){
    return (e & 0x80000000u) ? __uint_as_float(e & 0x7FFFFFFFu)
                             : __uint_as_float(~e);
}
__device__ __forceinline__ uint32_t packh2(float a, float b){
    __half2 h = __floats2half2_rn(a, b);
    return *reinterpret_cast<uint32_t*>(&h);
}
__device__ __forceinline__ float2 unph2(uint32_t u){
    __half2 h = *reinterpret_cast<__half2*>(&u);
    return __half22float2(h);
}
__device__ __forceinline__ void mma_f16(float c[4],
        uint32_t a0,uint32_t a1,uint32_t a2,uint32_t a3,
        uint32_t b0,uint32_t b1){
    asm volatile("mma.sync.aligned.m16n8k16.row.col.f32.f16.f16.f32 "
        "{%0,%1,%2,%3}, {%4,%5,%6,%7}, {%8,%9}, {%0,%1,%2,%3};"
        : "+f"(c[0]),"+f"(c[1]),"+f"(c[2]),"+f"(c[3])
        : "r"(a0),"r"(a1),"r"(a2),"r"(a3),"r"(b0),"r"(b1));
}
__device__ __forceinline__ uint32_t smem_u32(const void* p){
    uint32_t a;
    asm("{ .reg .u64 t; cvta.to.shared.u64 t, %1; cvt.u32.u64 %0, t; }"
        : "=r"(a) : "l"(p));
    return a;
}
__device__ __forceinline__ void cpa16(uint32_t dst, const void* src){
    asm volatile("cp.async.cg.shared.global [%0], [%1], 16;" :: "r"(dst), "l"(src));
}
#define CPA_COMMIT() asm volatile("cp.async.commit_group;" ::: "memory")
#define CPA_WAIT0()  asm volatile("cp.async.wait_group 0;" ::: "memory")

// ---------------- prep: pair-order half2 P + reset ----------------
__global__ __launch_bounds__(256) void prep_kernel(const float* __restrict__ proj){
    int i = blockIdx.x*256 + threadIdx.x;      // 0..8191
    if (i == 0) g_kmax_bits = 0u;
    int ntg = i >> 8, s = (i >> 6) & 3, gg = (i >> 3) & 7, slot = i & 7;
    int g = gg ^ s;
    int t4p = ((slot >> 1) ^ ntg) & 3;
    int h = slot & 1;
    int n = ntg*8 + g, kp = s*8 + h*4 + t4p;
    g_P2[i] = packh2(proj[n*64 + kp*2] * DN, proj[n*64 + kp*2 + 1] * DN);
}

// ================= feature kernel (fp16 mma) =================
// Block: 128 rows, 16 warps. D[128 x 256] = X @ (DN*P)^T. Register epilogue.
template<bool IS_Q>
__global__ __launch_bounds__(512) void feat_mma(const float* __restrict__ data){
    extern __shared__ uint32_t smu[];
    uint32_t* sA = smu;            // 4096 u32 frag-order (half2 pairs)
    uint32_t* sB = smu + 4096;     // 8192 u32 pair-order (cp.async'd)
    __shared__ float rowsq[128];
    __shared__ unsigned rowmx[128];
    __shared__ unsigned bmax;

    int tid = threadIdx.x, lane = tid & 31, warp = tid >> 5;
    int gid = lane >> 2, t4 = lane & 3;
    int rowbase = blockIdx.x * 128;
    if (tid == 0) bmax = 0u;
    if (IS_Q && tid < 128) rowmx[tid] = 0u;

    {
        uint32_t sBA = smem_u32(sB);
        for (int i = tid; i < 2048; i += 512)
            cpa16(sBA + i*16, g_P2 + i*4);
        CPA_COMMIT();
    }
    const float* xg = data + (size_t)rowbase * DDIM;
    {
        int kp2 = lane;
        int s = kp2 >> 3, t4s = kp2 & 3, jk = ((kp2 >> 2) & 1) << 1;
        #pragma unroll
        for (int kl = 0; kl < 8; kl++){
            int r = warp + kl*16;
            float2 x2 = *reinterpret_cast<const float2*>(&xg[r*64 + kp2*2]);
            float sq = x2.x*x2.x + x2.y*x2.y;
            #pragma unroll
            for (int o = 16; o; o >>= 1) sq += __shfl_xor_sync(~0u, sq, o);
            if (lane == 0) rowsq[r] = sq;
            int mt = r >> 4, rr = r & 15;
            int ln = ((rr & 7) << 2) | t4s;
            int j  = (rr >> 3) | jk;
            sA[(mt*4 + s)*128 + ln*4 + j] = packh2(x2.x, x2.y);
        }
    }
    CPA_WAIT0();
    __syncthreads();

    int mh = warp >> 2, nq = warp & 3;
    float c[2][8][4];
    #pragma unroll
    for (int mi = 0; mi < 2; mi++)
        #pragma unroll
        for (int nt = 0; nt < 8; nt++){ c[mi][nt][0]=0.f;c[mi][nt][1]=0.f;c[mi][nt][2]=0.f;c[mi][nt][3]=0.f; }

    #pragma unroll
    for (int s = 0; s < 4; s++){
        uint4 av0 = *reinterpret_cast<uint4*>(&sA[((mh*2  )*4 + s)*128 + lane*4]);
        uint4 av1 = *reinterpret_cast<uint4*>(&sA[((mh*2+1)*4 + s)*128 + lane*4]);
        #pragma unroll
        for (int nt = 0; nt < 8; nt++){
            int ntg = nq*8 + nt;
            uint2 bv = *reinterpret_cast<uint2*>(
                &sB[(ntg*4 + s)*64 + ((gid ^ s) << 3) + ((t4 ^ (nt & 3)) << 1)]);
            mma_f16(c[0][nt], av0.x,av0.y,av0.z,av0.w, bv.x,bv.y);
            mma_f16(c[1][nt], av1.x,av1.y,av1.z,av1.w, bv.x,bv.y);
        }
    }

    if (IS_Q){
        float mx[2][2];
        #pragma unroll
        for (int mi = 0; mi < 2; mi++){
            mx[mi][0] = -3.4e38f; mx[mi][1] = -3.4e38f;
            #pragma unroll
            for (int nt = 0; nt < 8; nt++){
                mx[mi][0] = fmaxf(mx[mi][0], fmaxf(c[mi][nt][0], c[mi][nt][1]));
                mx[mi][1] = fmaxf(mx[mi][1], fmaxf(c[mi][nt][2], c[mi][nt][3]));
            }
            #pragma unroll
            for (int o = 1; o < 4; o <<= 1){
                mx[mi][0] = fmaxf(mx[mi][0], __shfl_xor_sync(~0u, mx[mi][0], o));
                mx[mi][1] = fmaxf(mx[mi][1], __shfl_xor_sync(~0u, mx[mi][1], o));
            }
        }
        if (t4 == 0){
            #pragma unroll
            for (int mi = 0; mi < 2; mi++){
                atomicMax(&rowmx[mh*32 + mi*16 + gid],     enc_f(mx[mi][0]));
                atomicMax(&rowmx[mh*32 + mi*16 + gid + 8], enc_f(mx[mi][1]));
            }
        }
        __syncthreads();
        uint32_t* ogu = reinterpret_cast<uint32_t*>(g_qp + (size_t)rowbase*MDIM);
        #pragma unroll
        for (int mi = 0; mi < 2; mi++){
            int r0 = mh*32 + mi*16 + gid;
            float sub0 = rowsq[r0]*DIAGC   + dec_f(rowmx[r0]);
            float sub1 = rowsq[r0+8]*DIAGC + dec_f(rowmx[r0+8]);
            #pragma unroll
            for (int nt = 0; nt < 8; nt++){
                int colh = nq*32 + nt*4 + t4;
                ogu[(size_t)r0*128 + colh] = packh2(
                    __expf(c[mi][nt][0]-sub0)+KEPS,
                    __expf(c[mi][nt][1]-sub0)+KEPS);
                ogu[(size_t)(r0+8)*128 + colh] = packh2(
                    __expf(c[mi][nt][2]-sub1)+KEPS,
                    __expf(c[mi][nt][3]-sub1)+KEPS);
            }
        }
    } else {
        float mx = -3.4e38f;
        #pragma unroll
        for (int mi = 0; mi < 2; mi++)
            #pragma unroll
            for (int nt = 0; nt < 8; nt++)
                mx = fmaxf(mx, fmaxf(fmaxf(c[mi][nt][0], c[mi][nt][1]),
                                     fmaxf(c[mi][nt][2], c[mi][nt][3])));
        #pragma unroll
        for (int o = 16; o; o >>= 1) mx = fmaxf(mx, __shfl_xor_sync(~0u, mx, o));
        if (lane == 0) atomicMax(&bmax, enc_f(mx));
        __syncthreads();
        float bmaxf = dec_f(bmax);
        if (tid == 0){
            atomicMax(&g_kmax_bits, bmax);
            g_bmax[blockIdx.x] = bmaxf;
        }
        uint32_t* ogu = reinterpret_cast<uint32_t*>(g_kp + (size_t)rowbase*MDIM);
        #pragma unroll
        for (int mi = 0; mi < 2; mi++){
            int r0 = mh*32 + mi*16 + gid;
            float s0 = rowsq[r0]*DIAGC + bmaxf, s1 = rowsq[r0+8]*DIAGC + bmaxf;
            #pragma unroll
            for (int nt = 0; nt < 8; nt++){
                int colh = nq*32 + nt*4 + t4;
                ogu[(size_t)r0*128 + colh] = packh2(
                    __expf(c[mi][nt][0]-s0), __expf(c[mi][nt][1]-s0));
                ogu[(size_t)(r0+8)*128 + colh] = packh2(
                    __expf(c[mi][nt][2]-s1), __expf(c[mi][nt][3]-s1));
            }
        }
    }
}

// ================= chunk states (m-split, fp16) =================
// kp finalize folded in: kf = E*exp(bmax_blk - kmax) + KEPS during staging.
__global__ __launch_bounds__(256,3) void chunk_mma(const float* __restrict__ v){
    extern __shared__ uint32_t smu[];
    uint32_t* VT = smu;            // [64 e][FP2] pairs over r
    uint32_t* KT = smu + 64*FP2;   // pair-order 4096 u32 (128 m)
    __shared__ float zbuf[256];

    int tid = threadIdx.x, lane = tid & 31, warp = tid >> 5;
    int gid = lane >> 2, t4 = lane & 3;
    int bh = blockIdx.y, cidx = blockIdx.x;
    int mbase = blockIdx.z * 128;
    int rowbase, npass;
    __half *Sout; float *Zout;
    if (cidx == 0){
        rowbase = bh*NSEQ; npass = 4;
        Sout = g_Scond + (size_t)bh*MDIM*DDIM;
        Zout = g_Zcond + bh*MDIM;
    } else {
        rowbase = bh*NSEQ + LCOND + (cidx-1)*CSZ; npass = 1;
        Sout = g_S + (size_t)(bh*NCH + cidx-1)*MDIM*DDIM;
        Zout = g_Z + (bh*NCH + cidx-1)*MDIM;
    }
    float kmax = dec_f(g_kmax_bits);

    int eh = warp >> 2, nq = warp & 3;
    float c[2][4][4];
    #pragma unroll
    for (int mi = 0; mi < 2; mi++)
        #pragma unroll
        for (int nt = 0; nt < 4; nt++){ c[mi][nt][0]=0.f;c[mi][nt][1]=0.f;c[mi][nt][2]=0.f;c[mi][nt][3]=0.f; }
    float z = 0.f;

    int m_local = tid & 127, rbase = (tid >> 7) * 32;
    int m_ntg = m_local >> 3, m_g = m_local & 7, m_x = m_ntg & 3;
    for (int p = 0; p < npass; p++){
        int r0 = rowbase + p*64;
        float sblk = __expf(g_bmax[(r0 + rbase) >> 7] - kmax);
        __syncthreads();
        const float* vg = v + (size_t)r0*DDIM;
        for (int i = tid; i < 2048; i += 256){
            int rp = i >> 6, e = i & 63;
            VT[e*FP2 + rp] = packh2(vg[rp*128 + e], vg[rp*128 + 64 + e]);
        }
        const __half* kg = g_kp + (size_t)(r0 + rbase)*MDIM + mbase + m_local;
        #pragma unroll 4
        for (int j = 0; j < 16; j++){
            float kf0 = fmaf(__half2float(kg[(size_t)(2*j)*MDIM]),   sblk, KEPS);
            float kf1 = fmaf(__half2float(kg[(size_t)(2*j+1)*MDIM]), sblk, KEPS);
            z += kf0 + kf1;
            int rp = (rbase >> 1) + j;
            int s4 = rp >> 3, t4p = rp & 3, h = (rp >> 2) & 1;
            KT[(m_ntg*4 + s4)*64 + ((m_g ^ s4) << 3) + ((t4p ^ m_x) << 1) + h] = packh2(kf0, kf1);
        }
        __syncthreads();
        #pragma unroll
        for (int s = 0; s < 4; s++){
            int kp0 = s*8, er0 = eh*32;
            uint32_t a00 = VT[(er0+gid   )*FP2 + kp0 + t4];
            uint32_t a01 = VT[(er0+gid+8 )*FP2 + kp0 + t4];
            uint32_t a02 = VT[(er0+gid   )*FP2 + kp0 + t4 + 4];
            uint32_t a03 = VT[(er0+gid+8 )*FP2 + kp0 + t4 + 4];
            uint32_t a10 = VT[(er0+gid+16)*FP2 + kp0 + t4];
            uint32_t a11 = VT[(er0+gid+24)*FP2 + kp0 + t4];
            uint32_t a12 = VT[(er0+gid+16)*FP2 + kp0 + t4 + 4];
            uint32_t a13 = VT[(er0+gid+24)*FP2 + kp0 + t4 + 4];
            #pragma unroll
            for (int nt = 0; nt < 4; nt++){
                int ntg = nq*4 + nt;
                uint2 bv = *reinterpret_cast<uint2*>(
                    &KT[(ntg*4 + s)*64 + ((gid ^ s) << 3) + ((t4 ^ (ntg & 3)) << 1)]);
                mma_f16(c[0][nt], a00,a01,a02,a03, bv.x,bv.y);
                mma_f16(c[1][nt], a10,a11,a12,a13, bv.x,bv.y);
            }
        }
    }
    zbuf[tid] = z;
    uint32_t* SoU = reinterpret_cast<uint32_t*>(Sout);
    #pragma unroll
    for (int mi = 0; mi < 2; mi++){
        int r0 = eh*32 + mi*16 + gid;
        #pragma unroll
        for (int nt = 0; nt < 4; nt++){
            int colh = (mbase >> 1) + nq*16 + nt*4 + t4;
            SoU[(size_t)r0*128 + colh]     = packh2(c[mi][nt][0], c[mi][nt][1]);
            SoU[(size_t)(r0+8)*128 + colh] = packh2(c[mi][nt][2], c[mi][nt][3]);
        }
    }
    __syncthreads();
    if (tid < 128) Zout[mbase + tid] = zbuf[tid] + zbuf[tid + 128];
}

// ================= exclusive prefix over chunks =================
__global__ __launch_bounds__(256) void prefix_kernel(){
    int idx = blockIdx.x*256 + threadIdx.x;
    const int totS2 = BH*8192;                 // half2 columns
    if (idx < totS2){
        int bh = idx >> 13;
        int j  = idx & 8191;
        float2 acc = unph2(reinterpret_cast<uint32_t*>(g_Scond)[idx]);
        uint32_t* p = reinterpret_cast<uint32_t*>(g_S) + (size_t)bh*NCH*8192 + j;
        #pragma unroll 4
        for (int c = 0; c < NCH; c++){
            uint32_t t = p[(size_t)c*8192];
            p[(size_t)c*8192] = packh2(acc.x, acc.y);
            float2 f = unph2(t);
            acc.x += f.x; acc.y += f.y;
        }
    } else {
        int k2 = idx - totS2;
        int bh = k2 >> 8;
        int j  = k2 & 255;
        float acc = g_Zcond[k2];
        float* p = g_Z + bh*NCH*MDIM + j;
        #pragma unroll 4
        for (int c = 0; c < NCH; c++){
            float t = p[c*MDIM];
            p[c*MDIM] = acc;
            acc += t;
        }
    }
}

// ================= attention output (fp16) =================
// K tile holds raw E; scores fixed up as s*accA + KEPS*qsum(t).
__global__ __launch_bounds__(256,3) void attn_mma(const float* __restrict__ v,
                                                  float* __restrict__ out){
    extern __shared__ uint32_t smu[];
    uint32_t* Qs = smu;               // [64][FP2]
    uint32_t* Ks = smu + 64*FP2;      // K tile ; phase2: V^T pairs
    uint32_t* Ss = smu + 2*64*FP2;    // S tile ; phase2: As pairs
    __shared__ float zps[64];
    __shared__ float den2p[4][64];
    __shared__ float denrow[64];
    __shared__ float qsumS[64];
    __shared__ float invden[64];

    int tid = threadIdx.x, lane = tid & 31, warp = tid >> 5;
    int gid = lane >> 2, t4 = lane & 3;
    int bh = blockIdx.y, cc = blockIdx.x;
    bool is_cond = (cc < 4);
    int rowbase;
    const __half *Sp; const float *zp;
    if (is_cond){
        rowbase = bh*NSEQ + cc*64;
        Sp = g_Scond + (size_t)bh*MDIM*DDIM;
        zp = g_Zcond + bh*MDIM;
    } else {
        int c = cc - 4;
        rowbase = bh*NSEQ + LCOND + c*CSZ;
        Sp = g_S + (size_t)(bh*NCH + c)*MDIM*DDIM;
        zp = g_Z + (bh*NCH + c)*MDIM;
    }
    const __half* Qg = g_qp + (size_t)rowbase*MDIM;
    const __half* Kg = g_kp + (size_t)rowbase*MDIM;
    const float* Vg = v + (size_t)rowbase*DDIM;
    float epsv = is_cond ? 0.f : SEPS2;
    float sblk = __expf(g_bmax[rowbase >> 7] - dec_f(g_kmax_bits));
    uint32_t QsA = smem_u32(Qs), KsA = smem_u32(Ks), SsA = smem_u32(Ss);

    if (tid < 64){ denrow[tid] = 0.f; qsumS[tid] = 0.f; }

    int mh = warp >> 2, nq = warp & 3;
    float accO[2][2][4], accA[2][2][4];
    #pragma unroll
    for (int mi = 0; mi < 2; mi++)
        #pragma unroll
        for (int nt = 0; nt < 2; nt++){
            accO[mi][nt][0]=0.f;accO[mi][nt][1]=0.f;accO[mi][nt][2]=0.f;accO[mi][nt][3]=0.f;
            accA[mi][nt][0]=0.f;accA[mi][nt][1]=0.f;accA[mi][nt][2]=0.f;accA[mi][nt][3]=0.f;
        }
    float den2 = 0.f;

    for (int mtl = 0; mtl < 4; mtl++){
        int m0 = mtl*64;
        __syncthreads();
        for (int i = tid; i < 512; i += 256){
            int t = i >> 3, qd = (i & 7)*4;
            cpa16(QsA + (t*FP2 + qd)*4, Qg + (size_t)t*MDIM + m0 + qd*2);
            cpa16(SsA + (t*FP2 + qd)*4, Sp + (size_t)t*MDIM + m0 + qd*2);
        }
        if (!is_cond)
            for (int i = tid; i < 512; i += 256){
                int t = i >> 3, qd = (i & 7)*4;
                cpa16(KsA + (t*FP2 + qd)*4, Kg + (size_t)t*MDIM + m0 + qd*2);
            }
        if (tid < 64) zps[tid] = zp[m0 + tid];
        CPA_COMMIT(); CPA_WAIT0();
        __syncthreads();
        {
            int row = tid & 63, grp = tid >> 6;
            float d = 0.f, qs = 0.f;
            #pragma unroll
            for (int j = 0; j < 8; j++){
                int mp = grp*8 + j;
                float2 f = unph2(Qs[row*FP2 + mp]);
                d = fmaf(f.x, zps[2*mp] + epsv, d);
                d = fmaf(f.y, zps[2*mp+1] + epsv, d);
                qs += f.x + f.y;
            }
            den2 += d;
            if (!is_cond) atomicAdd(&qsumS[row], qs);
        }
        #pragma unroll
        for (int s = 0; s < 4; s++){
            int kp0 = s*8, mr = mh*32;
            uint32_t a00 = Qs[(mr+gid   )*FP2 + kp0 + t4];
            uint32_t a01 = Qs[(mr+gid+8 )*FP2 + kp0 + t4];
            uint32_t a02 = Qs[(mr+gid   )*FP2 + kp0 + t4 + 4];
            uint32_t a03 = Qs[(mr+gid+8 )*FP2 + kp0 + t4 + 4];
            uint32_t a10 = Qs[(mr+gid+16)*FP2 + kp0 + t4];
            uint32_t a11 = Qs[(mr+gid+24)*FP2 + kp0 + t4];
            uint32_t a12 = Qs[(mr+gid+16)*FP2 + kp0 + t4 + 4];
            uint32_t a13 = Qs[(mr+gid+24)*FP2 + kp0 + t4 + 4];
            #pragma unroll
            for (int nt = 0; nt < 2; nt++){
                int n0 = nq*16 + nt*8;
                uint32_t s0 = Ss[(n0+gid)*FP2 + kp0 + t4];
                uint32_t s1 = Ss[(n0+gid)*FP2 + kp0 + t4 + 4];
                mma_f16(accO[0][nt], a00,a01,a02,a03, s0,s1);
                mma_f16(accO[1][nt], a10,a11,a12,a13, s0,s1);
                if (!is_cond){
                    uint32_t b0 = Ks[(n0+gid)*FP2 + kp0 + t4];
                    uint32_t b1 = Ks[(n0+gid)*FP2 + kp0 + t4 + 4];
                    mma_f16(accA[0][nt], a00,a01,a02,a03, b0,b1);
                    mma_f16(accA[1][nt], a10,a11,a12,a13, b0,b1);
                }
            }
        }
    }
    __syncthreads();
    den2p[tid >> 6][tid & 63] = den2;

    if (!is_cond){
        #pragma unroll
        for (int mi = 0; mi < 2; mi++){
            int r0 = mh*32 + mi*16 + gid;
            float base0 = KEPS * qsumS[r0], base1 = KEPS * qsumS[r0+8];
            float rs0 = 0.f, rs1 = 0.f;
            #pragma unroll
            for (int nt = 0; nt < 2; nt++){
                int col = nq*16 + nt*8 + t4*2;
                int colh = nq*8 + nt*4 + t4;
                float v00 = (col   <= r0  ) ? fmaf(sblk, accA[mi][nt][0], base0) : 0.f;
                float v01 = (col+1 <= r0  ) ? fmaf(sblk, accA[mi][nt][1], base0) : 0.f;
                float v10 = (col   <= r0+8) ? fmaf(sblk, accA[mi][nt][2], base1) : 0.f;
                float v11 = (col+1 <= r0+8) ? fmaf(sblk, accA[mi][nt][3], base1) : 0.f;
                rs0 += v00 + v01; rs1 += v10 + v11;
                Ss[r0*FP2 + colh]     = packh2(v00, v01);
                Ss[(r0+8)*FP2 + colh] = packh2(v10, v11);
            }
            atomicAdd(&denrow[r0],   rs0);
            atomicAdd(&denrow[r0+8], rs1);
        }
        for (int i = tid; i < 2048; i += 256){
            int sp = i >> 6, e = i & 63;
            Ks[e*FP2 + sp] = packh2(Vg[sp*128 + e], Vg[sp*128 + 64 + e]);
        }
        __syncthreads();
        #pragma unroll
        for (int s = 0; s < 4; s++){
            int kp0 = s*8, mr = mh*32;
            uint32_t a00 = Ss[(mr+gid   )*FP2 + kp0 + t4];
            uint32_t a01 = Ss[(mr+gid+8 )*FP2 + kp0 + t4];
            uint32_t a02 = Ss[(mr+gid   )*FP2 + kp0 + t4 + 4];
            uint32_t a03 = Ss[(mr+gid+8 )*FP2 + kp0 + t4 + 4];
            uint32_t a10 = Ss[(mr+gid+16)*FP2 + kp0 + t4];
            uint32_t a11 = Ss[(mr+gid+24)*FP2 + kp0 + t4];
            uint32_t a12 = Ss[(mr+gid+16)*FP2 + kp0 + t4 + 4];
            uint32_t a13 = Ss[(mr+gid+24)*FP2 + kp0 + t4 + 4];
            #pragma unroll
            for (int nt = 0; nt < 2; nt++){
                int n0 = nq*16 + nt*8;
                uint32_t b0 = Ks[(n0+gid)*FP2 + kp0 + t4];
                uint32_t b1 = Ks[(n0+gid)*FP2 + kp0 + t4 + 4];
                mma_f16(accO[0][nt], a00,a01,a02,a03, b0,b1);
                mma_f16(accO[1][nt], a10,a11,a12,a13, b0,b1);
            }
        }
    }
    __syncthreads();
    if (tid < 64){
        float d = denrow[tid] + den2p[0][tid] + den2p[1][tid]
                + den2p[2][tid] + den2p[3][tid];
        invden[tid] = 1.f / d;
    }
    __syncthreads();
    #pragma unroll
    for (int mi = 0; mi < 2; mi++){
        int r0 = mh*32 + mi*16 + gid;
        float i0 = invden[r0], i1 = invden[r0+8];
        #pragma unroll
        for (int nt = 0; nt < 2; nt++){
            int col = nq*16 + nt*8 + t4*2;
            float2 o0 = make_float2(accO[mi][nt][0]*i0, accO[mi][nt][1]*i0);
            float2 o1 = make_float2(accO[mi][nt][2]*i1, accO[mi][nt][3]*i1);
            *reinterpret_cast<float2*>(&out[(size_t)(rowbase+r0  )*DDIM + col]) = o0;
            *reinterpret_cast<float2*>(&out[(size_t)(rowbase+r0+8)*DDIM + col]) = o1;
        }
    }
}

// ================= launch =================
extern "C" void kernel_launch(void* const* d_in, const int* in_sizes, int n_in,
                              void* d_out, int out_size){
    const float* q    = (const float*)d_in[0];
    const float* k    = (const float*)d_in[1];
    const float* v    = (const float*)d_in[2];
    const float* proj = (const float*)d_in[3];
    float* out = (float*)d_out;

    const int FEAT_SMEM  = (4096 + 8192) * 4;       // 49152
    const int CHUNK_SMEM = (64*FP2 + 4096) * 4;     // 25600
    const int ATTN_SMEM  = 3*64*FP2*4;              // 27648
    cudaFuncSetAttribute(feat_mma<true>,  cudaFuncAttributeMaxDynamicSharedMemorySize, FEAT_SMEM);
    cudaFuncSetAttribute(feat_mma<false>, cudaFuncAttributeMaxDynamicSharedMemorySize, FEAT_SMEM);
    cudaFuncSetAttribute(chunk_mma,       cudaFuncAttributeMaxDynamicSharedMemorySize, CHUNK_SMEM);
    cudaFuncSetAttribute(attn_mma,        cudaFuncAttributeMaxDynamicSharedMemorySize, ATTN_SMEM);

    prep_kernel<<<32,256>>>(proj);
    feat_mma<false><<<1024,512,FEAT_SMEM>>>(k);
    feat_mma<true ><<<1024,512,FEAT_SMEM>>>(q);
    chunk_mma<<<dim3(61,32,2),256,CHUNK_SMEM>>>(v);
    prefix_kernel<<<1056,256>>>();
    attn_mma<<<dim3(64,32),256,ATTN_SMEM>>>(v, out);
}